// round 2
// baseline (speedup 1.0000x reference)
#include <cuda_runtime.h>
#include <cuda_bf16.h>
#include <math.h>

// Problem constants
#define B_   2
#define L_   2048
#define D_   1024
#define H_   16
#define HS_  64
#define BL_  (B_ * L_)        // 4096
#define N3D_ (3 * D_)         // 3072

// Scratch (device globals; allocation in kernel_launch is forbidden)
__device__ float g_q[B_ * H_ * L_ * HS_];   // (b*H+h, l, d), pre-scaled by 1/8
__device__ float g_k[B_ * H_ * L_ * HS_];
__device__ float g_v[B_ * H_ * L_ * HS_];
__device__ float g_y[BL_ * D_];             // (b, l, h*64+d)

// ---------------------------------------------------------------------------
// GEMM 1: qkv = x @ W_attn + b_attn, scattered into g_q/g_k/g_v head-major.
// M=4096, N=3072, K=1024. Tiles: 128x128x16, 256 threads, 8x8 per thread.
// ---------------------------------------------------------------------------
__global__ __launch_bounds__(256) void gemm_qkv_kernel(
    const float* __restrict__ X, const float* __restrict__ W,
    const float* __restrict__ bias)
{
    __shared__ float As[16][132];   // transposed A tile: As[k][m], padded
    __shared__ float Bs[16][128];

    const int tid = threadIdx.x;
    const int tx = tid & 15, ty = tid >> 4;
    const int row0 = blockIdx.y * 128;
    const int col0 = blockIdx.x * 128;

    float acc[8][8];
#pragma unroll
    for (int r = 0; r < 8; r++)
#pragma unroll
        for (int c = 0; c < 8; c++) acc[r][c] = 0.0f;

    for (int k0 = 0; k0 < 1024; k0 += 16) {
        // Load A tile (128 rows x 16 k) as float4 along k, scatter transposed
#pragma unroll
        for (int t = tid; t < 512; t += 256) {
            int r = t >> 2, c4 = t & 3;
            float4 a = *(const float4*)&X[(size_t)(row0 + r) * 1024 + k0 + c4 * 4];
            As[c4 * 4 + 0][r] = a.x;
            As[c4 * 4 + 1][r] = a.y;
            As[c4 * 4 + 2][r] = a.z;
            As[c4 * 4 + 3][r] = a.w;
        }
        // Load B tile (16 k x 128 n)
#pragma unroll
        for (int t = tid; t < 512; t += 256) {
            int r = t >> 5, c4 = t & 31;
            *(float4*)&Bs[r][c4 * 4] =
                *(const float4*)&W[(size_t)(k0 + r) * N3D_ + col0 + c4 * 4];
        }
        __syncthreads();

#pragma unroll
        for (int kk = 0; kk < 16; kk++) {
            float a[8], b[8];
            *(float4*)&a[0] = *(float4*)&As[kk][ty * 8];
            *(float4*)&a[4] = *(float4*)&As[kk][ty * 8 + 4];
            *(float4*)&b[0] = *(float4*)&Bs[kk][tx * 8];
            *(float4*)&b[4] = *(float4*)&Bs[kk][tx * 8 + 4];
#pragma unroll
            for (int r = 0; r < 8; r++)
#pragma unroll
                for (int c = 0; c < 8; c++) acc[r][c] = fmaf(a[r], b[c], acc[r][c]);
        }
        __syncthreads();
    }

    // Epilogue: scatter to q/k/v head-major layout. 8 cols are contiguous and
    // never cross a 64-wide head boundary (col0 + tx*8 is 8-aligned).
    const int colbase = col0 + tx * 8;
    const int sec = colbase / D_;            // 0=q, 1=k, 2=v
    const int cm = colbase % D_;
    const int h = cm / HS_, d = cm % HS_;
    float* dst = (sec == 0) ? g_q : (sec == 1) ? g_k : g_v;
    const float scl = (sec == 0) ? 0.125f : 1.0f;   // 1/sqrt(64) folded into q

#pragma unroll
    for (int r = 0; r < 8; r++) {
        int mrow = row0 + ty * 8 + r;
        int b = mrow >> 11, l = mrow & 2047;
        float* out = &dst[(((size_t)(b * H_ + h)) * L_ + l) * HS_ + d];
#pragma unroll
        for (int c = 0; c < 8; c++)
            out[c] = (acc[r][c] + bias[colbase + c]) * scl;
    }
}

// ---------------------------------------------------------------------------
// Flash-style causal attention with relative-position bias.
// Score(q,k) = qv . (kv + Er[L-1+k-q])  (q pre-scaled). Block = one (b*h, q-tile).
// ---------------------------------------------------------------------------
#define QOFF  0
#define KOFF  4160            // 64*65
#define VOFF  8320
#define EOFF  12480
#define SOFF  20736           // 12480 + 127*65 = 20735, padded to 20736
#define MOFF  24896           // 20736 + 4160
#define LOFF  24960
#define AOFF  25024
#define SMEM_FLOATS 25088
#define SMEM_BYTES  (SMEM_FLOATS * 4)

__global__ __launch_bounds__(256, 2) void attn_kernel(const float* __restrict__ Er)
{
    extern __shared__ float sm[];
    float* Qs = sm + QOFF;     // [64][65]
    float* Ks = sm + KOFF;     // [64][65]
    float* Vs = sm + VOFF;     // [64][65]
    float* Es = sm + EOFF;     // [127][65]
    float* Ss = sm + SOFF;     // [64][65]  scores -> probabilities in place
    float* Ms = sm + MOFF;     // [64] running max
    float* Ls = sm + LOFF;     // [64] running denom
    float* ASc = sm + AOFF;    // [64] rescale alpha

    const int tid = threadIdx.x;
    const int bh = blockIdx.x;           // 0..31
    const int qt = blockIdx.y;           // 0..31
    const int q0 = qt * 64;
    const int tx = tid & 15, ty = tid >> 4;
    const int i0 = ty * 4;               // local q rows
    const int j0 = tx * 4;               // local k cols (== output d cols in phase C)
    const int w = tid >> 5, lane = tid & 31;
    const float NEG_INF = -__int_as_float(0x7f800000) * 0.0f - 1e30f; // just use -1e30 sentinel? no:
    const float MINF = __int_as_float(0xff800000);                    // -inf

    // Load Q tile
    for (int t = tid; t < 64 * 64; t += 256) {
        int i = t >> 6, d = t & 63;
        Qs[i * 65 + d] = g_q[((size_t)bh * L_ + q0 + i) * HS_ + d];
    }
    if (tid < 64) { Ms[tid] = MINF; Ls[tid] = 0.0f; }

    float yacc[4][4];
#pragma unroll
    for (int r = 0; r < 4; r++)
#pragma unroll
        for (int c = 0; c < 4; c++) yacc[r][c] = 0.0f;

    for (int kt = 0; kt <= qt; kt++) {
        const int k0 = kt * 64;
        __syncthreads();   // previous phase C done before overwriting tiles

        // Load K and V tiles
        for (int t = tid; t < 64 * 64; t += 256) {
            int i = t >> 6, d = t & 63;
            Ks[i * 65 + d] = g_k[((size_t)bh * L_ + k0 + i) * HS_ + d];
            Vs[i * 65 + d] = g_v[((size_t)bh * L_ + k0 + i) * HS_ + d];
        }
        // Load Er window: rows eBase .. eBase+126, e_local = 63 + j - i
        const int eBase = (L_ - 1) + k0 - q0 - 63;   // >= 0 always
        for (int t = tid; t < 127 * 64; t += 256) {
            int rr = t >> 6, d = t & 63;
            int er = eBase + rr; if (er > L_ - 1) er = L_ - 1;   // clamp (masked region)
            Es[rr * 65 + d] = Er[(size_t)er * HS_ + d];
        }
        __syncthreads();

        // ---- Phase A: scores S = Q.K^T + Q.Er(diag) ----
        float acc[4][4];
#pragma unroll
        for (int r = 0; r < 4; r++)
#pragma unroll
            for (int c = 0; c < 4; c++) acc[r][c] = 0.0f;

        const int e0 = j0 - i0 + 60;   // Es row for (r=3, c=0) .. +6 for (r=0,c=3)
#pragma unroll 8
        for (int d = 0; d < 64; d++) {
            float qv[4], kv[4], ev[7];
#pragma unroll
            for (int r = 0; r < 4; r++) qv[r] = Qs[(i0 + r) * 65 + d];
#pragma unroll
            for (int c = 0; c < 4; c++) kv[c] = Ks[(j0 + c) * 65 + d];
#pragma unroll
            for (int u = 0; u < 7; u++) ev[u] = Es[(e0 + u) * 65 + d];
#pragma unroll
            for (int r = 0; r < 4; r++)
#pragma unroll
                for (int c = 0; c < 4; c++)
                    acc[r][c] = fmaf(qv[r], kv[c] + ev[c - r + 3], acc[r][c]);
        }

        const bool diag = (kt == qt);
#pragma unroll
        for (int r = 0; r < 4; r++)
#pragma unroll
            for (int c = 0; c < 4; c++) {
                float s = acc[r][c];
                if (diag && (j0 + c) > (i0 + r)) s = MINF;
                Ss[(i0 + r) * 65 + j0 + c] = s;
            }
        __syncthreads();

        // ---- Phase B: online softmax row update (warp w owns rows 8w..8w+7) ----
#pragma unroll
        for (int rr = 0; rr < 8; rr++) {
            const int i = w * 8 + rr;
            float s0 = Ss[i * 65 + lane];
            float s1 = Ss[i * 65 + 32 + lane];
            float mx = fmaxf(s0, s1);
#pragma unroll
            for (int off = 16; off > 0; off >>= 1)
                mx = fmaxf(mx, __shfl_xor_sync(0xffffffffu, mx, off));
            const float mold = Ms[i];
            const float mnew = fmaxf(mold, mx);
            const float p0 = __expf(s0 - mnew);
            const float p1 = __expf(s1 - mnew);
            Ss[i * 65 + lane] = p0;
            Ss[i * 65 + 32 + lane] = p1;
            float ps = p0 + p1;
#pragma unroll
            for (int off = 16; off > 0; off >>= 1)
                ps += __shfl_xor_sync(0xffffffffu, ps, off);
            if (lane == 0) {
                const float al = __expf(mold - mnew);   // 0 on first tile
                ASc[i] = al;
                Ls[i] = Ls[i] * al + ps;
                Ms[i] = mnew;
            }
        }
        __syncthreads();

        // ---- Phase C: Y = Y*alpha + P.V ----
        float ar[4];
#pragma unroll
        for (int r = 0; r < 4; r++) ar[r] = ASc[i0 + r];
#pragma unroll
        for (int r = 0; r < 4; r++)
#pragma unroll
            for (int c = 0; c < 4; c++) yacc[r][c] *= ar[r];

#pragma unroll 8
        for (int j = 0; j < 64; j++) {
            float pv[4], vv[4];
#pragma unroll
            for (int r = 0; r < 4; r++) pv[r] = Ss[(i0 + r) * 65 + j];
#pragma unroll
            for (int c = 0; c < 4; c++) vv[c] = Vs[j * 65 + j0 + c];
#pragma unroll
            for (int r = 0; r < 4; r++)
#pragma unroll
                for (int c = 0; c < 4; c++)
                    yacc[r][c] = fmaf(pv[r], vv[c], yacc[r][c]);
        }
    }

    // ---- Epilogue: normalize and write to (B, L, D) layout ----
    const int b = bh >> 4, h = bh & 15;
#pragma unroll
    for (int r = 0; r < 4; r++) {
        const float linv = 1.0f / Ls[i0 + r];
        float* out = &g_y[((size_t)b * L_ + q0 + i0 + r) * D_ + h * HS_ + j0];
        float4 o;
        o.x = yacc[r][0] * linv; o.y = yacc[r][1] * linv;
        o.z = yacc[r][2] * linv; o.w = yacc[r][3] * linv;
        *(float4*)out = o;
    }
    (void)NEG_INF;
}

// ---------------------------------------------------------------------------
// GEMM 2: out = y @ W_proj + b_proj.  M=4096, N=1024, K=1024.
// ---------------------------------------------------------------------------
__global__ __launch_bounds__(256) void gemm_proj_kernel(
    const float* __restrict__ W, const float* __restrict__ bias,
    float* __restrict__ out)
{
    __shared__ float As[16][132];
    __shared__ float Bs[16][128];

    const int tid = threadIdx.x;
    const int tx = tid & 15, ty = tid >> 4;
    const int row0 = blockIdx.y * 128;
    const int col0 = blockIdx.x * 128;

    float acc[8][8];
#pragma unroll
    for (int r = 0; r < 8; r++)
#pragma unroll
        for (int c = 0; c < 8; c++) acc[r][c] = 0.0f;

    for (int k0 = 0; k0 < 1024; k0 += 16) {
#pragma unroll
        for (int t = tid; t < 512; t += 256) {
            int r = t >> 2, c4 = t & 3;
            float4 a = *(const float4*)&g_y[(size_t)(row0 + r) * 1024 + k0 + c4 * 4];
            As[c4 * 4 + 0][r] = a.x;
            As[c4 * 4 + 1][r] = a.y;
            As[c4 * 4 + 2][r] = a.z;
            As[c4 * 4 + 3][r] = a.w;
        }
#pragma unroll
        for (int t = tid; t < 512; t += 256) {
            int r = t >> 5, c4 = t & 31;
            *(float4*)&Bs[r][c4 * 4] =
                *(const float4*)&W[(size_t)(k0 + r) * D_ + col0 + c4 * 4];
        }
        __syncthreads();

#pragma unroll
        for (int kk = 0; kk < 16; kk++) {
            float a[8], b[8];
            *(float4*)&a[0] = *(float4*)&As[kk][ty * 8];
            *(float4*)&a[4] = *(float4*)&As[kk][ty * 8 + 4];
            *(float4*)&b[0] = *(float4*)&Bs[kk][tx * 8];
            *(float4*)&b[4] = *(float4*)&Bs[kk][tx * 8 + 4];
#pragma unroll
            for (int r = 0; r < 8; r++)
#pragma unroll
                for (int c = 0; c < 8; c++) acc[r][c] = fmaf(a[r], b[c], acc[r][c]);
        }
        __syncthreads();
    }

    const int colbase = col0 + tx * 8;
#pragma unroll
    for (int r = 0; r < 8; r++) {
        int mrow = row0 + ty * 8 + r;
        float* o = &out[(size_t)mrow * D_ + colbase];
#pragma unroll
        for (int c = 0; c < 8; c++)
            o[c] = acc[r][c] + bias[colbase + c];
    }
}

// ---------------------------------------------------------------------------
extern "C" void kernel_launch(void* const* d_in, const int* in_sizes, int n_in,
                              void* d_out, int out_size)
{
    const float* x      = (const float*)d_in[0];   // (2, 2048, 1024)
    const float* W_attn = (const float*)d_in[1];   // (1024, 3072)
    const float* b_attn = (const float*)d_in[2];   // (3072,)
    const float* W_proj = (const float*)d_in[3];   // (1024, 1024)
    const float* b_proj = (const float*)d_in[4];   // (1024,)
    const float* Er     = (const float*)d_in[5];   // (2048, 64)
    float* out = (float*)d_out;

    cudaFuncSetAttribute(attn_kernel,
                         cudaFuncAttributeMaxDynamicSharedMemorySize, SMEM_BYTES);

    // 1) QKV projection + head scatter (+ q scaling)
    gemm_qkv_kernel<<<dim3(N3D_ / 128, BL_ / 128), 256>>>(x, W_attn, b_attn);

    // 2) Causal attention with relative position bias
    attn_kernel<<<dim3(B_ * H_, L_ / 64), 256, SMEM_BYTES>>>(Er);

    // 3) Output projection
    gemm_proj_kernel<<<dim3(D_ / 128, BL_ / 128), 256>>>(W_proj, b_proj, out);
}

// round 10
// speedup vs baseline: 2.0389x; 2.0389x over previous
#include <cuda_runtime.h>
#include <cuda_bf16.h>
#include <math.h>
#include <stdint.h>

// Problem constants
#define B_   2
#define L_   2048
#define D_   1024
#define H_   16
#define HS_  64
#define BL_  (B_ * L_)        // 4096
#define N3D_ (3 * D_)         // 3072
#define GK   1024             // K dim of both GEMMs

// Scratch (device globals; allocation in kernel_launch is forbidden)
__device__ float g_q[B_ * H_ * L_ * HS_];   // (b*H+h, l, d), pre-scaled by 1/8
__device__ float g_k[B_ * H_ * L_ * HS_];
__device__ float g_v[B_ * H_ * L_ * HS_];
__device__ float g_y[BL_ * D_];             // (b, l, h*64+d)
__device__ float g_wat[N3D_ * D_];          // W_attn^T  [3072][1024]
__device__ float g_wpt[D_ * D_];            // W_proj^T  [1024][1024]

// ---------------------------------------------------------------------------
// tf32 mma.sync helpers (sm_80+ features only — compile for plain sm_103)
// ---------------------------------------------------------------------------
__device__ __forceinline__ uint32_t f2tf(float f) {
    uint32_t u;
    asm("cvt.rna.tf32.f32 %0, %1;" : "=r"(u) : "f"(f));
    return u;
}

// D(16x8,f32) += A(16x8,tf32,row) * B(8x8,tf32,col)
__device__ __forceinline__ void mma_tf32(float* c, const uint32_t* a, const uint32_t* b) {
    asm volatile(
        "mma.sync.aligned.m16n8k8.row.col.f32.tf32.tf32.f32 "
        "{%0,%1,%2,%3},{%4,%5,%6,%7},{%8,%9},{%0,%1,%2,%3};"
        : "+f"(c[0]), "+f"(c[1]), "+f"(c[2]), "+f"(c[3])
        : "r"(a[0]), "r"(a[1]), "r"(a[2]), "r"(a[3]), "r"(b[0]), "r"(b[1]));
}

__device__ __forceinline__ void sts_tf32x4(uint32_t* p, float4 v) {
    uint4 u;
    u.x = f2tf(v.x); u.y = f2tf(v.y); u.z = f2tf(v.z); u.w = f2tf(v.w);
    *(uint4*)p = u;
}

// ---------------------------------------------------------------------------
// Transpose: src[K][N] -> dst[N][K]   (fp32; tf32 conversion happens at use)
// ---------------------------------------------------------------------------
__global__ __launch_bounds__(256) void transpose_kernel(
    const float* __restrict__ src, float* __restrict__ dst, int K, int N)
{
    __shared__ float s[32][33];
    const int tx = threadIdx.x & 31, ty = threadIdx.x >> 5;   // 32x8
    const int gx = blockIdx.x * 32, gy = blockIdx.y * 32;
#pragma unroll
    for (int j = 0; j < 4; j++)
        s[ty + j * 8][tx] = src[(size_t)(gy + ty + j * 8) * N + gx + tx];
    __syncthreads();
#pragma unroll
    for (int j = 0; j < 4; j++)
        dst[(size_t)(gx + ty + j * 8) * K + gy + tx] = s[tx][ty + j * 8];
}

// ---------------------------------------------------------------------------
// tf32 mma.sync GEMM: C[M][Ntot] = A[M][1024] x Bt[Ntot][1024]^T + bias
// CTA tile 128x128, 8 warps (4m x 2n grid, warp tile 32x64), K chunks of 16
// double-buffered. Smem k-stride = 20 words => conflict-free fragment LDS.
// MODE 0: qkv epilogue (scatter to g_q/g_k/g_v head-major, q scaled by 1/8)
// MODE 1: proj epilogue (row-major out)
// ---------------------------------------------------------------------------
template <int MODE>
__global__ __launch_bounds__(256, 2) void gemm_mma(
    const float* __restrict__ A, const float* __restrict__ Bt,
    const float* __restrict__ bias, float* __restrict__ outp)
{
    __shared__ float    bias_s[128];
    __shared__ uint32_t As[2][128 * 20];
    __shared__ uint32_t Bs[2][128 * 20];

    const int tid = threadIdx.x;
    const int lane = tid & 31;
    const int wid = tid >> 5;
    const int grp = lane >> 2, tig = lane & 3;
    const int wm = wid & 3, wn = wid >> 2;       // warp tile: rows wm*32, cols wn*64
    const int row0 = blockIdx.y * 128, col0 = blockIdx.x * 128;

    if (tid < 128) bias_s[tid] = bias[col0 + tid];

    const int lr = tid >> 2;              // 0..63
    const int lq = (tid & 3) * 4;         // 0,4,8,12 (word offset within k16)

    float acc[2][8][4];
#pragma unroll
    for (int mt = 0; mt < 2; mt++)
#pragma unroll
        for (int nt = 0; nt < 8; nt++)
#pragma unroll
            for (int i = 0; i < 4; i++) acc[mt][nt][i] = 0.0f;

    float4 pa0, pa1, pb0, pb1;
    // prefetch + store chunk 0
    pa0 = *(const float4*)&A [(size_t)(row0 + lr)      * GK + lq];
    pa1 = *(const float4*)&A [(size_t)(row0 + 64 + lr) * GK + lq];
    pb0 = *(const float4*)&Bt[(size_t)(col0 + lr)      * GK + lq];
    pb1 = *(const float4*)&Bt[(size_t)(col0 + 64 + lr) * GK + lq];
    sts_tf32x4(&As[0][lr * 20 + lq],        pa0);
    sts_tf32x4(&As[0][(64 + lr) * 20 + lq], pa1);
    sts_tf32x4(&Bs[0][lr * 20 + lq],        pb0);
    sts_tf32x4(&Bs[0][(64 + lr) * 20 + lq], pb1);
    __syncthreads();

    for (int c = 0; c < 64; c++) {
        const int bf = c & 1;
        if (c < 63) {
            const int k0 = (c + 1) * 16;
            pa0 = *(const float4*)&A [(size_t)(row0 + lr)      * GK + k0 + lq];
            pa1 = *(const float4*)&A [(size_t)(row0 + 64 + lr) * GK + k0 + lq];
            pb0 = *(const float4*)&Bt[(size_t)(col0 + lr)      * GK + k0 + lq];
            pb1 = *(const float4*)&Bt[(size_t)(col0 + 64 + lr) * GK + k0 + lq];
        }

#pragma unroll
        for (int ks = 0; ks < 2; ks++) {
            const int k = ks * 8;
            uint32_t af[2][4];
#pragma unroll
            for (int mt = 0; mt < 2; mt++) {
                const uint32_t* r0 = &As[bf][(wm * 32 + mt * 16 + grp) * 20];
                af[mt][0] = r0[k + tig];
                af[mt][1] = r0[8 * 20 + k + tig];
                af[mt][2] = r0[k + tig + 4];
                af[mt][3] = r0[8 * 20 + k + tig + 4];
            }
            uint32_t bfr[8][2];
#pragma unroll
            for (int nt = 0; nt < 8; nt++) {
                const uint32_t* rb = &Bs[bf][(wn * 64 + nt * 8 + grp) * 20];
                bfr[nt][0] = rb[k + tig];
                bfr[nt][1] = rb[k + tig + 4];
            }
#pragma unroll
            for (int mt = 0; mt < 2; mt++)
#pragma unroll
                for (int nt = 0; nt < 8; nt++)
                    mma_tf32(acc[mt][nt], af[mt], bfr[nt]);
        }

        if (c < 63) {
            const int nb = bf ^ 1;
            sts_tf32x4(&As[nb][lr * 20 + lq],        pa0);
            sts_tf32x4(&As[nb][(64 + lr) * 20 + lq], pa1);
            sts_tf32x4(&Bs[nb][lr * 20 + lq],        pb0);
            sts_tf32x4(&Bs[nb][(64 + lr) * 20 + lq], pb1);
        }
        __syncthreads();
    }

    // ---- epilogue ----
#pragma unroll
    for (int nt = 0; nt < 8; nt++) {
        const int colb = col0 + wn * 64 + nt * 8;    // multiple of 8
        const int cloc = colb - col0 + 2 * tig;
        float scl = 1.0f;
        float* dstb = outp;
        int h = 0;
        if (MODE == 0) {
            const int sec = colb >> 10;
            const int cm = colb & 1023;
            h = cm >> 6;
            dstb = (sec == 0) ? g_q : (sec == 1) ? g_k : g_v;
            scl = (sec == 0) ? 0.125f : 1.0f;
        }
        const int d0 = MODE == 0 ? ((colb & 63) + 2 * tig) : 0;
#pragma unroll
        for (int mt = 0; mt < 2; mt++) {
            const int gm_lo = row0 + wm * 32 + mt * 16 + grp;
            const int gm_hi = gm_lo + 8;
            float2 lo, hi;
            lo.x = (acc[mt][nt][0] + bias_s[cloc])     * scl;
            lo.y = (acc[mt][nt][1] + bias_s[cloc + 1]) * scl;
            hi.x = (acc[mt][nt][2] + bias_s[cloc])     * scl;
            hi.y = (acc[mt][nt][3] + bias_s[cloc + 1]) * scl;
            if (MODE == 0) {
                const int bb_lo = gm_lo >> 11, l_lo = gm_lo & 2047;
                const int bb_hi = gm_hi >> 11, l_hi = gm_hi & 2047;
                *(float2*)&dstb[(((size_t)(bb_lo * H_ + h)) * L_ + l_lo) * HS_ + d0] = lo;
                *(float2*)&dstb[(((size_t)(bb_hi * H_ + h)) * L_ + l_hi) * HS_ + d0] = hi;
            } else {
                *(float2*)&outp[(size_t)gm_lo * D_ + colb + 2 * tig] = lo;
                *(float2*)&outp[(size_t)gm_hi * D_ + colb + 2 * tig] = hi;
            }
        }
    }
}

// ---------------------------------------------------------------------------
// Flash-style causal attention with relative-position bias, tf32 mma.sync.
// Per (bh, 64-row q-tile). Phase A computes S_all(64x192) = Q x [K ; ErW]^T in
// one fused MMA pass (cols 0..63 = QK^T, cols 64..191 = R[i][u] = q_i.Er[u]);
// the skew becomes the contiguous gather R[i][63-i+j] inside softmax.
// ---------------------------------------------------------------------------
#define ALD 68                 // k-stride (words) for Q/K/V/S tiles
#define RLD 132                // row stride for R
#define QOFF 0                 // 64*68   = 4352
#define KOFF 4352
#define VOFF 8704
#define EOFF 13056             // 128*68  = 8704
#define SOFF 21760             // 64*68
#define ROFF 26112             // 64*132  = 8448
#define MOFF 34560
#define LOFF 34624
#define AOFF 34688
#define ATT_SMEMF 34752
#define ATT_SMEMB (ATT_SMEMF * 4)

__global__ __launch_bounds__(256, 1) void attn_kernel(const float* __restrict__ Er)
{
    extern __shared__ float sm[];
    uint32_t* Qs = (uint32_t*)(sm + QOFF);
    uint32_t* Ks = (uint32_t*)(sm + KOFF);
    uint32_t* Vs = (uint32_t*)(sm + VOFF);
    uint32_t* Es = (uint32_t*)(sm + EOFF);
    float*    Sf = sm + SOFF;                 // scores (f32) then P (tf32 bits)
    uint32_t* Su = (uint32_t*)(sm + SOFF);
    float*    Rf = sm + ROFF;
    float*    Ms = sm + MOFF;
    float*    Ls = sm + LOFF;
    float*    Af = sm + AOFF;

    const int tid = threadIdx.x;
    const int wid = tid >> 5, lane = tid & 31;
    const int grp = lane >> 2, tig = lane & 3;
    const int bh = blockIdx.x;           // 0..31
    const int qt = blockIdx.y;           // 0..31
    const int q0 = qt * 64;
    const float MINF = __int_as_float(0xff800000);

    const int m0 = (wid & 3) * 16;       // phase A/C m-tile base (16 rows)
    const int nh = wid >> 2;             // phase A n-half (0/1), phase C col half

    // Load Q tile (tf32)
#pragma unroll
    for (int i = 0; i < 4; i++) {
        const int idx = i * 256 + tid;
        const int row = idx >> 4, dq = (idx & 15) * 4;
        float4 v = *(const float4*)&g_q[((size_t)bh * L_ + q0 + row) * HS_ + dq];
        sts_tf32x4(&Qs[row * ALD + dq], v);
    }
    if (tid < 64) { Ms[tid] = MINF; Ls[tid] = 0.0f; }

    float yacc[4][4];
#pragma unroll
    for (int nt = 0; nt < 4; nt++)
#pragma unroll
        for (int i = 0; i < 4; i++) yacc[nt][i] = 0.0f;

    for (int kt = 0; kt <= qt; kt++) {
        const int k0 = kt * 64;
        __syncthreads();   // prior phase C reads done before overwriting tiles

        // Load K, V tiles (tf32)
#pragma unroll
        for (int i = 0; i < 4; i++) {
            const int idx = i * 256 + tid;
            const int row = idx >> 4, dq = (idx & 15) * 4;
            float4 kv = *(const float4*)&g_k[((size_t)bh * L_ + k0 + row) * HS_ + dq];
            float4 vv = *(const float4*)&g_v[((size_t)bh * L_ + k0 + row) * HS_ + dq];
            sts_tf32x4(&Ks[row * ALD + dq], kv);
            sts_tf32x4(&Vs[row * ALD + dq], vv);
        }
        // Load Er window (128 rows, clamped; clamped rows are causally masked)
        const int eBase = (L_ - 1) + k0 - q0 - 63;
#pragma unroll
        for (int i = 0; i < 8; i++) {
            const int idx = i * 256 + tid;
            const int row = idx >> 4, dq = (idx & 15) * 4;
            int er = eBase + row; if (er > L_ - 1) er = L_ - 1;
            float4 v = *(const float4*)&Er[(size_t)er * HS_ + dq];
            sts_tf32x4(&Es[row * ALD + dq], v);
        }
        __syncthreads();

        // ---- Phase A: S_all(64x192) = Q x [K ; ErW]^T ----
        float sacc[12][4];
#pragma unroll
        for (int nt = 0; nt < 12; nt++)
#pragma unroll
            for (int i = 0; i < 4; i++) sacc[nt][i] = 0.0f;

#pragma unroll
        for (int ks = 0; ks < 8; ks++) {
            const int k = ks * 8;
            uint32_t af[4];
            const uint32_t* q0p = &Qs[(m0 + grp) * ALD];
            af[0] = q0p[k + tig];
            af[1] = q0p[8 * ALD + k + tig];
            af[2] = q0p[k + tig + 4];
            af[3] = q0p[8 * ALD + k + tig + 4];
#pragma unroll
            for (int nt = 0; nt < 12; nt++) {
                const int ntg = nh * 12 + nt;
                const uint32_t* rb = (ntg < 8)
                    ? &Ks[(ntg * 8 + grp) * ALD]
                    : &Es[((ntg - 8) * 8 + grp) * ALD];
                uint32_t bf[2];
                bf[0] = rb[k + tig];
                bf[1] = rb[k + tig + 4];
                mma_tf32(sacc[nt], af, bf);
            }
        }
#pragma unroll
        for (int nt = 0; nt < 12; nt++) {
            const int ntg = nh * 12 + nt;
            float2 lo = make_float2(sacc[nt][0], sacc[nt][1]);
            float2 hi = make_float2(sacc[nt][2], sacc[nt][3]);
            if (ntg < 8) {
                *(float2*)&Sf[(m0 + grp) * ALD + ntg * 8 + 2 * tig]     = lo;
                *(float2*)&Sf[(m0 + 8 + grp) * ALD + ntg * 8 + 2 * tig] = hi;
            } else {
                const int cb = (ntg - 8) * 8 + 2 * tig;
                *(float2*)&Rf[(m0 + grp) * RLD + cb]     = lo;
                *(float2*)&Rf[(m0 + 8 + grp) * RLD + cb] = hi;
            }
        }
        __syncthreads();

        // ---- Phase B: online softmax; write P back as tf32 bits ----
        const bool diag = (kt == qt);
#pragma unroll
        for (int rr = 0; rr < 8; rr++) {
            const int i = wid * 8 + rr;
            const float* rrow = &Rf[i * RLD + 63 - i];
            float s0 = Sf[i * ALD + lane]      + rrow[lane];
            float s1 = Sf[i * ALD + 32 + lane] + rrow[32 + lane];
            if (diag) {
                if (lane > i) s0 = MINF;
                if (32 + lane > i) s1 = MINF;
            }
            float mx = fmaxf(s0, s1);
#pragma unroll
            for (int off = 16; off > 0; off >>= 1)
                mx = fmaxf(mx, __shfl_xor_sync(0xffffffffu, mx, off));
            const float mold = Ms[i];
            const float mnew = fmaxf(mold, mx);
            const float p0 = __expf(s0 - mnew);
            const float p1 = __expf(s1 - mnew);
            Su[i * ALD + lane]      = f2tf(p0);
            Su[i * ALD + 32 + lane] = f2tf(p1);
            float ps = p0 + p1;
#pragma unroll
            for (int off = 16; off > 0; off >>= 1)
                ps += __shfl_xor_sync(0xffffffffu, ps, off);
            if (lane == 0) {
                const float al = __expf(mold - mnew);   // 0 on first tile
                Af[i] = al;
                Ls[i] = Ls[i] * al + ps;
                Ms[i] = mnew;
            }
        }
        __syncthreads();

        // ---- Phase C: Y = Y*alpha + P.V  (warp: 16 rows x 32 cols) ----
        const int n0c = nh * 32;
        const float aL = Af[m0 + grp], aH = Af[m0 + 8 + grp];
#pragma unroll
        for (int nt = 0; nt < 4; nt++) {
            yacc[nt][0] *= aL; yacc[nt][1] *= aL;
            yacc[nt][2] *= aH; yacc[nt][3] *= aH;
        }
#pragma unroll
        for (int ks = 0; ks < 8; ks++) {
            const int k = ks * 8;
            uint32_t af[4];
            const uint32_t* p0p = &Su[(m0 + grp) * ALD];
            af[0] = p0p[k + tig];
            af[1] = p0p[8 * ALD + k + tig];
            af[2] = p0p[k + tig + 4];
            af[3] = p0p[8 * ALD + k + tig + 4];
#pragma unroll
            for (int nt = 0; nt < 4; nt++) {
                uint32_t bf[2];
                bf[0] = Vs[(k + tig) * ALD + n0c + nt * 8 + grp];
                bf[1] = Vs[(k + tig + 4) * ALD + n0c + nt * 8 + grp];
                mma_tf32(yacc[nt], af, bf);
            }
        }
    }

    // ---- Epilogue: normalize, write (B, L, D) ----
    const int b = bh >> 4, h = bh & 15;
    const int n0c = nh * 32;
    const float linvL = 1.0f / Ls[m0 + grp];
    const float linvH = 1.0f / Ls[m0 + 8 + grp];
#pragma unroll
    for (int nt = 0; nt < 4; nt++) {
        const int col = h * 64 + n0c + nt * 8 + 2 * tig;
        const int rl = q0 + m0 + grp, rh = rl + 8;
        float2 lo = make_float2(yacc[nt][0] * linvL, yacc[nt][1] * linvL);
        float2 hi = make_float2(yacc[nt][2] * linvH, yacc[nt][3] * linvH);
        *(float2*)&g_y[((size_t)b * L_ + rl) * D_ + col] = lo;
        *(float2*)&g_y[((size_t)b * L_ + rh) * D_ + col] = hi;
    }
}

// ---------------------------------------------------------------------------
extern "C" void kernel_launch(void* const* d_in, const int* in_sizes, int n_in,
                              void* d_out, int out_size)
{
    const float* x      = (const float*)d_in[0];   // (2, 2048, 1024)
    const float* W_attn = (const float*)d_in[1];   // (1024, 3072)
    const float* b_attn = (const float*)d_in[2];   // (3072,)
    const float* W_proj = (const float*)d_in[3];   // (1024, 1024)
    const float* b_proj = (const float*)d_in[4];   // (1024,)
    const float* Er     = (const float*)d_in[5];   // (2048, 64)
    float* out = (float*)d_out;

    cudaFuncSetAttribute(attn_kernel,
                         cudaFuncAttributeMaxDynamicSharedMemorySize, ATT_SMEMB);

    float* wat; cudaGetSymbolAddress((void**)&wat, g_wat);
    float* wpt; cudaGetSymbolAddress((void**)&wpt, g_wpt);
    float* y;   cudaGetSymbolAddress((void**)&y, g_y);

    // 0) Transpose weights to [N][K] for k-contiguous B-operand loads
    transpose_kernel<<<dim3(N3D_ / 32, D_ / 32), 256>>>(W_attn, wat, D_, N3D_);
    transpose_kernel<<<dim3(D_ / 32, D_ / 32), 256>>>(W_proj, wpt, D_, D_);

    // 1) QKV projection, tf32 mma (+ head scatter, q scaling)
    gemm_mma<0><<<dim3(N3D_ / 128, BL_ / 128), 256>>>(x, wat, b_attn, nullptr);

    // 2) Causal attention with relative position bias, tf32 mma
    attn_kernel<<<dim3(B_ * H_, L_ / 64), 256, ATT_SMEMB>>>(Er);

    // 3) Output projection, tf32 mma
    gemm_mma<1><<<dim3(D_ / 128, BL_ / 128), 256>>>(y, wpt, b_proj, out);
}

// round 11
// speedup vs baseline: 2.2875x; 1.1219x over previous
#include <cuda_runtime.h>
#include <cuda_bf16.h>
#include <math.h>
#include <stdint.h>

// Problem constants
#define B_   2
#define L_   2048
#define D_   1024
#define H_   16
#define HS_  64
#define BL_  (B_ * L_)        // 4096
#define N3D_ (3 * D_)         // 3072
#define GK   1024             // K dim of both GEMMs

// Scratch (device globals; allocation in kernel_launch is forbidden)
__device__ float g_q[B_ * H_ * L_ * HS_];   // (b*H+h, l, d), pre-scaled by 1/8
__device__ float g_k[B_ * H_ * L_ * HS_];
__device__ float g_v[B_ * H_ * L_ * HS_];
__device__ float g_y[BL_ * D_];             // (b, l, h*64+d)
__device__ float g_wat[N3D_ * D_];          // W_attn^T  [3072][1024]
__device__ float g_wpt[D_ * D_];            // W_proj^T  [1024][1024]

// ---------------------------------------------------------------------------
// tf32 mma.sync helpers (sm_80+ features only — compile for plain sm_103)
// ---------------------------------------------------------------------------
__device__ __forceinline__ uint32_t f2tf(float f) {
    uint32_t u;
    asm("cvt.rna.tf32.f32 %0, %1;" : "=r"(u) : "f"(f));
    return u;
}

// D(16x8,f32) += A(16x8,tf32,row) * B(8x8,tf32,col)
__device__ __forceinline__ void mma_tf32(float* c, const uint32_t* a, const uint32_t* b) {
    asm volatile(
        "mma.sync.aligned.m16n8k8.row.col.f32.tf32.tf32.f32 "
        "{%0,%1,%2,%3},{%4,%5,%6,%7},{%8,%9},{%0,%1,%2,%3};"
        : "+f"(c[0]), "+f"(c[1]), "+f"(c[2]), "+f"(c[3])
        : "r"(a[0]), "r"(a[1]), "r"(a[2]), "r"(a[3]), "r"(b[0]), "r"(b[1]));
}

__device__ __forceinline__ void sts_tf32x4(uint32_t* p, float4 v) {
    uint4 u;
    u.x = f2tf(v.x); u.y = f2tf(v.y); u.z = f2tf(v.z); u.w = f2tf(v.w);
    *(uint4*)p = u;
}

// ---------------------------------------------------------------------------
// Transpose: src[K][N] -> dst[N][K]   (fp32; tf32 conversion happens at use)
// ---------------------------------------------------------------------------
__global__ __launch_bounds__(256) void transpose_kernel(
    const float* __restrict__ src, float* __restrict__ dst, int K, int N)
{
    __shared__ float s[32][33];
    const int tx = threadIdx.x & 31, ty = threadIdx.x >> 5;   // 32x8
    const int gx = blockIdx.x * 32, gy = blockIdx.y * 32;
#pragma unroll
    for (int j = 0; j < 4; j++)
        s[ty + j * 8][tx] = src[(size_t)(gy + ty + j * 8) * N + gx + tx];
    __syncthreads();
#pragma unroll
    for (int j = 0; j < 4; j++)
        dst[(size_t)(gx + ty + j * 8) * K + gy + tx] = s[tx][ty + j * 8];
}

// ---------------------------------------------------------------------------
// tf32 mma.sync GEMM: C[M][Ntot] = A[M][1024] x Bt[Ntot][1024]^T + bias
// (unchanged from R10 passing version)
// ---------------------------------------------------------------------------
template <int MODE>
__global__ __launch_bounds__(256, 2) void gemm_mma(
    const float* __restrict__ A, const float* __restrict__ Bt,
    const float* __restrict__ bias, float* __restrict__ outp)
{
    __shared__ float    bias_s[128];
    __shared__ uint32_t As[2][128 * 20];
    __shared__ uint32_t Bs[2][128 * 20];

    const int tid = threadIdx.x;
    const int lane = tid & 31;
    const int wid = tid >> 5;
    const int grp = lane >> 2, tig = lane & 3;
    const int wm = wid & 3, wn = wid >> 2;
    const int row0 = blockIdx.y * 128, col0 = blockIdx.x * 128;

    if (tid < 128) bias_s[tid] = bias[col0 + tid];

    const int lr = tid >> 2;
    const int lq = (tid & 3) * 4;

    float acc[2][8][4];
#pragma unroll
    for (int mt = 0; mt < 2; mt++)
#pragma unroll
        for (int nt = 0; nt < 8; nt++)
#pragma unroll
            for (int i = 0; i < 4; i++) acc[mt][nt][i] = 0.0f;

    float4 pa0, pa1, pb0, pb1;
    pa0 = *(const float4*)&A [(size_t)(row0 + lr)      * GK + lq];
    pa1 = *(const float4*)&A [(size_t)(row0 + 64 + lr) * GK + lq];
    pb0 = *(const float4*)&Bt[(size_t)(col0 + lr)      * GK + lq];
    pb1 = *(const float4*)&Bt[(size_t)(col0 + 64 + lr) * GK + lq];
    sts_tf32x4(&As[0][lr * 20 + lq],        pa0);
    sts_tf32x4(&As[0][(64 + lr) * 20 + lq], pa1);
    sts_tf32x4(&Bs[0][lr * 20 + lq],        pb0);
    sts_tf32x4(&Bs[0][(64 + lr) * 20 + lq], pb1);
    __syncthreads();

    for (int c = 0; c < 64; c++) {
        const int bf = c & 1;
        if (c < 63) {
            const int k0 = (c + 1) * 16;
            pa0 = *(const float4*)&A [(size_t)(row0 + lr)      * GK + k0 + lq];
            pa1 = *(const float4*)&A [(size_t)(row0 + 64 + lr) * GK + k0 + lq];
            pb0 = *(const float4*)&Bt[(size_t)(col0 + lr)      * GK + k0 + lq];
            pb1 = *(const float4*)&Bt[(size_t)(col0 + 64 + lr) * GK + k0 + lq];
        }

#pragma unroll
        for (int ks = 0; ks < 2; ks++) {
            const int k = ks * 8;
            uint32_t af[2][4];
#pragma unroll
            for (int mt = 0; mt < 2; mt++) {
                const uint32_t* r0 = &As[bf][(wm * 32 + mt * 16 + grp) * 20];
                af[mt][0] = r0[k + tig];
                af[mt][1] = r0[8 * 20 + k + tig];
                af[mt][2] = r0[k + tig + 4];
                af[mt][3] = r0[8 * 20 + k + tig + 4];
            }
            uint32_t bfr[8][2];
#pragma unroll
            for (int nt = 0; nt < 8; nt++) {
                const uint32_t* rb = &Bs[bf][(wn * 64 + nt * 8 + grp) * 20];
                bfr[nt][0] = rb[k + tig];
                bfr[nt][1] = rb[k + tig + 4];
            }
#pragma unroll
            for (int mt = 0; mt < 2; mt++)
#pragma unroll
                for (int nt = 0; nt < 8; nt++)
                    mma_tf32(acc[mt][nt], af[mt], bfr[nt]);
        }

        if (c < 63) {
            const int nb = bf ^ 1;
            sts_tf32x4(&As[nb][lr * 20 + lq],        pa0);
            sts_tf32x4(&As[nb][(64 + lr) * 20 + lq], pa1);
            sts_tf32x4(&Bs[nb][lr * 20 + lq],        pb0);
            sts_tf32x4(&Bs[nb][(64 + lr) * 20 + lq], pb1);
        }
        __syncthreads();
    }

#pragma unroll
    for (int nt = 0; nt < 8; nt++) {
        const int colb = col0 + wn * 64 + nt * 8;
        const int cloc = colb - col0 + 2 * tig;
        float scl = 1.0f;
        float* dstb = outp;
        int h = 0;
        if (MODE == 0) {
            const int sec = colb >> 10;
            const int cm = colb & 1023;
            h = cm >> 6;
            dstb = (sec == 0) ? g_q : (sec == 1) ? g_k : g_v;
            scl = (sec == 0) ? 0.125f : 1.0f;
        }
        const int d0 = MODE == 0 ? ((colb & 63) + 2 * tig) : 0;
#pragma unroll
        for (int mt = 0; mt < 2; mt++) {
            const int gm_lo = row0 + wm * 32 + mt * 16 + grp;
            const int gm_hi = gm_lo + 8;
            float2 lo, hi;
            lo.x = (acc[mt][nt][0] + bias_s[cloc])     * scl;
            lo.y = (acc[mt][nt][1] + bias_s[cloc + 1]) * scl;
            hi.x = (acc[mt][nt][2] + bias_s[cloc])     * scl;
            hi.y = (acc[mt][nt][3] + bias_s[cloc + 1]) * scl;
            if (MODE == 0) {
                const int bb_lo = gm_lo >> 11, l_lo = gm_lo & 2047;
                const int bb_hi = gm_hi >> 11, l_hi = gm_hi & 2047;
                *(float2*)&dstb[(((size_t)(bb_lo * H_ + h)) * L_ + l_lo) * HS_ + d0] = lo;
                *(float2*)&dstb[(((size_t)(bb_hi * H_ + h)) * L_ + l_hi) * HS_ + d0] = hi;
            } else {
                *(float2*)&outp[(size_t)gm_lo * D_ + colb + 2 * tig] = lo;
                *(float2*)&outp[(size_t)gm_hi * D_ + colb + 2 * tig] = hi;
            }
        }
    }
}

// ---------------------------------------------------------------------------
// Flash-style causal attention with relative-position bias, tf32 mma.sync.
// R11: R overlaid on Er buffer (smem 139->103KB), phase A split into K-pass +
// Er-pass (regs <=128), 2 CTAs/SM, and two paired q-tiles (by, 31-by) per
// block for uniform work (33 k-tiles each).
// ---------------------------------------------------------------------------
#define ALD 68                 // k-stride (words) for Q/K/V/S tiles
#define RLD 132                // row stride for R (overlaid on E)
#define QOFF 0                 // 64*68 = 4352
#define KOFF 4352
#define VOFF 8704
#define EOFF 13056             // 128*68 = 8704 words; R (64*132=8448) overlays
#define SOFF 21760             // 64*68 = 4352
#define MOFF 26112
#define LOFF 26176
#define AOFF 26240
#define ATT_SMEMF 26304
#define ATT_SMEMB (ATT_SMEMF * 4)   // 105216 B -> 2 CTAs/SM

__global__ __launch_bounds__(256, 2) void attn_kernel(const float* __restrict__ Er)
{
    extern __shared__ float sm[];
    uint32_t* Qs = (uint32_t*)(sm + QOFF);
    uint32_t* Ks = (uint32_t*)(sm + KOFF);
    uint32_t* Vs = (uint32_t*)(sm + VOFF);
    uint32_t* Es = (uint32_t*)(sm + EOFF);
    float*    Rf = sm + EOFF;                 // overlaid with E
    float*    Sf = sm + SOFF;                 // scores (f32) then P (tf32 bits)
    uint32_t* Su = (uint32_t*)(sm + SOFF);
    float*    Ms = sm + MOFF;
    float*    Ls = sm + LOFF;
    float*    Af = sm + AOFF;

    const int tid = threadIdx.x;
    const int wid = tid >> 5, lane = tid & 31;
    const int grp = lane >> 2, tig = lane & 3;
    const int bh = blockIdx.x;           // 0..31
    const float MINF = __int_as_float(0xff800000);

    const int m0 = (wid & 3) * 16;       // warp m-tile base (16 rows)
    const int nh = wid >> 2;             // warp n-half (0/1)
    const int b = bh >> 4, h = bh & 15;

#pragma unroll 1
    for (int tq = 0; tq < 2; tq++) {
        const int qt = tq == 0 ? (int)blockIdx.y : 31 - (int)blockIdx.y;
        const int q0 = qt * 64;

        __syncthreads();   // previous q-tile fully done (epilogue reads Ls)

        // Load Q tile (tf32)
#pragma unroll
        for (int i = 0; i < 4; i++) {
            const int idx = i * 256 + tid;
            const int row = idx >> 4, dq = (idx & 15) * 4;
            float4 v = *(const float4*)&g_q[((size_t)bh * L_ + q0 + row) * HS_ + dq];
            sts_tf32x4(&Qs[row * ALD + dq], v);
        }
        if (tid < 64) { Ms[tid] = MINF; Ls[tid] = 0.0f; }

        float yacc[4][4];
#pragma unroll
        for (int nt = 0; nt < 4; nt++)
#pragma unroll
            for (int i = 0; i < 4; i++) yacc[nt][i] = 0.0f;

#pragma unroll 1
        for (int kt = 0; kt <= qt; kt++) {
            const int k0 = kt * 64;
            __syncthreads();   // prior phase C reads (V, P) done

            // Load K, V tiles (tf32)
#pragma unroll
            for (int i = 0; i < 4; i++) {
                const int idx = i * 256 + tid;
                const int row = idx >> 4, dq = (idx & 15) * 4;
                float4 kv = *(const float4*)&g_k[((size_t)bh * L_ + k0 + row) * HS_ + dq];
                float4 vv = *(const float4*)&g_v[((size_t)bh * L_ + k0 + row) * HS_ + dq];
                sts_tf32x4(&Ks[row * ALD + dq], kv);
                sts_tf32x4(&Vs[row * ALD + dq], vv);
            }
            // Load Er window (128 rows; clamped rows are causally masked)
            const int eBase = (L_ - 1) + k0 - q0 - 63;
#pragma unroll
            for (int i = 0; i < 8; i++) {
                const int idx = i * 256 + tid;
                const int row = idx >> 4, dq = (idx & 15) * 4;
                int er = eBase + row; if (er > L_ - 1) er = L_ - 1;
                float4 v = *(const float4*)&Er[(size_t)er * HS_ + dq];
                sts_tf32x4(&Es[row * ALD + dq], v);
            }
            __syncthreads();

            // ---- Phase A / K-pass: S(64x64) = Q x K^T  (warp: 16r x 32c) ----
            {
                float ka[4][4];
#pragma unroll
                for (int nt = 0; nt < 4; nt++)
#pragma unroll
                    for (int i = 0; i < 4; i++) ka[nt][i] = 0.0f;
#pragma unroll
                for (int ks = 0; ks < 8; ks++) {
                    const int k = ks * 8;
                    uint32_t af[4];
                    const uint32_t* qp = &Qs[(m0 + grp) * ALD];
                    af[0] = qp[k + tig];
                    af[1] = qp[8 * ALD + k + tig];
                    af[2] = qp[k + tig + 4];
                    af[3] = qp[8 * ALD + k + tig + 4];
#pragma unroll
                    for (int nt = 0; nt < 4; nt++) {
                        const uint32_t* rb = &Ks[(nh * 32 + nt * 8 + grp) * ALD];
                        uint32_t bfv[2];
                        bfv[0] = rb[k + tig];
                        bfv[1] = rb[k + tig + 4];
                        mma_tf32(ka[nt], af, bfv);
                    }
                }
#pragma unroll
                for (int nt = 0; nt < 4; nt++) {
                    const int cb = nh * 32 + nt * 8 + 2 * tig;
                    *(float2*)&Sf[(m0 + grp) * ALD + cb]     = make_float2(ka[nt][0], ka[nt][1]);
                    *(float2*)&Sf[(m0 + 8 + grp) * ALD + cb] = make_float2(ka[nt][2], ka[nt][3]);
                }
            }

            // ---- Phase A / Er-pass: R(64x128) = Q x ErW^T (warp: 16r x 64c) ----
            float ea[8][4];
#pragma unroll
            for (int nt = 0; nt < 8; nt++)
#pragma unroll
                for (int i = 0; i < 4; i++) ea[nt][i] = 0.0f;
#pragma unroll
            for (int ks = 0; ks < 8; ks++) {
                const int k = ks * 8;
                uint32_t af[4];
                const uint32_t* qp = &Qs[(m0 + grp) * ALD];
                af[0] = qp[k + tig];
                af[1] = qp[8 * ALD + k + tig];
                af[2] = qp[k + tig + 4];
                af[3] = qp[8 * ALD + k + tig + 4];
#pragma unroll
                for (int nt = 0; nt < 8; nt++) {
                    const uint32_t* rb = &Es[(nh * 64 + nt * 8 + grp) * ALD];
                    uint32_t bfv[2];
                    bfv[0] = rb[k + tig];
                    bfv[1] = rb[k + tig + 4];
                    mma_tf32(ea[nt], af, bfv);
                }
            }
            __syncthreads();   // ALL Er reads complete before R overlays E
#pragma unroll
            for (int nt = 0; nt < 8; nt++) {
                const int cb = nh * 64 + nt * 8 + 2 * tig;
                *(float2*)&Rf[(m0 + grp) * RLD + cb]     = make_float2(ea[nt][0], ea[nt][1]);
                *(float2*)&Rf[(m0 + 8 + grp) * RLD + cb] = make_float2(ea[nt][2], ea[nt][3]);
            }
            __syncthreads();

            // ---- Phase B: online softmax; write P back as tf32 bits ----
            const bool diag = (kt == qt);
#pragma unroll
            for (int rr = 0; rr < 8; rr++) {
                const int i = wid * 8 + rr;
                const float* rrow = &Rf[i * RLD + 63 - i];
                float s0 = Sf[i * ALD + lane]      + rrow[lane];
                float s1 = Sf[i * ALD + 32 + lane] + rrow[32 + lane];
                if (diag) {
                    if (lane > i) s0 = MINF;
                    if (32 + lane > i) s1 = MINF;
                }
                float mx = fmaxf(s0, s1);
#pragma unroll
                for (int off = 16; off > 0; off >>= 1)
                    mx = fmaxf(mx, __shfl_xor_sync(0xffffffffu, mx, off));
                const float mold = Ms[i];
                const float mnew = fmaxf(mold, mx);
                const float p0 = __expf(s0 - mnew);
                const float p1 = __expf(s1 - mnew);
                Su[i * ALD + lane]      = f2tf(p0);
                Su[i * ALD + 32 + lane] = f2tf(p1);
                float ps = p0 + p1;
#pragma unroll
                for (int off = 16; off > 0; off >>= 1)
                    ps += __shfl_xor_sync(0xffffffffu, ps, off);
                if (lane == 0) {
                    const float al = __expf(mold - mnew);   // 0 on first tile
                    Af[i] = al;
                    Ls[i] = Ls[i] * al + ps;
                    Ms[i] = mnew;
                }
            }
            __syncthreads();

            // ---- Phase C: Y = Y*alpha + P.V  (warp: 16 rows x 32 cols) ----
            const int n0c = nh * 32;
            const float aL = Af[m0 + grp], aH = Af[m0 + 8 + grp];
#pragma unroll
            for (int nt = 0; nt < 4; nt++) {
                yacc[nt][0] *= aL; yacc[nt][1] *= aL;
                yacc[nt][2] *= aH; yacc[nt][3] *= aH;
            }
#pragma unroll
            for (int ks = 0; ks < 8; ks++) {
                const int k = ks * 8;
                uint32_t af[4];
                const uint32_t* pp = &Su[(m0 + grp) * ALD];
                af[0] = pp[k + tig];
                af[1] = pp[8 * ALD + k + tig];
                af[2] = pp[k + tig + 4];
                af[3] = pp[8 * ALD + k + tig + 4];
#pragma unroll
                for (int nt = 0; nt < 4; nt++) {
                    uint32_t bfv[2];
                    bfv[0] = Vs[(k + tig) * ALD + n0c + nt * 8 + grp];
                    bfv[1] = Vs[(k + tig + 4) * ALD + n0c + nt * 8 + grp];
                    mma_tf32(yacc[nt], af, bfv);
                }
            }
        }

        // ---- Epilogue: normalize, write (B, L, D) ----
        const int n0c = nh * 32;
        const float linvL = 1.0f / Ls[m0 + grp];
        const float linvH = 1.0f / Ls[m0 + 8 + grp];
#pragma unroll
        for (int nt = 0; nt < 4; nt++) {
            const int col = h * 64 + n0c + nt * 8 + 2 * tig;
            const int rl = q0 + m0 + grp, rh = rl + 8;
            float2 lo = make_float2(yacc[nt][0] * linvL, yacc[nt][1] * linvL);
            float2 hi = make_float2(yacc[nt][2] * linvH, yacc[nt][3] * linvH);
            *(float2*)&g_y[((size_t)b * L_ + rl) * D_ + col] = lo;
            *(float2*)&g_y[((size_t)b * L_ + rh) * D_ + col] = hi;
        }
    }
}

// ---------------------------------------------------------------------------
extern "C" void kernel_launch(void* const* d_in, const int* in_sizes, int n_in,
                              void* d_out, int out_size)
{
    const float* x      = (const float*)d_in[0];   // (2, 2048, 1024)
    const float* W_attn = (const float*)d_in[1];   // (1024, 3072)
    const float* b_attn = (const float*)d_in[2];   // (3072,)
    const float* W_proj = (const float*)d_in[3];   // (1024, 1024)
    const float* b_proj = (const float*)d_in[4];   // (1024,)
    const float* Er     = (const float*)d_in[5];   // (2048, 64)
    float* out = (float*)d_out;

    cudaFuncSetAttribute(attn_kernel,
                         cudaFuncAttributeMaxDynamicSharedMemorySize, ATT_SMEMB);

    float* wat; cudaGetSymbolAddress((void**)&wat, g_wat);
    float* wpt; cudaGetSymbolAddress((void**)&wpt, g_wpt);
    float* y;   cudaGetSymbolAddress((void**)&y, g_y);

    // 0) Transpose weights to [N][K] for k-contiguous B-operand loads
    transpose_kernel<<<dim3(N3D_ / 32, D_ / 32), 256>>>(W_attn, wat, D_, N3D_);
    transpose_kernel<<<dim3(D_ / 32, D_ / 32), 256>>>(W_proj, wpt, D_, D_);

    // 1) QKV projection, tf32 mma (+ head scatter, q scaling)
    gemm_mma<0><<<dim3(N3D_ / 128, BL_ / 128), 256>>>(x, wat, b_attn, nullptr);

    // 2) Causal attention with relative position bias, tf32 mma
    attn_kernel<<<dim3(B_ * H_, 16), 256, ATT_SMEMB>>>(Er);

    // 3) Output projection, tf32 mma
    gemm_mma<1><<<dim3(D_ / 128, BL_ / 128), 256>>>(y, wpt, b_proj, out);
}

// round 12
// speedup vs baseline: 2.4992x; 1.0925x over previous
#include <cuda_runtime.h>
#include <cuda_bf16.h>
#include <math.h>
#include <stdint.h>

// Problem constants
#define B_   2
#define L_   2048
#define D_   1024
#define H_   16
#define HS_  64
#define BL_  (B_ * L_)        // 4096
#define N3D_ (3 * D_)         // 3072
#define GK   1024             // K dim of both GEMMs

// Scratch (device globals; allocation in kernel_launch is forbidden)
__device__ float g_q[B_ * H_ * L_ * HS_];   // (b*H+h, l, d), pre-scaled by 1/8
__device__ float g_k[B_ * H_ * L_ * HS_];
__device__ float g_v[B_ * H_ * L_ * HS_];
__device__ float g_y[BL_ * D_];             // (b, l, h*64+d)
__device__ float g_wat[N3D_ * D_];          // W_attn^T  [3072][1024]
__device__ float g_wpt[D_ * D_];            // W_proj^T  [1024][1024]

// ---------------------------------------------------------------------------
// tf32 mma.sync helpers (sm_80+ features only — compile for plain sm_103)
// ---------------------------------------------------------------------------
__device__ __forceinline__ uint32_t f2tf(float f) {
    uint32_t u;
    asm("cvt.rna.tf32.f32 %0, %1;" : "=r"(u) : "f"(f));
    return u;
}

// D(16x8,f32) += A(16x8,tf32,row) * B(8x8,tf32,col)
__device__ __forceinline__ void mma_tf32(float* c, const uint32_t* a, const uint32_t* b) {
    asm volatile(
        "mma.sync.aligned.m16n8k8.row.col.f32.tf32.tf32.f32 "
        "{%0,%1,%2,%3},{%4,%5,%6,%7},{%8,%9},{%0,%1,%2,%3};"
        : "+f"(c[0]), "+f"(c[1]), "+f"(c[2]), "+f"(c[3])
        : "r"(a[0]), "r"(a[1]), "r"(a[2]), "r"(a[3]), "r"(b[0]), "r"(b[1]));
}

__device__ __forceinline__ void sts_tf32x4(uint32_t* p, float4 v) {
    uint4 u;
    u.x = f2tf(v.x); u.y = f2tf(v.y); u.z = f2tf(v.z); u.w = f2tf(v.w);
    *(uint4*)p = u;
}

// Fast exp on the FMA/ALU pipes (no MUFU). Valid for x <= 0 (clamped at -87);
// magic-number round-to-nearest, degree-5 poly on [-0.5,0.5], exponent splice.
__device__ __forceinline__ float fexp(float x) {
    x = fmaxf(x, -87.0f);
    const float L2E = 1.4426950408889634f;
    float y = fmaf(x, L2E, 12582912.0f);           // RN to integer (2^23+2^22)
    int   n = __float_as_int(y) - 0x4B400000;      // integer part (signed)
    float fl = y - 12582912.0f;
    float f = fmaf(x, L2E, -fl);                   // f in [-0.5, 0.5]
    float p = 1.3333558146428443e-3f;
    p = fmaf(p, f, 9.6181291076284772e-3f);
    p = fmaf(p, f, 5.5504108664821580e-2f);
    p = fmaf(p, f, 2.4022650695910071e-1f);
    p = fmaf(p, f, 6.9314718055994531e-1f);
    p = fmaf(p, f, 1.0f);                          // p in [0.70, 1.42]
    return __int_as_float(__float_as_int(p) + (n << 23));
}

// ---------------------------------------------------------------------------
// Transpose: src[K][N] -> dst[N][K]
// ---------------------------------------------------------------------------
__global__ __launch_bounds__(256) void transpose_kernel(
    const float* __restrict__ src, float* __restrict__ dst, int K, int N)
{
    __shared__ float s[32][33];
    const int tx = threadIdx.x & 31, ty = threadIdx.x >> 5;   // 32x8
    const int gx = blockIdx.x * 32, gy = blockIdx.y * 32;
#pragma unroll
    for (int j = 0; j < 4; j++)
        s[ty + j * 8][tx] = src[(size_t)(gy + ty + j * 8) * N + gx + tx];
    __syncthreads();
#pragma unroll
    for (int j = 0; j < 4; j++)
        dst[(size_t)(gx + ty + j * 8) * K + gy + tx] = s[tx][ty + j * 8];
}

// ---------------------------------------------------------------------------
// tf32 mma.sync GEMM (unchanged from R11 passing version)
// ---------------------------------------------------------------------------
template <int MODE>
__global__ __launch_bounds__(256, 2) void gemm_mma(
    const float* __restrict__ A, const float* __restrict__ Bt,
    const float* __restrict__ bias, float* __restrict__ outp)
{
    __shared__ float    bias_s[128];
    __shared__ uint32_t As[2][128 * 20];
    __shared__ uint32_t Bs[2][128 * 20];

    const int tid = threadIdx.x;
    const int lane = tid & 31;
    const int wid = tid >> 5;
    const int grp = lane >> 2, tig = lane & 3;
    const int wm = wid & 3, wn = wid >> 2;
    const int row0 = blockIdx.y * 128, col0 = blockIdx.x * 128;

    if (tid < 128) bias_s[tid] = bias[col0 + tid];

    const int lr = tid >> 2;
    const int lq = (tid & 3) * 4;

    float acc[2][8][4];
#pragma unroll
    for (int mt = 0; mt < 2; mt++)
#pragma unroll
        for (int nt = 0; nt < 8; nt++)
#pragma unroll
            for (int i = 0; i < 4; i++) acc[mt][nt][i] = 0.0f;

    float4 pa0, pa1, pb0, pb1;
    pa0 = *(const float4*)&A [(size_t)(row0 + lr)      * GK + lq];
    pa1 = *(const float4*)&A [(size_t)(row0 + 64 + lr) * GK + lq];
    pb0 = *(const float4*)&Bt[(size_t)(col0 + lr)      * GK + lq];
    pb1 = *(const float4*)&Bt[(size_t)(col0 + 64 + lr) * GK + lq];
    sts_tf32x4(&As[0][lr * 20 + lq],        pa0);
    sts_tf32x4(&As[0][(64 + lr) * 20 + lq], pa1);
    sts_tf32x4(&Bs[0][lr * 20 + lq],        pb0);
    sts_tf32x4(&Bs[0][(64 + lr) * 20 + lq], pb1);
    __syncthreads();

    for (int c = 0; c < 64; c++) {
        const int bf = c & 1;
        if (c < 63) {
            const int k0 = (c + 1) * 16;
            pa0 = *(const float4*)&A [(size_t)(row0 + lr)      * GK + k0 + lq];
            pa1 = *(const float4*)&A [(size_t)(row0 + 64 + lr) * GK + k0 + lq];
            pb0 = *(const float4*)&Bt[(size_t)(col0 + lr)      * GK + k0 + lq];
            pb1 = *(const float4*)&Bt[(size_t)(col0 + 64 + lr) * GK + k0 + lq];
        }

#pragma unroll
        for (int ks = 0; ks < 2; ks++) {
            const int k = ks * 8;
            uint32_t af[2][4];
#pragma unroll
            for (int mt = 0; mt < 2; mt++) {
                const uint32_t* r0 = &As[bf][(wm * 32 + mt * 16 + grp) * 20];
                af[mt][0] = r0[k + tig];
                af[mt][1] = r0[8 * 20 + k + tig];
                af[mt][2] = r0[k + tig + 4];
                af[mt][3] = r0[8 * 20 + k + tig + 4];
            }
            uint32_t bfr[8][2];
#pragma unroll
            for (int nt = 0; nt < 8; nt++) {
                const uint32_t* rb = &Bs[bf][(wn * 64 + nt * 8 + grp) * 20];
                bfr[nt][0] = rb[k + tig];
                bfr[nt][1] = rb[k + tig + 4];
            }
#pragma unroll
            for (int mt = 0; mt < 2; mt++)
#pragma unroll
                for (int nt = 0; nt < 8; nt++)
                    mma_tf32(acc[mt][nt], af[mt], bfr[nt]);
        }

        if (c < 63) {
            const int nb = bf ^ 1;
            sts_tf32x4(&As[nb][lr * 20 + lq],        pa0);
            sts_tf32x4(&As[nb][(64 + lr) * 20 + lq], pa1);
            sts_tf32x4(&Bs[nb][lr * 20 + lq],        pb0);
            sts_tf32x4(&Bs[nb][(64 + lr) * 20 + lq], pb1);
        }
        __syncthreads();
    }

#pragma unroll
    for (int nt = 0; nt < 8; nt++) {
        const int colb = col0 + wn * 64 + nt * 8;
        const int cloc = colb - col0 + 2 * tig;
        float scl = 1.0f;
        float* dstb = outp;
        int h = 0;
        if (MODE == 0) {
            const int sec = colb >> 10;
            const int cm = colb & 1023;
            h = cm >> 6;
            dstb = (sec == 0) ? g_q : (sec == 1) ? g_k : g_v;
            scl = (sec == 0) ? 0.125f : 1.0f;
        }
        const int d0 = MODE == 0 ? ((colb & 63) + 2 * tig) : 0;
#pragma unroll
        for (int mt = 0; mt < 2; mt++) {
            const int gm_lo = row0 + wm * 32 + mt * 16 + grp;
            const int gm_hi = gm_lo + 8;
            float2 lo, hi;
            lo.x = (acc[mt][nt][0] + bias_s[cloc])     * scl;
            lo.y = (acc[mt][nt][1] + bias_s[cloc + 1]) * scl;
            hi.x = (acc[mt][nt][2] + bias_s[cloc])     * scl;
            hi.y = (acc[mt][nt][3] + bias_s[cloc + 1]) * scl;
            if (MODE == 0) {
                const int bb_lo = gm_lo >> 11, l_lo = gm_lo & 2047;
                const int bb_hi = gm_hi >> 11, l_hi = gm_hi & 2047;
                *(float2*)&dstb[(((size_t)(bb_lo * H_ + h)) * L_ + l_lo) * HS_ + d0] = lo;
                *(float2*)&dstb[(((size_t)(bb_hi * H_ + h)) * L_ + l_hi) * HS_ + d0] = hi;
            } else {
                *(float2*)&outp[(size_t)gm_lo * D_ + colb + 2 * tig] = lo;
                *(float2*)&outp[(size_t)gm_hi * D_ + colb + 2 * tig] = hi;
            }
        }
    }
}

// ---------------------------------------------------------------------------
// Flash-style causal attention with relative-position bias, tf32 mma.sync.
// R12: (a) fexp on FMA pipe instead of MUFU __expf; (b) incremental Er window:
// consecutive k-tile windows overlap by 64 rows, so only the NEW 64x64 R half
// is computed per tile (ping-pong halves, phys col = (u + 64*kt) & 127);
// (c) K-pass and new-half Er-pass merged (shared Q fragments); (d) E buffer
// overlays S (E consumed before S written). Smem 104KB -> 2 CTAs/SM.
// ---------------------------------------------------------------------------
#define ALD 68                 // k-stride (words) for Q/K/V/E/S tiles
#define RLD 132                // row stride for R (128 cols + pad)
#define QOFF 0                 // 64*68 = 4352
#define KOFF 4352
#define VOFF 8704
#define ESOFF 13056            // E (64x68) overlaid with S (64x68)
#define ROFF 17408             // R: 64*132 = 8448
#define MOFF 25856
#define LOFF 25920
#define AOFF 25984
#define ATT_SMEMF 26048
#define ATT_SMEMB (ATT_SMEMF * 4)   // 104192 B -> 2 CTAs/SM

__global__ __launch_bounds__(256, 2) void attn_kernel(const float* __restrict__ Er)
{
    extern __shared__ float sm[];
    uint32_t* Qs = (uint32_t*)(sm + QOFF);
    uint32_t* Ks = (uint32_t*)(sm + KOFF);
    uint32_t* Vs = (uint32_t*)(sm + VOFF);
    uint32_t* Es = (uint32_t*)(sm + ESOFF);   // E tile; later overlaid by S
    float*    Sf = sm + ESOFF;                // scores (f32) then P (tf32 bits)
    uint32_t* Su = (uint32_t*)(sm + ESOFF);
    float*    Rf = sm + ROFF;
    float*    Ms = sm + MOFF;
    float*    Ls = sm + LOFF;
    float*    Af = sm + AOFF;

    const int tid = threadIdx.x;
    const int wid = tid >> 5, lane = tid & 31;
    const int grp = lane >> 2, tig = lane & 3;
    const int bh = blockIdx.x;           // 0..31
    const float MINF = __int_as_float(0xff800000);

    const int m0 = (wid & 3) * 16;       // warp m-tile base (16 rows)
    const int nh = wid >> 2;             // warp n-half (0/1)
    const int b = bh >> 4, h = bh & 15;

#pragma unroll 1
    for (int tq = 0; tq < 2; tq++) {
        const int qt = tq == 0 ? (int)blockIdx.y : 31 - (int)blockIdx.y;
        const int q0 = qt * 64;

        __syncthreads();   // previous q-tile fully done

        // Load Q tile (tf32)
#pragma unroll
        for (int i = 0; i < 4; i++) {
            const int idx = i * 256 + tid;
            const int row = idx >> 4, dq = (idx & 15) * 4;
            float4 v = *(const float4*)&g_q[((size_t)bh * L_ + q0 + row) * HS_ + dq];
            sts_tf32x4(&Qs[row * ALD + dq], v);
        }
        if (tid < 64) { Ms[tid] = MINF; Ls[tid] = 0.0f; }

        float yacc[4][4];
#pragma unroll
        for (int nt = 0; nt < 4; nt++)
#pragma unroll
            for (int i = 0; i < 4; i++) yacc[nt][i] = 0.0f;

#pragma unroll 1
        for (int kt = 0; kt <= qt; kt++) {
            const int k0 = kt * 64;
            const int eBase = (L_ - 1) + k0 - q0 - 63;
            __syncthreads();   // prior PV (S,V) and softmax (R) reads done

            // Load K, V tiles (tf32)
#pragma unroll
            for (int i = 0; i < 4; i++) {
                const int idx = i * 256 + tid;
                const int row = idx >> 4, dq = (idx & 15) * 4;
                float4 kv = *(const float4*)&g_k[((size_t)bh * L_ + k0 + row) * HS_ + dq];
                float4 vv = *(const float4*)&g_v[((size_t)bh * L_ + k0 + row) * HS_ + dq];
                sts_tf32x4(&Ks[row * ALD + dq], kv);
                sts_tf32x4(&Vs[row * ALD + dq], vv);
            }

            if (kt == 0) {
                // one-time: compute R half for window offsets [0..63]
#pragma unroll
                for (int i = 0; i < 4; i++) {
                    const int idx = i * 256 + tid;
                    const int row = idx >> 4, dq = (idx & 15) * 4;
                    int er = eBase + row; if (er > L_ - 1) er = L_ - 1;
                    float4 v = *(const float4*)&Er[(size_t)er * HS_ + dq];
                    sts_tf32x4(&Es[row * ALD + dq], v);
                }
                __syncthreads();
                float ea0[4][4];
#pragma unroll
                for (int nt = 0; nt < 4; nt++)
#pragma unroll
                    for (int i = 0; i < 4; i++) ea0[nt][i] = 0.0f;
#pragma unroll
                for (int ks = 0; ks < 8; ks++) {
                    const int k = ks * 8;
                    uint32_t qf[4];
                    const uint32_t* qp = &Qs[(m0 + grp) * ALD];
                    qf[0] = qp[k + tig];
                    qf[1] = qp[8 * ALD + k + tig];
                    qf[2] = qp[k + tig + 4];
                    qf[3] = qp[8 * ALD + k + tig + 4];
#pragma unroll
                    for (int nt = 0; nt < 4; nt++) {
                        const uint32_t* rb = &Es[(nh * 32 + nt * 8 + grp) * ALD];
                        uint32_t bfv[2];
                        bfv[0] = rb[k + tig];
                        bfv[1] = rb[k + tig + 4];
                        mma_tf32(ea0[nt], qf, bfv);
                    }
                }
#pragma unroll
                for (int nt = 0; nt < 4; nt++) {
                    const int cb = nh * 32 + nt * 8 + 2 * tig;   // phys base 0
                    *(float2*)&Rf[(m0 + grp) * RLD + cb]     = make_float2(ea0[nt][0], ea0[nt][1]);
                    *(float2*)&Rf[(m0 + 8 + grp) * RLD + cb] = make_float2(ea0[nt][2], ea0[nt][3]);
                }
                __syncthreads();   // all E reads done before reloading E below
            }

            // Load E new half: window offsets [64..127] = Er rows eBase+64..
#pragma unroll
            for (int i = 0; i < 4; i++) {
                const int idx = i * 256 + tid;
                const int row = idx >> 4, dq = (idx & 15) * 4;
                int er = eBase + 64 + row; if (er > L_ - 1) er = L_ - 1;
                float4 v = *(const float4*)&Er[(size_t)er * HS_ + dq];
                sts_tf32x4(&Es[row * ALD + dq], v);
            }
            __syncthreads();

            // ---- Merged phase A: ka = Q.K^T tile, ea = Q.Enew^T tile ----
            float ka[4][4], ea[4][4];
#pragma unroll
            for (int nt = 0; nt < 4; nt++)
#pragma unroll
                for (int i = 0; i < 4; i++) { ka[nt][i] = 0.0f; ea[nt][i] = 0.0f; }
#pragma unroll
            for (int ks = 0; ks < 8; ks++) {
                const int k = ks * 8;
                uint32_t qf[4];
                const uint32_t* qp = &Qs[(m0 + grp) * ALD];
                qf[0] = qp[k + tig];
                qf[1] = qp[8 * ALD + k + tig];
                qf[2] = qp[k + tig + 4];
                qf[3] = qp[8 * ALD + k + tig + 4];
#pragma unroll
                for (int nt = 0; nt < 4; nt++) {
                    const uint32_t* rb = &Ks[(nh * 32 + nt * 8 + grp) * ALD];
                    uint32_t bfv[2];
                    bfv[0] = rb[k + tig];
                    bfv[1] = rb[k + tig + 4];
                    mma_tf32(ka[nt], qf, bfv);
                }
#pragma unroll
                for (int nt = 0; nt < 4; nt++) {
                    const uint32_t* rb = &Es[(nh * 32 + nt * 8 + grp) * ALD];
                    uint32_t bfv[2];
                    bfv[0] = rb[k + tig];
                    bfv[1] = rb[k + tig + 4];
                    mma_tf32(ea[nt], qf, bfv);
                }
            }
            __syncthreads();   // all E reads done before S overlays E

            // Store S (over E) and R new half (phys base alternates)
            const int pb = ((kt + 1) & 1) * 64;
#pragma unroll
            for (int nt = 0; nt < 4; nt++) {
                const int cb = nh * 32 + nt * 8 + 2 * tig;
                *(float2*)&Sf[(m0 + grp) * ALD + cb]     = make_float2(ka[nt][0], ka[nt][1]);
                *(float2*)&Sf[(m0 + 8 + grp) * ALD + cb] = make_float2(ka[nt][2], ka[nt][3]);
                *(float2*)&Rf[(m0 + grp) * RLD + pb + cb]     = make_float2(ea[nt][0], ea[nt][1]);
                *(float2*)&Rf[(m0 + 8 + grp) * RLD + pb + cb] = make_float2(ea[nt][2], ea[nt][3]);
            }
            __syncthreads();

            // ---- Phase B: online softmax (fexp); P written as tf32 bits ----
            const bool diag = (kt == qt);
            const int rphase = (kt & 1) * 64;
#pragma unroll
            for (int rr = 0; rr < 8; rr++) {
                const int i = wid * 8 + rr;
                const int ro = 63 - i + rphase;
                const float* rrow = &Rf[i * RLD];
                const float r0 = rrow[(ro + lane) & 127];
                const float r1 = rrow[(ro + 32 + lane) & 127];
                float s0 = Sf[i * ALD + lane]      + r0;
                float s1 = Sf[i * ALD + 32 + lane] + r1;
                if (diag) {
                    if (lane > i) s0 = MINF;
                    if (32 + lane > i) s1 = MINF;
                }
                float mx = fmaxf(s0, s1);
#pragma unroll
                for (int off = 16; off > 0; off >>= 1)
                    mx = fmaxf(mx, __shfl_xor_sync(0xffffffffu, mx, off));
                const float mold = Ms[i];
                const float mnew = fmaxf(mold, mx);
                const float p0 = fexp(s0 - mnew);
                const float p1 = fexp(s1 - mnew);
                Su[i * ALD + lane]      = f2tf(p0);
                Su[i * ALD + 32 + lane] = f2tf(p1);
                float ps = p0 + p1;
#pragma unroll
                for (int off = 16; off > 0; off >>= 1)
                    ps += __shfl_xor_sync(0xffffffffu, ps, off);
                if (lane == 0) {
                    const float al = fexp(mold - mnew);   // ~0 on first tile
                    Af[i] = al;
                    Ls[i] = Ls[i] * al + ps;
                    Ms[i] = mnew;
                }
            }
            __syncthreads();

            // ---- Phase C: Y = Y*alpha + P.V  (warp: 16 rows x 32 cols) ----
            const int n0c = nh * 32;
            const float aL = Af[m0 + grp], aH = Af[m0 + 8 + grp];
#pragma unroll
            for (int nt = 0; nt < 4; nt++) {
                yacc[nt][0] *= aL; yacc[nt][1] *= aL;
                yacc[nt][2] *= aH; yacc[nt][3] *= aH;
            }
#pragma unroll
            for (int ks = 0; ks < 8; ks++) {
                const int k = ks * 8;
                uint32_t pf[4];
                const uint32_t* pp = &Su[(m0 + grp) * ALD];
                pf[0] = pp[k + tig];
                pf[1] = pp[8 * ALD + k + tig];
                pf[2] = pp[k + tig + 4];
                pf[3] = pp[8 * ALD + k + tig + 4];
#pragma unroll
                for (int nt = 0; nt < 4; nt++) {
                    uint32_t bfv[2];
                    bfv[0] = Vs[(k + tig) * ALD + n0c + nt * 8 + grp];
                    bfv[1] = Vs[(k + tig + 4) * ALD + n0c + nt * 8 + grp];
                    mma_tf32(yacc[nt], pf, bfv);
                }
            }
        }

        // ---- Epilogue: normalize, write (B, L, D) ----
        const int n0c = nh * 32;
        const float linvL = 1.0f / Ls[m0 + grp];
        const float linvH = 1.0f / Ls[m0 + 8 + grp];
#pragma unroll
        for (int nt = 0; nt < 4; nt++) {
            const int col = h * 64 + n0c + nt * 8 + 2 * tig;
            const int rl = q0 + m0 + grp, rh = rl + 8;
            float2 lo = make_float2(yacc[nt][0] * linvL, yacc[nt][1] * linvL);
            float2 hi = make_float2(yacc[nt][2] * linvH, yacc[nt][3] * linvH);
            *(float2*)&g_y[((size_t)b * L_ + rl) * D_ + col] = lo;
            *(float2*)&g_y[((size_t)b * L_ + rh) * D_ + col] = hi;
        }
    }
}

// ---------------------------------------------------------------------------
extern "C" void kernel_launch(void* const* d_in, const int* in_sizes, int n_in,
                              void* d_out, int out_size)
{
    const float* x      = (const float*)d_in[0];   // (2, 2048, 1024)
    const float* W_attn = (const float*)d_in[1];   // (1024, 3072)
    const float* b_attn = (const float*)d_in[2];   // (3072,)
    const float* W_proj = (const float*)d_in[3];   // (1024, 1024)
    const float* b_proj = (const float*)d_in[4];   // (1024,)
    const float* Er     = (const float*)d_in[5];   // (2048, 64)
    float* out = (float*)d_out;

    cudaFuncSetAttribute(attn_kernel,
                         cudaFuncAttributeMaxDynamicSharedMemorySize, ATT_SMEMB);

    float* wat; cudaGetSymbolAddress((void**)&wat, g_wat);
    float* wpt; cudaGetSymbolAddress((void**)&wpt, g_wpt);
    float* y;   cudaGetSymbolAddress((void**)&y, g_y);

    // 0) Transpose weights to [N][K] for k-contiguous B-operand loads
    transpose_kernel<<<dim3(N3D_ / 32, D_ / 32), 256>>>(W_attn, wat, D_, N3D_);
    transpose_kernel<<<dim3(D_ / 32, D_ / 32), 256>>>(W_proj, wpt, D_, D_);

    // 1) QKV projection, tf32 mma (+ head scatter, q scaling)
    gemm_mma<0><<<dim3(N3D_ / 128, BL_ / 128), 256>>>(x, wat, b_attn, nullptr);

    // 2) Causal attention with relative position bias, tf32 mma
    attn_kernel<<<dim3(B_ * H_, 16), 256, ATT_SMEMB>>>(Er);

    // 3) Output projection, tf32 mma
    gemm_mma<1><<<dim3(D_ / 128, BL_ / 128), 256>>>(y, wpt, b_proj, out);
}

// round 13
// speedup vs baseline: 2.6769x; 1.0711x over previous
#include <cuda_runtime.h>
#include <cuda_bf16.h>
#include <cuda_fp16.h>
#include <math.h>
#include <stdint.h>

// Problem constants
#define B_   2
#define L_   2048
#define D_   1024
#define H_   16
#define HS_  64
#define BL_  (B_ * L_)        // 4096
#define N3D_ (3 * D_)         // 3072
#define GK   1024             // K dim of both GEMMs

// Scratch (device globals; allocation in kernel_launch is forbidden)
__device__ float g_q[B_ * H_ * L_ * HS_];   // (b*H+h, l, d), pre-scaled by 1/8
__device__ float g_k[B_ * H_ * L_ * HS_];
__device__ float g_v[B_ * H_ * L_ * HS_];
__device__ float g_y[BL_ * D_];             // (b, l, h*64+d)
__device__ float g_wat[N3D_ * D_];          // W_attn^T  [3072][1024]
__device__ float g_wpt[D_ * D_];            // W_proj^T  [1024][1024]

// ---------------------------------------------------------------------------
// tf32 mma.sync helpers
// ---------------------------------------------------------------------------
__device__ __forceinline__ uint32_t f2tf(float f) {
    uint32_t u;
    asm("cvt.rna.tf32.f32 %0, %1;" : "=r"(u) : "f"(f));
    return u;
}

// D(16x8,f32) += A(16x8,tf32,row) * B(8x8,tf32,col)
__device__ __forceinline__ void mma_tf32(float* c, const uint32_t* a, const uint32_t* b) {
    asm volatile(
        "mma.sync.aligned.m16n8k8.row.col.f32.tf32.tf32.f32 "
        "{%0,%1,%2,%3},{%4,%5,%6,%7},{%8,%9},{%0,%1,%2,%3};"
        : "+f"(c[0]), "+f"(c[1]), "+f"(c[2]), "+f"(c[3])
        : "r"(a[0]), "r"(a[1]), "r"(a[2]), "r"(a[3]), "r"(b[0]), "r"(b[1]));
}

__device__ __forceinline__ void sts_tf32x4(uint32_t* p, float4 v) {
    uint4 u;
    u.x = f2tf(v.x); u.y = f2tf(v.y); u.z = f2tf(v.z); u.w = f2tf(v.w);
    *(uint4*)p = u;
}

// Fast exp on the FMA/ALU pipes (no MUFU). Valid for x <= 0 (clamped at -87).
__device__ __forceinline__ float fexp(float x) {
    x = fmaxf(x, -87.0f);
    const float L2E = 1.4426950408889634f;
    float y = fmaf(x, L2E, 12582912.0f);           // RN to integer
    int   n = __float_as_int(y) - 0x4B400000;
    float fl = y - 12582912.0f;
    float f = fmaf(x, L2E, -fl);                   // f in [-0.5, 0.5]
    float p = 1.3333558146428443e-3f;
    p = fmaf(p, f, 9.6181291076284772e-3f);
    p = fmaf(p, f, 5.5504108664821580e-2f);
    p = fmaf(p, f, 2.4022650695910071e-1f);
    p = fmaf(p, f, 6.9314718055994531e-1f);
    p = fmaf(p, f, 1.0f);
    return __int_as_float(__float_as_int(p) + (n << 23));
}

// ---------------------------------------------------------------------------
// Transpose: src[K][N] -> dst[N][K]
// ---------------------------------------------------------------------------
__global__ __launch_bounds__(256) void transpose_kernel(
    const float* __restrict__ src, float* __restrict__ dst, int K, int N)
{
    __shared__ float s[32][33];
    const int tx = threadIdx.x & 31, ty = threadIdx.x >> 5;
    const int gx = blockIdx.x * 32, gy = blockIdx.y * 32;
#pragma unroll
    for (int j = 0; j < 4; j++)
        s[ty + j * 8][tx] = src[(size_t)(gy + ty + j * 8) * N + gx + tx];
    __syncthreads();
#pragma unroll
    for (int j = 0; j < 4; j++)
        dst[(size_t)(gx + ty + j * 8) * K + gy + tx] = s[tx][ty + j * 8];
}

// ---------------------------------------------------------------------------
// tf32 mma.sync GEMM (unchanged from R12 passing version)
// ---------------------------------------------------------------------------
template <int MODE>
__global__ __launch_bounds__(256, 2) void gemm_mma(
    const float* __restrict__ A, const float* __restrict__ Bt,
    const float* __restrict__ bias, float* __restrict__ outp)
{
    __shared__ float    bias_s[128];
    __shared__ uint32_t As[2][128 * 20];
    __shared__ uint32_t Bs[2][128 * 20];

    const int tid = threadIdx.x;
    const int lane = tid & 31;
    const int wid = tid >> 5;
    const int grp = lane >> 2, tig = lane & 3;
    const int wm = wid & 3, wn = wid >> 2;
    const int row0 = blockIdx.y * 128, col0 = blockIdx.x * 128;

    if (tid < 128) bias_s[tid] = bias[col0 + tid];

    const int lr = tid >> 2;
    const int lq = (tid & 3) * 4;

    float acc[2][8][4];
#pragma unroll
    for (int mt = 0; mt < 2; mt++)
#pragma unroll
        for (int nt = 0; nt < 8; nt++)
#pragma unroll
            for (int i = 0; i < 4; i++) acc[mt][nt][i] = 0.0f;

    float4 pa0, pa1, pb0, pb1;
    pa0 = *(const float4*)&A [(size_t)(row0 + lr)      * GK + lq];
    pa1 = *(const float4*)&A [(size_t)(row0 + 64 + lr) * GK + lq];
    pb0 = *(const float4*)&Bt[(size_t)(col0 + lr)      * GK + lq];
    pb1 = *(const float4*)&Bt[(size_t)(col0 + 64 + lr) * GK + lq];
    sts_tf32x4(&As[0][lr * 20 + lq],        pa0);
    sts_tf32x4(&As[0][(64 + lr) * 20 + lq], pa1);
    sts_tf32x4(&Bs[0][lr * 20 + lq],        pb0);
    sts_tf32x4(&Bs[0][(64 + lr) * 20 + lq], pb1);
    __syncthreads();

    for (int c = 0; c < 64; c++) {
        const int bf = c & 1;
        if (c < 63) {
            const int k0 = (c + 1) * 16;
            pa0 = *(const float4*)&A [(size_t)(row0 + lr)      * GK + k0 + lq];
            pa1 = *(const float4*)&A [(size_t)(row0 + 64 + lr) * GK + k0 + lq];
            pb0 = *(const float4*)&Bt[(size_t)(col0 + lr)      * GK + k0 + lq];
            pb1 = *(const float4*)&Bt[(size_t)(col0 + 64 + lr) * GK + k0 + lq];
        }

#pragma unroll
        for (int ks = 0; ks < 2; ks++) {
            const int k = ks * 8;
            uint32_t af[2][4];
#pragma unroll
            for (int mt = 0; mt < 2; mt++) {
                const uint32_t* r0 = &As[bf][(wm * 32 + mt * 16 + grp) * 20];
                af[mt][0] = r0[k + tig];
                af[mt][1] = r0[8 * 20 + k + tig];
                af[mt][2] = r0[k + tig + 4];
                af[mt][3] = r0[8 * 20 + k + tig + 4];
            }
            uint32_t bfr[8][2];
#pragma unroll
            for (int nt = 0; nt < 8; nt++) {
                const uint32_t* rb = &Bs[bf][(wn * 64 + nt * 8 + grp) * 20];
                bfr[nt][0] = rb[k + tig];
                bfr[nt][1] = rb[k + tig + 4];
            }
#pragma unroll
            for (int mt = 0; mt < 2; mt++)
#pragma unroll
                for (int nt = 0; nt < 8; nt++)
                    mma_tf32(acc[mt][nt], af[mt], bfr[nt]);
        }

        if (c < 63) {
            const int nb = bf ^ 1;
            sts_tf32x4(&As[nb][lr * 20 + lq],        pa0);
            sts_tf32x4(&As[nb][(64 + lr) * 20 + lq], pa1);
            sts_tf32x4(&Bs[nb][lr * 20 + lq],        pb0);
            sts_tf32x4(&Bs[nb][(64 + lr) * 20 + lq], pb1);
        }
        __syncthreads();
    }

#pragma unroll
    for (int nt = 0; nt < 8; nt++) {
        const int colb = col0 + wn * 64 + nt * 8;
        const int cloc = colb - col0 + 2 * tig;
        float scl = 1.0f;
        float* dstb = outp;
        int h = 0;
        if (MODE == 0) {
            const int sec = colb >> 10;
            const int cm = colb & 1023;
            h = cm >> 6;
            dstb = (sec == 0) ? g_q : (sec == 1) ? g_k : g_v;
            scl = (sec == 0) ? 0.125f : 1.0f;
        }
        const int d0 = MODE == 0 ? ((colb & 63) + 2 * tig) : 0;
#pragma unroll
        for (int mt = 0; mt < 2; mt++) {
            const int gm_lo = row0 + wm * 32 + mt * 16 + grp;
            const int gm_hi = gm_lo + 8;
            float2 lo, hi;
            lo.x = (acc[mt][nt][0] + bias_s[cloc])     * scl;
            lo.y = (acc[mt][nt][1] + bias_s[cloc + 1]) * scl;
            hi.x = (acc[mt][nt][2] + bias_s[cloc])     * scl;
            hi.y = (acc[mt][nt][3] + bias_s[cloc + 1]) * scl;
            if (MODE == 0) {
                const int bb_lo = gm_lo >> 11, l_lo = gm_lo & 2047;
                const int bb_hi = gm_hi >> 11, l_hi = gm_hi & 2047;
                *(float2*)&dstb[(((size_t)(bb_lo * H_ + h)) * L_ + l_lo) * HS_ + d0] = lo;
                *(float2*)&dstb[(((size_t)(bb_hi * H_ + h)) * L_ + l_hi) * HS_ + d0] = hi;
            } else {
                *(float2*)&outp[(size_t)gm_lo * D_ + colb + 2 * tig] = lo;
                *(float2*)&outp[(size_t)gm_hi * D_ + colb + 2 * tig] = hi;
            }
        }
    }
}

// ---------------------------------------------------------------------------
// R13 attention: q-tile 128 rows, 8 warps x (16 rows x 64 cols). Register-
// resident S + softmax (M/L/alpha in regs, quad shuffles), P staged warp-
// locally, fp16 R ring (idx = absolute Er row & 255), 2 block barriers/tile.
// ---------------------------------------------------------------------------
#define ALD 68
#define AQOFF 0          // Q: 128*68  = 8704 words
#define AKOFF 8704       // K: 64*68   = 4352
#define AVOFF 13056      // V: 64*68
#define AEOFF 17408      // E: 64*68
#define APOFF 21760      // P: 128*68  = 8704
#define ARWORD 30464     // R: 128*256 fp16 = 16384 words
#define ATT_SMEMB ((30464 + 16384) * 4)   // 187392 B -> 1 CTA/SM

__global__ __launch_bounds__(256) void attn_kernel(const float* __restrict__ Er)
{
    extern __shared__ float sm[];
    uint32_t* Qs = (uint32_t*)(sm + AQOFF);
    uint32_t* Ks = (uint32_t*)(sm + AKOFF);
    uint32_t* Vs = (uint32_t*)(sm + AVOFF);
    uint32_t* Es = (uint32_t*)(sm + AEOFF);
    uint32_t* Ps = (uint32_t*)(sm + APOFF);
    __half*   Rh = (__half*)(sm + ARWORD);

    const int tid = threadIdx.x;
    const int wid = tid >> 5, lane = tid & 31;
    const int grp = lane >> 2, tig = lane & 3;
    const int bh = blockIdx.x;                 // 0..31
    const int qt = 15 - (int)blockIdx.y;       // biggest q-tiles first (LPT)
    const int q0 = qt * 128;
    const int nkt = 2 * qt + 2;
    const int e00 = (L_ - 1) - q0;             // abs Er row of window pos 0 @ kt=0
    const int m0 = wid * 16;
    const int i_lo = m0 + grp, i_hi = i_lo + 8;
    const int b = bh >> 4, h = bh & 15;
    const float NEG = -1e30f;

    // Load Q tile (128x64 -> tf32)
#pragma unroll
    for (int i = 0; i < 8; i++) {
        const int idx = i * 256 + tid;
        const int row = idx >> 4, dq = (idx & 15) * 4;
        float4 v = *(const float4*)&g_q[((size_t)bh * L_ + q0 + row) * HS_ + dq];
        sts_tf32x4(&Qs[row * ALD + dq], v);
    }

    float m_lo = NEG, m_hi = NEG, l_lo = 0.0f, l_hi = 0.0f;
    float yacc[8][4];
#pragma unroll
    for (int nt = 0; nt < 8; nt++)
#pragma unroll
        for (int i = 0; i < 4; i++) yacc[nt][i] = 0.0f;

    // ---- R ring prefill: two E blocks covering [e00-128, e00) ----
#pragma unroll 1
    for (int t = 0; t < 2; t++) {
        const int eb = e00 - 128 + 64 * t;
        __syncthreads();   // t=0: Q stores visible; t=1: prior E MMA done
#pragma unroll
        for (int i = 0; i < 4; i++) {
            const int idx = i * 256 + tid;
            const int row = idx >> 4, dq = (idx & 15) * 4;
            int er = eb + row; er = er < 0 ? 0 : (er > L_ - 1 ? L_ - 1 : er);
            float4 v = *(const float4*)&Er[(size_t)er * HS_ + dq];
            sts_tf32x4(&Es[row * ALD + dq], v);
        }
        __syncthreads();
        float ea[8][4];
#pragma unroll
        for (int nt = 0; nt < 8; nt++)
#pragma unroll
            for (int i = 0; i < 4; i++) ea[nt][i] = 0.0f;
#pragma unroll
        for (int ks = 0; ks < 8; ks++) {
            const int k = ks * 8;
            uint32_t qf[4];
            const uint32_t* qp = &Qs[i_lo * ALD];
            qf[0] = qp[k + tig];
            qf[1] = qp[8 * ALD + k + tig];
            qf[2] = qp[k + tig + 4];
            qf[3] = qp[8 * ALD + k + tig + 4];
#pragma unroll
            for (int nt = 0; nt < 8; nt++) {
                const uint32_t* rb = &Es[(nt * 8 + grp) * ALD];
                uint32_t bfv[2] = { rb[k + tig], rb[k + tig + 4] };
                mma_tf32(ea[nt], qf, bfv);
            }
        }
#pragma unroll
        for (int nt = 0; nt < 8; nt++) {
            const int cc = eb + nt * 8 + 2 * tig;
            Rh[(i_lo << 8) | (cc & 255)]       = __float2half(ea[nt][0]);
            Rh[(i_lo << 8) | ((cc + 1) & 255)] = __float2half(ea[nt][1]);
            Rh[(i_hi << 8) | (cc & 255)]       = __float2half(ea[nt][2]);
            Rh[(i_hi << 8) | ((cc + 1) & 255)] = __float2half(ea[nt][3]);
        }
        __syncwarp();
    }

    // ---- main k-tile loop ----
#pragma unroll 1
    for (int kt = 0; kt < nkt; kt++) {
        const int k0 = kt * 64;
        const int eb = e00 + 64 * kt;          // new E block this tile
        const int e0k = e00 + 64 * kt;         // window pos-0 abs row (= eb)

        __syncthreads();   // prior iteration's V/E/K consumers done
#pragma unroll
        for (int i = 0; i < 4; i++) {
            const int idx = i * 256 + tid;
            const int row = idx >> 4, dq = (idx & 15) * 4;
            float4 kv = *(const float4*)&g_k[((size_t)bh * L_ + k0 + row) * HS_ + dq];
            float4 vv = *(const float4*)&g_v[((size_t)bh * L_ + k0 + row) * HS_ + dq];
            sts_tf32x4(&Ks[row * ALD + dq], kv);
            sts_tf32x4(&Vs[row * ALD + dq], vv);
            int er = eb + row; er = er < 0 ? 0 : (er > L_ - 1 ? L_ - 1 : er);
            float4 ev = *(const float4*)&Er[(size_t)er * HS_ + dq];
            sts_tf32x4(&Es[row * ALD + dq], ev);
        }
        __syncthreads();

        // ---- Phase A: ka = Q.K^T (16x64), ea = Q.Enew^T (16x64), shared qf ----
        float ka[8][4], ea[8][4];
#pragma unroll
        for (int nt = 0; nt < 8; nt++)
#pragma unroll
            for (int i = 0; i < 4; i++) { ka[nt][i] = 0.0f; ea[nt][i] = 0.0f; }
#pragma unroll
        for (int ks = 0; ks < 8; ks++) {
            const int k = ks * 8;
            uint32_t qf[4];
            const uint32_t* qp = &Qs[i_lo * ALD];
            qf[0] = qp[k + tig];
            qf[1] = qp[8 * ALD + k + tig];
            qf[2] = qp[k + tig + 4];
            qf[3] = qp[8 * ALD + k + tig + 4];
#pragma unroll
            for (int nt = 0; nt < 8; nt++) {
                const uint32_t* rb = &Ks[(nt * 8 + grp) * ALD];
                uint32_t bfv[2] = { rb[k + tig], rb[k + tig + 4] };
                mma_tf32(ka[nt], qf, bfv);
            }
#pragma unroll
            for (int nt = 0; nt < 8; nt++) {
                const uint32_t* rb = &Es[(nt * 8 + grp) * ALD];
                uint32_t bfv[2] = { rb[k + tig], rb[k + tig + 4] };
                mma_tf32(ea[nt], qf, bfv);
            }
        }
        // store new R block (warp-local rows)
#pragma unroll
        for (int nt = 0; nt < 8; nt++) {
            const int cc = eb + nt * 8 + 2 * tig;
            Rh[(i_lo << 8) | (cc & 255)]       = __float2half(ea[nt][0]);
            Rh[(i_lo << 8) | ((cc + 1) & 255)] = __float2half(ea[nt][1]);
            Rh[(i_hi << 8) | (cc & 255)]       = __float2half(ea[nt][2]);
            Rh[(i_hi << 8) | ((cc + 1) & 255)] = __float2half(ea[nt][3]);
        }
        __syncwarp();

        // ---- Phase B: register softmax ----
        const bool masked = (kt >= 2 * qt);
        const int lim_lo = q0 - k0 + i_lo, lim_hi = q0 - k0 + i_hi;
        float mx0 = NEG, mx1 = NEG;
#pragma unroll
        for (int nt = 0; nt < 8; nt++) {
            const int j = nt * 8 + 2 * tig;
            float s00 = ka[nt][0] + __half2float(Rh[(i_lo << 8) | ((e0k + j     - i_lo) & 255)]);
            float s01 = ka[nt][1] + __half2float(Rh[(i_lo << 8) | ((e0k + j + 1 - i_lo) & 255)]);
            float s10 = ka[nt][2] + __half2float(Rh[(i_hi << 8) | ((e0k + j     - i_hi) & 255)]);
            float s11 = ka[nt][3] + __half2float(Rh[(i_hi << 8) | ((e0k + j + 1 - i_hi) & 255)]);
            if (masked) {
                if (j     > lim_lo) s00 = NEG;
                if (j + 1 > lim_lo) s01 = NEG;
                if (j     > lim_hi) s10 = NEG;
                if (j + 1 > lim_hi) s11 = NEG;
            }
            ka[nt][0] = s00; ka[nt][1] = s01; ka[nt][2] = s10; ka[nt][3] = s11;
            mx0 = fmaxf(mx0, fmaxf(s00, s01));
            mx1 = fmaxf(mx1, fmaxf(s10, s11));
        }
        mx0 = fmaxf(mx0, __shfl_xor_sync(0xffffffffu, mx0, 1));
        mx0 = fmaxf(mx0, __shfl_xor_sync(0xffffffffu, mx0, 2));
        mx1 = fmaxf(mx1, __shfl_xor_sync(0xffffffffu, mx1, 1));
        mx1 = fmaxf(mx1, __shfl_xor_sync(0xffffffffu, mx1, 2));
        const float mn0 = fmaxf(m_lo, mx0), mn1 = fmaxf(m_hi, mx1);
        const float a0 = fexp(m_lo - mn0),  a1 = fexp(m_hi - mn1);
        m_lo = mn0; m_hi = mn1;

        float sum0 = 0.0f, sum1 = 0.0f;
#pragma unroll
        for (int nt = 0; nt < 8; nt++) {
            const float p00 = fexp(ka[nt][0] - mn0);
            const float p01 = fexp(ka[nt][1] - mn0);
            const float p10 = fexp(ka[nt][2] - mn1);
            const float p11 = fexp(ka[nt][3] - mn1);
            sum0 += p00 + p01;
            sum1 += p10 + p11;
            const int co = nt * 8 + 2 * tig;
            uint2 lo = make_uint2(f2tf(p00), f2tf(p01));
            uint2 hi = make_uint2(f2tf(p10), f2tf(p11));
            *(uint2*)&Ps[i_lo * ALD + co] = lo;
            *(uint2*)&Ps[i_hi * ALD + co] = hi;
        }
        sum0 += __shfl_xor_sync(0xffffffffu, sum0, 1);
        sum0 += __shfl_xor_sync(0xffffffffu, sum0, 2);
        sum1 += __shfl_xor_sync(0xffffffffu, sum1, 1);
        sum1 += __shfl_xor_sync(0xffffffffu, sum1, 2);
        l_lo = l_lo * a0 + sum0;
        l_hi = l_hi * a1 + sum1;
#pragma unroll
        for (int nt = 0; nt < 8; nt++) {
            yacc[nt][0] *= a0; yacc[nt][1] *= a0;
            yacc[nt][2] *= a1; yacc[nt][3] *= a1;
        }
        __syncwarp();

        // ---- Phase C: Y += P.V (16x64, k = 64 score cols) ----
#pragma unroll
        for (int ks = 0; ks < 8; ks++) {
            const int k = ks * 8;
            uint32_t pf[4];
            const uint32_t* pp = &Ps[i_lo * ALD];
            pf[0] = pp[k + tig];
            pf[1] = pp[8 * ALD + k + tig];
            pf[2] = pp[k + tig + 4];
            pf[3] = pp[8 * ALD + k + tig + 4];
#pragma unroll
            for (int nt = 0; nt < 8; nt++) {
                uint32_t bfv[2];
                bfv[0] = Vs[(k + tig) * ALD + nt * 8 + grp];
                bfv[1] = Vs[(k + tig + 4) * ALD + nt * 8 + grp];
                mma_tf32(yacc[nt], pf, bfv);
            }
        }
    }

    // ---- Epilogue: normalize, write (B, L, D) ----
    const float linv0 = 1.0f / l_lo, linv1 = 1.0f / l_hi;
    const int rl = q0 + i_lo, rh = q0 + i_hi;
#pragma unroll
    for (int nt = 0; nt < 8; nt++) {
        const int col = h * 64 + nt * 8 + 2 * tig;
        float2 lo = make_float2(yacc[nt][0] * linv0, yacc[nt][1] * linv0);
        float2 hi = make_float2(yacc[nt][2] * linv1, yacc[nt][3] * linv1);
        *(float2*)&g_y[((size_t)b * L_ + rl) * D_ + col] = lo;
        *(float2*)&g_y[((size_t)b * L_ + rh) * D_ + col] = hi;
    }
}

// ---------------------------------------------------------------------------
extern "C" void kernel_launch(void* const* d_in, const int* in_sizes, int n_in,
                              void* d_out, int out_size)
{
    const float* x      = (const float*)d_in[0];   // (2, 2048, 1024)
    const float* W_attn = (const float*)d_in[1];   // (1024, 3072)
    const float* b_attn = (const float*)d_in[2];   // (3072,)
    const float* W_proj = (const float*)d_in[3];   // (1024, 1024)
    const float* b_proj = (const float*)d_in[4];   // (1024,)
    const float* Er     = (const float*)d_in[5];   // (2048, 64)
    float* out = (float*)d_out;

    cudaFuncSetAttribute(attn_kernel,
                         cudaFuncAttributeMaxDynamicSharedMemorySize, ATT_SMEMB);

    float* wat; cudaGetSymbolAddress((void**)&wat, g_wat);
    float* wpt; cudaGetSymbolAddress((void**)&wpt, g_wpt);
    float* y;   cudaGetSymbolAddress((void**)&y, g_y);

    // 0) Transpose weights to [N][K] for k-contiguous B-operand loads
    transpose_kernel<<<dim3(N3D_ / 32, D_ / 32), 256>>>(W_attn, wat, D_, N3D_);
    transpose_kernel<<<dim3(D_ / 32, D_ / 32), 256>>>(W_proj, wpt, D_, D_);

    // 1) QKV projection, tf32 mma (+ head scatter, q scaling)
    gemm_mma<0><<<dim3(N3D_ / 128, BL_ / 128), 256>>>(x, wat, b_attn, nullptr);

    // 2) Causal attention with relative position bias, tf32 mma
    attn_kernel<<<dim3(B_ * H_, 16), 256, ATT_SMEMB>>>(Er);

    // 3) Output projection, tf32 mma
    gemm_mma<1><<<dim3(D_ / 128, BL_ / 128), 256>>>(y, wpt, b_proj, out);
}

// round 14
// speedup vs baseline: 2.9381x; 1.0976x over previous
#include <cuda_runtime.h>
#include <cuda_bf16.h>
#include <cuda_fp16.h>
#include <math.h>
#include <stdint.h>

// Problem constants
#define B_   2
#define L_   2048
#define D_   1024
#define H_   16
#define HS_  64
#define BL_  (B_ * L_)        // 4096
#define N3D_ (3 * D_)         // 3072
#define GK   1024             // K dim of both GEMMs

// Scratch (device globals; allocation in kernel_launch is forbidden)
__device__ float g_q[B_ * H_ * L_ * HS_];   // (b*H+h, l, d), pre-scaled by 1/8
__device__ float g_k[B_ * H_ * L_ * HS_];
__device__ float g_v[B_ * H_ * L_ * HS_];
__device__ float g_y[BL_ * D_];             // (b, l, h*64+d)
__device__ float g_wat[N3D_ * D_];          // W_attn^T  [3072][1024]
__device__ float g_wpt[D_ * D_];            // W_proj^T  [1024][1024]

// ---------------------------------------------------------------------------
// tf32 mma.sync helpers
// ---------------------------------------------------------------------------
__device__ __forceinline__ uint32_t f2tf(float f) {
    uint32_t u;
    asm("cvt.rna.tf32.f32 %0, %1;" : "=r"(u) : "f"(f));
    return u;
}

// D(16x8,f32) += A(16x8,tf32,row) * B(8x8,tf32,col)
__device__ __forceinline__ void mma_tf32(float* c, const uint32_t* a, const uint32_t* b) {
    asm volatile(
        "mma.sync.aligned.m16n8k8.row.col.f32.tf32.tf32.f32 "
        "{%0,%1,%2,%3},{%4,%5,%6,%7},{%8,%9},{%0,%1,%2,%3};"
        : "+f"(c[0]), "+f"(c[1]), "+f"(c[2]), "+f"(c[3])
        : "r"(a[0]), "r"(a[1]), "r"(a[2]), "r"(a[3]), "r"(b[0]), "r"(b[1]));
}

__device__ __forceinline__ void sts_tf32x4(uint32_t* p, float4 v) {
    uint4 u;
    u.x = f2tf(v.x); u.y = f2tf(v.y); u.z = f2tf(v.z); u.w = f2tf(v.w);
    *(uint4*)p = u;
}

// Fast exp on the FMA/ALU pipes (no MUFU). Valid for x <= 0 (clamped at -87).
__device__ __forceinline__ float fexp(float x) {
    x = fmaxf(x, -87.0f);
    const float L2E = 1.4426950408889634f;
    float y = fmaf(x, L2E, 12582912.0f);           // RN to integer
    int   n = __float_as_int(y) - 0x4B400000;
    float fl = y - 12582912.0f;
    float f = fmaf(x, L2E, -fl);                   // f in [-0.5, 0.5]
    float p = 1.3333558146428443e-3f;
    p = fmaf(p, f, 9.6181291076284772e-3f);
    p = fmaf(p, f, 5.5504108664821580e-2f);
    p = fmaf(p, f, 2.4022650695910071e-1f);
    p = fmaf(p, f, 6.9314718055994531e-1f);
    p = fmaf(p, f, 1.0f);
    return __int_as_float(__float_as_int(p) + (n << 23));
}

// ---------------------------------------------------------------------------
// Transpose: src[K][N] -> dst[N][K]
// ---------------------------------------------------------------------------
__global__ __launch_bounds__(256) void transpose_kernel(
    const float* __restrict__ src, float* __restrict__ dst, int K, int N)
{
    __shared__ float s[32][33];
    const int tx = threadIdx.x & 31, ty = threadIdx.x >> 5;
    const int gx = blockIdx.x * 32, gy = blockIdx.y * 32;
#pragma unroll
    for (int j = 0; j < 4; j++)
        s[ty + j * 8][tx] = src[(size_t)(gy + ty + j * 8) * N + gx + tx];
    __syncthreads();
#pragma unroll
    for (int j = 0; j < 4; j++)
        dst[(size_t)(gx + ty + j * 8) * K + gy + tx] = s[tx][ty + j * 8];
}

// ---------------------------------------------------------------------------
// tf32 mma.sync GEMM (unchanged from R13 passing version)
// ---------------------------------------------------------------------------
template <int MODE>
__global__ __launch_bounds__(256, 2) void gemm_mma(
    const float* __restrict__ A, const float* __restrict__ Bt,
    const float* __restrict__ bias, float* __restrict__ outp)
{
    __shared__ float    bias_s[128];
    __shared__ uint32_t As[2][128 * 20];
    __shared__ uint32_t Bs[2][128 * 20];

    const int tid = threadIdx.x;
    const int lane = tid & 31;
    const int wid = tid >> 5;
    const int grp = lane >> 2, tig = lane & 3;
    const int wm = wid & 3, wn = wid >> 2;
    const int row0 = blockIdx.y * 128, col0 = blockIdx.x * 128;

    if (tid < 128) bias_s[tid] = bias[col0 + tid];

    const int lr = tid >> 2;
    const int lq = (tid & 3) * 4;

    float acc[2][8][4];
#pragma unroll
    for (int mt = 0; mt < 2; mt++)
#pragma unroll
        for (int nt = 0; nt < 8; nt++)
#pragma unroll
            for (int i = 0; i < 4; i++) acc[mt][nt][i] = 0.0f;

    float4 pa0, pa1, pb0, pb1;
    pa0 = *(const float4*)&A [(size_t)(row0 + lr)      * GK + lq];
    pa1 = *(const float4*)&A [(size_t)(row0 + 64 + lr) * GK + lq];
    pb0 = *(const float4*)&Bt[(size_t)(col0 + lr)      * GK + lq];
    pb1 = *(const float4*)&Bt[(size_t)(col0 + 64 + lr) * GK + lq];
    sts_tf32x4(&As[0][lr * 20 + lq],        pa0);
    sts_tf32x4(&As[0][(64 + lr) * 20 + lq], pa1);
    sts_tf32x4(&Bs[0][lr * 20 + lq],        pb0);
    sts_tf32x4(&Bs[0][(64 + lr) * 20 + lq], pb1);
    __syncthreads();

    for (int c = 0; c < 64; c++) {
        const int bf = c & 1;
        if (c < 63) {
            const int k0 = (c + 1) * 16;
            pa0 = *(const float4*)&A [(size_t)(row0 + lr)      * GK + k0 + lq];
            pa1 = *(const float4*)&A [(size_t)(row0 + 64 + lr) * GK + k0 + lq];
            pb0 = *(const float4*)&Bt[(size_t)(col0 + lr)      * GK + k0 + lq];
            pb1 = *(const float4*)&Bt[(size_t)(col0 + 64 + lr) * GK + k0 + lq];
        }

#pragma unroll
        for (int ks = 0; ks < 2; ks++) {
            const int k = ks * 8;
            uint32_t af[2][4];
#pragma unroll
            for (int mt = 0; mt < 2; mt++) {
                const uint32_t* r0 = &As[bf][(wm * 32 + mt * 16 + grp) * 20];
                af[mt][0] = r0[k + tig];
                af[mt][1] = r0[8 * 20 + k + tig];
                af[mt][2] = r0[k + tig + 4];
                af[mt][3] = r0[8 * 20 + k + tig + 4];
            }
            uint32_t bfr[8][2];
#pragma unroll
            for (int nt = 0; nt < 8; nt++) {
                const uint32_t* rb = &Bs[bf][(wn * 64 + nt * 8 + grp) * 20];
                bfr[nt][0] = rb[k + tig];
                bfr[nt][1] = rb[k + tig + 4];
            }
#pragma unroll
            for (int mt = 0; mt < 2; mt++)
#pragma unroll
                for (int nt = 0; nt < 8; nt++)
                    mma_tf32(acc[mt][nt], af[mt], bfr[nt]);
        }

        if (c < 63) {
            const int nb = bf ^ 1;
            sts_tf32x4(&As[nb][lr * 20 + lq],        pa0);
            sts_tf32x4(&As[nb][(64 + lr) * 20 + lq], pa1);
            sts_tf32x4(&Bs[nb][lr * 20 + lq],        pb0);
            sts_tf32x4(&Bs[nb][(64 + lr) * 20 + lq], pb1);
        }
        __syncthreads();
    }

#pragma unroll
    for (int nt = 0; nt < 8; nt++) {
        const int colb = col0 + wn * 64 + nt * 8;
        const int cloc = colb - col0 + 2 * tig;
        float scl = 1.0f;
        float* dstb = outp;
        int h = 0;
        if (MODE == 0) {
            const int sec = colb >> 10;
            const int cm = colb & 1023;
            h = cm >> 6;
            dstb = (sec == 0) ? g_q : (sec == 1) ? g_k : g_v;
            scl = (sec == 0) ? 0.125f : 1.0f;
        }
        const int d0 = MODE == 0 ? ((colb & 63) + 2 * tig) : 0;
#pragma unroll
        for (int mt = 0; mt < 2; mt++) {
            const int gm_lo = row0 + wm * 32 + mt * 16 + grp;
            const int gm_hi = gm_lo + 8;
            float2 lo, hi;
            lo.x = (acc[mt][nt][0] + bias_s[cloc])     * scl;
            lo.y = (acc[mt][nt][1] + bias_s[cloc + 1]) * scl;
            hi.x = (acc[mt][nt][2] + bias_s[cloc])     * scl;
            hi.y = (acc[mt][nt][3] + bias_s[cloc + 1]) * scl;
            if (MODE == 0) {
                const int bb_lo = gm_lo >> 11, l_lo = gm_lo & 2047;
                const int bb_hi = gm_hi >> 11, l_hi = gm_hi & 2047;
                *(float2*)&dstb[(((size_t)(bb_lo * H_ + h)) * L_ + l_lo) * HS_ + d0] = lo;
                *(float2*)&dstb[(((size_t)(bb_hi * H_ + h)) * L_ + l_hi) * HS_ + d0] = hi;
            } else {
                *(float2*)&outp[(size_t)gm_lo * D_ + colb + 2 * tig] = lo;
                *(float2*)&outp[(size_t)gm_hi * D_ + colb + 2 * tig] = hi;
            }
        }
    }
}

// ---------------------------------------------------------------------------
// R14 attention: double-buffered K/V/E + one-tile-ahead register prefetch
// (1 block barrier per k-tile, loads hidden behind compute), register softmax,
// P relayout C-frag -> A-frag via quad shuffles (no smem P), fp16 R ring.
// ---------------------------------------------------------------------------
#define ALD 68
#define AQOFF  0           // Q: 128*68 = 8704 words
#define ABUF0  8704        // K,V,E: 3*4352 = 13056 words
#define ABUF1  21760
#define ARWORD 34816       // R fp16 128*256 = 16384 words
#define ATT_SMEMB ((34816 + 16384) * 4)   // 204800 B -> 1 CTA/SM

// Q x E-block MMA -> store 64 new R ring columns (warp-local rows)
__device__ __forceinline__ void er_mma_store(
    const uint32_t* Qs, const uint32_t* Es, __half* Rh,
    int eb, int i_lo, int i_hi, int grp, int tig)
{
    float ea[8][4];
#pragma unroll
    for (int nt = 0; nt < 8; nt++)
#pragma unroll
        for (int i = 0; i < 4; i++) ea[nt][i] = 0.0f;
#pragma unroll
    for (int ks = 0; ks < 8; ks++) {
        const int k = ks * 8;
        uint32_t qf[4];
        const uint32_t* qp = &Qs[i_lo * ALD];
        qf[0] = qp[k + tig];
        qf[1] = qp[8 * ALD + k + tig];
        qf[2] = qp[k + tig + 4];
        qf[3] = qp[8 * ALD + k + tig + 4];
#pragma unroll
        for (int nt = 0; nt < 8; nt++) {
            const uint32_t* rb = &Es[(nt * 8 + grp) * ALD];
            uint32_t bfv[2] = { rb[k + tig], rb[k + tig + 4] };
            mma_tf32(ea[nt], qf, bfv);
        }
    }
#pragma unroll
    for (int nt = 0; nt < 8; nt++) {
        const int cc = eb + nt * 8 + 2 * tig;
        Rh[(i_lo << 8) | (cc & 255)]       = __float2half(ea[nt][0]);
        Rh[(i_lo << 8) | ((cc + 1) & 255)] = __float2half(ea[nt][1]);
        Rh[(i_hi << 8) | (cc & 255)]       = __float2half(ea[nt][2]);
        Rh[(i_hi << 8) | ((cc + 1) & 255)] = __float2half(ea[nt][3]);
    }
}

__global__ __launch_bounds__(256) void attn_kernel(const float* __restrict__ Er)
{
    extern __shared__ float sm[];
    uint32_t* Qs  = (uint32_t*)(sm + AQOFF);
    uint32_t* bufA = (uint32_t*)(sm + ABUF0);
    uint32_t* bufB = (uint32_t*)(sm + ABUF1);
    __half*   Rh  = (__half*)(sm + ARWORD);

    const int tid = threadIdx.x;
    const int wid = tid >> 5, lane = tid & 31;
    const int grp = lane >> 2, tig = lane & 3;
    const int bh = blockIdx.x;                 // 0..31
    const int qt = 15 - (int)blockIdx.y;       // biggest q-tiles first (LPT)
    const int q0 = qt * 128;
    const int nkt = 2 * qt + 2;
    const int e00 = (L_ - 1) - q0;
    const int m0 = wid * 16;
    const int i_lo = m0 + grp, i_hi = i_lo + 8;
    const int b = bh >> 4, h = bh & 15;
    const float NEG = -1e30f;
    const int srcA = (lane & ~3) | (tig >> 1);
    const bool odd = (tig & 1);

    // Load Q tile (128x64 -> tf32)
#pragma unroll
    for (int i = 0; i < 8; i++) {
        const int idx = i * 256 + tid;
        const int row = idx >> 4, dq = (idx & 15) * 4;
        float4 v = *(const float4*)&g_q[((size_t)bh * L_ + q0 + row) * HS_ + dq];
        sts_tf32x4(&Qs[row * ALD + dq], v);
    }

    // ---- R ring prefill block A: [e00-128, e00-64) -> bufA.E ----
    {
        const int eb = e00 - 128;
#pragma unroll
        for (int i = 0; i < 4; i++) {
            const int idx = i * 256 + tid;
            const int row = idx >> 4, dq = (idx & 15) * 4;
            int er = eb + row; er = er < 0 ? 0 : (er > L_ - 1 ? L_ - 1 : er);
            float4 v = *(const float4*)&Er[(size_t)er * HS_ + dq];
            sts_tf32x4(&bufA[8704 + row * ALD + dq], v);
        }
        __syncthreads();
        er_mma_store(Qs, bufA + 8704, Rh, eb, i_lo, i_hi, grp, tig);
        __syncthreads();   // bufA.E free
    }
    // ---- prefill block B -> bufB.E; tile0 K,V,E -> bufA ----
    {
        const int ebB = e00 - 64;
#pragma unroll
        for (int i = 0; i < 4; i++) {
            const int idx = i * 256 + tid;
            const int row = idx >> 4, dq = (idx & 15) * 4;
            int er = ebB + row; er = er < 0 ? 0 : (er > L_ - 1 ? L_ - 1 : er);
            float4 v = *(const float4*)&Er[(size_t)er * HS_ + dq];
            sts_tf32x4(&bufB[8704 + row * ALD + dq], v);
            float4 kv = *(const float4*)&g_k[((size_t)bh * L_ + row) * HS_ + dq];
            float4 vv = *(const float4*)&g_v[((size_t)bh * L_ + row) * HS_ + dq];
            sts_tf32x4(&bufA[row * ALD + dq], kv);
            sts_tf32x4(&bufA[4352 + row * ALD + dq], vv);
            int er0 = e00 + row; if (er0 > L_ - 1) er0 = L_ - 1;
            float4 ev = *(const float4*)&Er[(size_t)er0 * HS_ + dq];
            sts_tf32x4(&bufA[8704 + row * ALD + dq], ev);
        }
        __syncthreads();
        er_mma_store(Qs, bufB + 8704, Rh, ebB, i_lo, i_hi, grp, tig);
        __syncthreads();   // bufB.E free (tile0 prefetch will overwrite it)
    }

    float m_lo = NEG, m_hi = NEG, l_lo = 0.0f, l_hi = 0.0f;
    float yacc[8][4];
#pragma unroll
    for (int nt = 0; nt < 8; nt++)
#pragma unroll
        for (int i = 0; i < 4; i++) yacc[nt][i] = 0.0f;

    // ---- main k-tile loop: compute on buf[kt&1], prefetch into buf[~] ----
#pragma unroll 1
    for (int kt = 0; kt < nkt; kt++) {
        uint32_t* cur = (kt & 1) ? bufB : bufA;
        uint32_t* nxt = (kt & 1) ? bufA : bufB;
        const int e0k = e00 + 64 * kt;

        // prefetch next tile's K,V,E into registers (latency hidden by compute)
        float4 pk[4], pv[4], pe[4];
        const bool pf = (kt + 1 < nkt);
        if (pf) {
            const int k0n = (kt + 1) * 64;
            const int ebn = e0k + 64;
#pragma unroll
            for (int i = 0; i < 4; i++) {
                const int idx = i * 256 + tid;
                const int row = idx >> 4, dq = (idx & 15) * 4;
                pk[i] = *(const float4*)&g_k[((size_t)bh * L_ + k0n + row) * HS_ + dq];
                pv[i] = *(const float4*)&g_v[((size_t)bh * L_ + k0n + row) * HS_ + dq];
                int er = ebn + row; if (er > L_ - 1) er = L_ - 1;
                pe[i] = *(const float4*)&Er[(size_t)er * HS_ + dq];
            }
        }

        const uint32_t* Ks = cur;
        const uint32_t* Vs = cur + 4352;
        const uint32_t* Es = cur + 8704;

        // ---- Phase A: ka = Q.K^T, ea = Q.Enew^T (shared Q fragments) ----
        float ka[8][4], ea[8][4];
#pragma unroll
        for (int nt = 0; nt < 8; nt++)
#pragma unroll
            for (int i = 0; i < 4; i++) { ka[nt][i] = 0.0f; ea[nt][i] = 0.0f; }
#pragma unroll
        for (int ks = 0; ks < 8; ks++) {
            const int k = ks * 8;
            uint32_t qf[4];
            const uint32_t* qp = &Qs[i_lo * ALD];
            qf[0] = qp[k + tig];
            qf[1] = qp[8 * ALD + k + tig];
            qf[2] = qp[k + tig + 4];
            qf[3] = qp[8 * ALD + k + tig + 4];
#pragma unroll
            for (int nt = 0; nt < 8; nt++) {
                const uint32_t* rb = &Ks[(nt * 8 + grp) * ALD];
                uint32_t bfv[2] = { rb[k + tig], rb[k + tig + 4] };
                mma_tf32(ka[nt], qf, bfv);
            }
#pragma unroll
            for (int nt = 0; nt < 8; nt++) {
                const uint32_t* rb = &Es[(nt * 8 + grp) * ALD];
                uint32_t bfv[2] = { rb[k + tig], rb[k + tig + 4] };
                mma_tf32(ea[nt], qf, bfv);
            }
        }
        // store new R ring block (warp-local rows)
#pragma unroll
        for (int nt = 0; nt < 8; nt++) {
            const int cc = e0k + nt * 8 + 2 * tig;
            Rh[(i_lo << 8) | (cc & 255)]       = __float2half(ea[nt][0]);
            Rh[(i_lo << 8) | ((cc + 1) & 255)] = __float2half(ea[nt][1]);
            Rh[(i_hi << 8) | (cc & 255)]       = __float2half(ea[nt][2]);
            Rh[(i_hi << 8) | ((cc + 1) & 255)] = __float2half(ea[nt][3]);
        }
        __syncwarp();

        // ---- Phase B: register softmax (P kept in ka as floats) ----
        const bool masked = (kt >= 2 * qt);
        const int lim_lo = q0 - kt * 64 + i_lo, lim_hi = lim_lo + 8;
        float mx0 = NEG, mx1 = NEG;
#pragma unroll
        for (int nt = 0; nt < 8; nt++) {
            const int j = nt * 8 + 2 * tig;
            float s00 = ka[nt][0] + __half2float(Rh[(i_lo << 8) | ((e0k + j     - i_lo) & 255)]);
            float s01 = ka[nt][1] + __half2float(Rh[(i_lo << 8) | ((e0k + j + 1 - i_lo) & 255)]);
            float s10 = ka[nt][2] + __half2float(Rh[(i_hi << 8) | ((e0k + j     - i_hi) & 255)]);
            float s11 = ka[nt][3] + __half2float(Rh[(i_hi << 8) | ((e0k + j + 1 - i_hi) & 255)]);
            if (masked) {
                if (j     > lim_lo) s00 = NEG;
                if (j + 1 > lim_lo) s01 = NEG;
                if (j     > lim_hi) s10 = NEG;
                if (j + 1 > lim_hi) s11 = NEG;
            }
            ka[nt][0] = s00; ka[nt][1] = s01; ka[nt][2] = s10; ka[nt][3] = s11;
            mx0 = fmaxf(mx0, fmaxf(s00, s01));
            mx1 = fmaxf(mx1, fmaxf(s10, s11));
        }
        mx0 = fmaxf(mx0, __shfl_xor_sync(0xffffffffu, mx0, 1));
        mx0 = fmaxf(mx0, __shfl_xor_sync(0xffffffffu, mx0, 2));
        mx1 = fmaxf(mx1, __shfl_xor_sync(0xffffffffu, mx1, 1));
        mx1 = fmaxf(mx1, __shfl_xor_sync(0xffffffffu, mx1, 2));
        const float mn0 = fmaxf(m_lo, mx0), mn1 = fmaxf(m_hi, mx1);
        const float a0 = fexp(m_lo - mn0),  a1 = fexp(m_hi - mn1);
        m_lo = mn0; m_hi = mn1;

        float sum0 = 0.0f, sum1 = 0.0f;
#pragma unroll
        for (int nt = 0; nt < 8; nt++) {
            const float p00 = fexp(ka[nt][0] - mn0);
            const float p01 = fexp(ka[nt][1] - mn0);
            const float p10 = fexp(ka[nt][2] - mn1);
            const float p11 = fexp(ka[nt][3] - mn1);
            sum0 += p00 + p01;
            sum1 += p10 + p11;
            ka[nt][0] = p00; ka[nt][1] = p01; ka[nt][2] = p10; ka[nt][3] = p11;
        }
        sum0 += __shfl_xor_sync(0xffffffffu, sum0, 1);
        sum0 += __shfl_xor_sync(0xffffffffu, sum0, 2);
        sum1 += __shfl_xor_sync(0xffffffffu, sum1, 1);
        sum1 += __shfl_xor_sync(0xffffffffu, sum1, 2);
        l_lo = l_lo * a0 + sum0;
        l_hi = l_hi * a1 + sum1;
#pragma unroll
        for (int nt = 0; nt < 8; nt++) {
            yacc[nt][0] *= a0; yacc[nt][1] *= a0;
            yacc[nt][2] *= a1; yacc[nt][3] *= a1;
        }

        // ---- Phase C: Y += P.V; P relayout C-frag -> A-frag via shuffles ----
#pragma unroll
        for (int ks = 0; ks < 8; ks++) {
            const int k = ks * 8;
            const float v0 = __shfl_sync(0xffffffffu, ka[ks][0], srcA);
            const float v1 = __shfl_sync(0xffffffffu, ka[ks][1], srcA);
            const float w0 = __shfl_sync(0xffffffffu, ka[ks][0], srcA + 2);
            const float w1 = __shfl_sync(0xffffffffu, ka[ks][1], srcA + 2);
            const float u0 = __shfl_sync(0xffffffffu, ka[ks][2], srcA);
            const float u1 = __shfl_sync(0xffffffffu, ka[ks][3], srcA);
            const float t0 = __shfl_sync(0xffffffffu, ka[ks][2], srcA + 2);
            const float t1 = __shfl_sync(0xffffffffu, ka[ks][3], srcA + 2);
            uint32_t af[4];
            af[0] = f2tf(odd ? v1 : v0);
            af[1] = f2tf(odd ? u1 : u0);
            af[2] = f2tf(odd ? w1 : w0);
            af[3] = f2tf(odd ? t1 : t0);
#pragma unroll
            for (int nt = 0; nt < 8; nt++) {
                uint32_t bfv[2];
                bfv[0] = Vs[(k + tig) * ALD + nt * 8 + grp];
                bfv[1] = Vs[(k + tig + 4) * ALD + nt * 8 + grp];
                mma_tf32(yacc[nt], af, bfv);
            }
        }

        // ---- store prefetched tile into the alternate buffer ----
        if (pf) {
#pragma unroll
            for (int i = 0; i < 4; i++) {
                const int idx = i * 256 + tid;
                const int row = idx >> 4, dq = (idx & 15) * 4;
                sts_tf32x4(&nxt[row * ALD + dq],        pk[i]);
                sts_tf32x4(&nxt[4352 + row * ALD + dq], pv[i]);
                sts_tf32x4(&nxt[8704 + row * ALD + dq], pe[i]);
            }
        }
        __syncthreads();
    }

    // ---- Epilogue: normalize, write (B, L, D) ----
    const float linv0 = 1.0f / l_lo, linv1 = 1.0f / l_hi;
    const int rl = q0 + i_lo, rh = q0 + i_hi;
#pragma unroll
    for (int nt = 0; nt < 8; nt++) {
        const int col = h * 64 + nt * 8 + 2 * tig;
        float2 lo = make_float2(yacc[nt][0] * linv0, yacc[nt][1] * linv0);
        float2 hi = make_float2(yacc[nt][2] * linv1, yacc[nt][3] * linv1);
        *(float2*)&g_y[((size_t)b * L_ + rl) * D_ + col] = lo;
        *(float2*)&g_y[((size_t)b * L_ + rh) * D_ + col] = hi;
    }
}

// ---------------------------------------------------------------------------
extern "C" void kernel_launch(void* const* d_in, const int* in_sizes, int n_in,
                              void* d_out, int out_size)
{
    const float* x      = (const float*)d_in[0];   // (2, 2048, 1024)
    const float* W_attn = (const float*)d_in[1];   // (1024, 3072)
    const float* b_attn = (const float*)d_in[2];   // (3072,)
    const float* W_proj = (const float*)d_in[3];   // (1024, 1024)
    const float* b_proj = (const float*)d_in[4];   // (1024,)
    const float* Er     = (const float*)d_in[5];   // (2048, 64)
    float* out = (float*)d_out;

    cudaFuncSetAttribute(attn_kernel,
                         cudaFuncAttributeMaxDynamicSharedMemorySize, ATT_SMEMB);

    float* wat; cudaGetSymbolAddress((void**)&wat, g_wat);
    float* wpt; cudaGetSymbolAddress((void**)&wpt, g_wpt);
    float* y;   cudaGetSymbolAddress((void**)&y, g_y);

    // 0) Transpose weights to [N][K] for k-contiguous B-operand loads
    transpose_kernel<<<dim3(N3D_ / 32, D_ / 32), 256>>>(W_attn, wat, D_, N3D_);
    transpose_kernel<<<dim3(D_ / 32, D_ / 32), 256>>>(W_proj, wpt, D_, D_);

    // 1) QKV projection, tf32 mma (+ head scatter, q scaling)
    gemm_mma<0><<<dim3(N3D_ / 128, BL_ / 128), 256>>>(x, wat, b_attn, nullptr);

    // 2) Causal attention with relative position bias, tf32 mma
    attn_kernel<<<dim3(B_ * H_, 16), 256, ATT_SMEMB>>>(Er);

    // 3) Output projection, tf32 mma
    gemm_mma<1><<<dim3(D_ / 128, BL_ / 128), 256>>>(y, wpt, b_proj, out);
}

// round 15
// speedup vs baseline: 3.8005x; 1.2935x over previous
#include <cuda_runtime.h>
#include <cuda_bf16.h>
#include <cuda_fp16.h>
#include <math.h>
#include <stdint.h>

// Problem constants
#define B_   2
#define L_   2048
#define D_   1024
#define H_   16
#define HS_  64
#define BL_  (B_ * L_)        // 4096
#define N3D_ (3 * D_)         // 3072
#define GK   1024             // K dim of both GEMMs

// Scratch (device globals; allocation in kernel_launch is forbidden)
__device__ float g_q[B_ * H_ * L_ * HS_];   // (b*H+h, l, d), pre-scaled by 1/8
__device__ float g_k[B_ * H_ * L_ * HS_];
__device__ float g_v[B_ * H_ * L_ * HS_];
__device__ float g_y[BL_ * D_];             // (b, l, h*64+d)
__device__ float g_wat[N3D_ * D_];          // W_attn^T  [3072][1024]
__device__ float g_wpt[D_ * D_];            // W_proj^T  [1024][1024]

// ---------------------------------------------------------------------------
// mma.sync helpers (sm_80+ features only)
// ---------------------------------------------------------------------------
__device__ __forceinline__ uint32_t f2tf(float f) {
    uint32_t u;
    asm("cvt.rna.tf32.f32 %0, %1;" : "=r"(u) : "f"(f));
    return u;
}

// D(16x8,f32) += A(16x8,tf32,row) * B(8x8,tf32,col)
__device__ __forceinline__ void mma_tf32(float* c, const uint32_t* a, const uint32_t* b) {
    asm volatile(
        "mma.sync.aligned.m16n8k8.row.col.f32.tf32.tf32.f32 "
        "{%0,%1,%2,%3},{%4,%5,%6,%7},{%8,%9},{%0,%1,%2,%3};"
        : "+f"(c[0]), "+f"(c[1]), "+f"(c[2]), "+f"(c[3])
        : "r"(a[0]), "r"(a[1]), "r"(a[2]), "r"(a[3]), "r"(b[0]), "r"(b[1]));
}

// D(16x8,f32) += A(16x16,f16,row) * B(16x8,f16,col)
__device__ __forceinline__ void mma_f16(float* c, const uint32_t* a, const uint32_t* b) {
    asm volatile(
        "mma.sync.aligned.m16n8k16.row.col.f32.f16.f16.f32 "
        "{%0,%1,%2,%3},{%4,%5,%6,%7},{%8,%9},{%0,%1,%2,%3};"
        : "+f"(c[0]), "+f"(c[1]), "+f"(c[2]), "+f"(c[3])
        : "r"(a[0]), "r"(a[1]), "r"(a[2]), "r"(a[3]), "r"(b[0]), "r"(b[1]));
}

__device__ __forceinline__ void sts_tf32x4(uint32_t* p, float4 v) {
    uint4 u;
    u.x = f2tf(v.x); u.y = f2tf(v.y); u.z = f2tf(v.z); u.w = f2tf(v.w);
    *(uint4*)p = u;
}

__device__ __forceinline__ uint32_t f2h2(float lo, float hi) {
    __half2 h = __floats2half2_rn(lo, hi);
    return *reinterpret_cast<uint32_t*>(&h);
}

// 4 floats -> 4 halves (packed as 2 words)
__device__ __forceinline__ void sts_f16x4(uint32_t* p, float4 v) {
    uint2 u;
    u.x = f2h2(v.x, v.y);
    u.y = f2h2(v.z, v.w);
    *(uint2*)p = u;
}

// Fast exp on the FMA/ALU pipes (no MUFU). Valid for x <= 0 (clamped at -87).
__device__ __forceinline__ float fexp(float x) {
    x = fmaxf(x, -87.0f);
    const float L2E = 1.4426950408889634f;
    float y = fmaf(x, L2E, 12582912.0f);           // RN to integer
    int   n = __float_as_int(y) - 0x4B400000;
    float fl = y - 12582912.0f;
    float f = fmaf(x, L2E, -fl);                   // f in [-0.5, 0.5]
    float p = 1.3333558146428443e-3f;
    p = fmaf(p, f, 9.6181291076284772e-3f);
    p = fmaf(p, f, 5.5504108664821580e-2f);
    p = fmaf(p, f, 2.4022650695910071e-1f);
    p = fmaf(p, f, 6.9314718055994531e-1f);
    p = fmaf(p, f, 1.0f);
    return __int_as_float(__float_as_int(p) + (n << 23));
}

// ---------------------------------------------------------------------------
// Transpose: src[K][N] -> dst[N][K]
// ---------------------------------------------------------------------------
__global__ __launch_bounds__(256) void transpose_kernel(
    const float* __restrict__ src, float* __restrict__ dst, int K, int N)
{
    __shared__ float s[32][33];
    const int tx = threadIdx.x & 31, ty = threadIdx.x >> 5;
    const int gx = blockIdx.x * 32, gy = blockIdx.y * 32;
#pragma unroll
    for (int j = 0; j < 4; j++)
        s[ty + j * 8][tx] = src[(size_t)(gy + ty + j * 8) * N + gx + tx];
    __syncthreads();
#pragma unroll
    for (int j = 0; j < 4; j++)
        dst[(size_t)(gx + ty + j * 8) * K + gy + tx] = s[tx][ty + j * 8];
}

// ---------------------------------------------------------------------------
// fp16 mma.sync GEMM: C[M][Ntot] = A[M][1024] x Bt[Ntot][1024]^T + bias
// CTA tile 128x128, 8 warps (4m x 2n), K chunks of 16 (fp16 in smem, fp32
// accum), double buffered. LW=12 words/row-chunk => conflict-free LDS.
// ---------------------------------------------------------------------------
#define GLW 12
template <int MODE>
__global__ __launch_bounds__(256, 2) void gemm_mma(
    const float* __restrict__ A, const float* __restrict__ Bt,
    const float* __restrict__ bias, float* __restrict__ outp)
{
    __shared__ float    bias_s[128];
    __shared__ uint32_t As[2][128 * GLW];
    __shared__ uint32_t Bs[2][128 * GLW];

    const int tid = threadIdx.x;
    const int lane = tid & 31;
    const int wid = tid >> 5;
    const int grp = lane >> 2, tig = lane & 3;
    const int wm = wid & 3, wn = wid >> 2;
    const int row0 = blockIdx.y * 128, col0 = blockIdx.x * 128;

    if (tid < 128) bias_s[tid] = bias[col0 + tid];

    const int lr = tid >> 2;              // 0..63
    const int lq = (tid & 3) * 4;         // float offset within k16
    const int lw = (tid & 3) * 2;         // word offset (halves) within chunk row

    float acc[2][8][4];
#pragma unroll
    for (int mt = 0; mt < 2; mt++)
#pragma unroll
        for (int nt = 0; nt < 8; nt++)
#pragma unroll
            for (int i = 0; i < 4; i++) acc[mt][nt][i] = 0.0f;

    float4 pa0, pa1, pb0, pb1;
    pa0 = *(const float4*)&A [(size_t)(row0 + lr)      * GK + lq];
    pa1 = *(const float4*)&A [(size_t)(row0 + 64 + lr) * GK + lq];
    pb0 = *(const float4*)&Bt[(size_t)(col0 + lr)      * GK + lq];
    pb1 = *(const float4*)&Bt[(size_t)(col0 + 64 + lr) * GK + lq];
    sts_f16x4(&As[0][lr * GLW + lw],        pa0);
    sts_f16x4(&As[0][(64 + lr) * GLW + lw], pa1);
    sts_f16x4(&Bs[0][lr * GLW + lw],        pb0);
    sts_f16x4(&Bs[0][(64 + lr) * GLW + lw], pb1);
    __syncthreads();

    for (int c = 0; c < 64; c++) {
        const int bf = c & 1;
        if (c < 63) {
            const int k0 = (c + 1) * 16;
            pa0 = *(const float4*)&A [(size_t)(row0 + lr)      * GK + k0 + lq];
            pa1 = *(const float4*)&A [(size_t)(row0 + 64 + lr) * GK + k0 + lq];
            pb0 = *(const float4*)&Bt[(size_t)(col0 + lr)      * GK + k0 + lq];
            pb1 = *(const float4*)&Bt[(size_t)(col0 + 64 + lr) * GK + k0 + lq];
        }

        // one k16 fp16 MMA step per chunk
        {
            uint32_t af[2][4];
#pragma unroll
            for (int mt = 0; mt < 2; mt++) {
                const uint32_t* r0 = &As[bf][(wm * 32 + mt * 16 + grp) * GLW];
                af[mt][0] = r0[tig];
                af[mt][1] = r0[8 * GLW + tig];
                af[mt][2] = r0[tig + 4];
                af[mt][3] = r0[8 * GLW + tig + 4];
            }
            uint32_t bfr[8][2];
#pragma unroll
            for (int nt = 0; nt < 8; nt++) {
                const uint32_t* rb = &Bs[bf][(wn * 64 + nt * 8 + grp) * GLW];
                bfr[nt][0] = rb[tig];
                bfr[nt][1] = rb[tig + 4];
            }
#pragma unroll
            for (int mt = 0; mt < 2; mt++)
#pragma unroll
                for (int nt = 0; nt < 8; nt++)
                    mma_f16(acc[mt][nt], af[mt], bfr[nt]);
        }

        if (c < 63) {
            const int nb = bf ^ 1;
            sts_f16x4(&As[nb][lr * GLW + lw],        pa0);
            sts_f16x4(&As[nb][(64 + lr) * GLW + lw], pa1);
            sts_f16x4(&Bs[nb][lr * GLW + lw],        pb0);
            sts_f16x4(&Bs[nb][(64 + lr) * GLW + lw], pb1);
        }
        __syncthreads();
    }

#pragma unroll
    for (int nt = 0; nt < 8; nt++) {
        const int colb = col0 + wn * 64 + nt * 8;
        const int cloc = colb - col0 + 2 * tig;
        float scl = 1.0f;
        float* dstb = outp;
        int h = 0;
        if (MODE == 0) {
            const int sec = colb >> 10;
            const int cm = colb & 1023;
            h = cm >> 6;
            dstb = (sec == 0) ? g_q : (sec == 1) ? g_k : g_v;
            scl = (sec == 0) ? 0.125f : 1.0f;
        }
        const int d0 = MODE == 0 ? ((colb & 63) + 2 * tig) : 0;
#pragma unroll
        for (int mt = 0; mt < 2; mt++) {
            const int gm_lo = row0 + wm * 32 + mt * 16 + grp;
            const int gm_hi = gm_lo + 8;
            float2 lo, hi;
            lo.x = (acc[mt][nt][0] + bias_s[cloc])     * scl;
            lo.y = (acc[mt][nt][1] + bias_s[cloc + 1]) * scl;
            hi.x = (acc[mt][nt][2] + bias_s[cloc])     * scl;
            hi.y = (acc[mt][nt][3] + bias_s[cloc + 1]) * scl;
            if (MODE == 0) {
                const int bb_lo = gm_lo >> 11, l_lo = gm_lo & 2047;
                const int bb_hi = gm_hi >> 11, l_hi = gm_hi & 2047;
                *(float2*)&dstb[(((size_t)(bb_lo * H_ + h)) * L_ + l_lo) * HS_ + d0] = lo;
                *(float2*)&dstb[(((size_t)(bb_hi * H_ + h)) * L_ + l_hi) * HS_ + d0] = hi;
            } else {
                *(float2*)&outp[(size_t)gm_lo * D_ + colb + 2 * tig] = lo;
                *(float2*)&outp[(size_t)gm_hi * D_ + colb + 2 * tig] = hi;
            }
        }
    }
}

// ---------------------------------------------------------------------------
// R15 attention: phase A in fp16 (Q/K/E tiles fp16, m16n8k16), phase C tf32,
// double-buffered K/V/E + register prefetch, register softmax, fp16 R ring.
// ---------------------------------------------------------------------------
#define LQW 36               // Q row stride in words (64 halves = 32w + pad)
#define LKW 36               // K/E row stride in words
#define LVW 68               // V row stride in words (tf32)
#define AQOFF  0             // Q: 128*36 = 4608 words
#define ABUF0  4608          // buffer: K(2304) + E(2304) + V(4352) = 8960
#define ABUF1  13568
#define ARWORD 22528         // R fp16 128*256 = 16384 words
#define ATT_SMEMB ((22528 + 16384) * 4)   // 155648 B

// Q x E-block fp16 MMA -> store 64 new R ring columns (warp-local rows)
__device__ __forceinline__ void er_mma_store(
    const uint32_t* Qs, const uint32_t* Es, __half* Rh,
    int eb, int i_lo, int i_hi, int grp, int tig)
{
    float ea[8][4];
#pragma unroll
    for (int nt = 0; nt < 8; nt++)
#pragma unroll
        for (int i = 0; i < 4; i++) ea[nt][i] = 0.0f;
#pragma unroll
    for (int ks = 0; ks < 4; ks++) {
        const int kw = ks * 8;
        uint32_t qf[4];
        const uint32_t* qlo = &Qs[i_lo * LQW + kw];
        const uint32_t* qhi = &Qs[i_hi * LQW + kw];
        qf[0] = qlo[tig]; qf[1] = qhi[tig];
        qf[2] = qlo[tig + 4]; qf[3] = qhi[tig + 4];
#pragma unroll
        for (int nt = 0; nt < 8; nt++) {
            const uint32_t* rb = &Es[(nt * 8 + grp) * LKW + kw];
            uint32_t bfv[2] = { rb[tig], rb[tig + 4] };
            mma_f16(ea[nt], qf, bfv);
        }
    }
#pragma unroll
    for (int nt = 0; nt < 8; nt++) {
        const int cc = eb + nt * 8 + 2 * tig;
        Rh[(i_lo << 8) | (cc & 255)]       = __float2half(ea[nt][0]);
        Rh[(i_lo << 8) | ((cc + 1) & 255)] = __float2half(ea[nt][1]);
        Rh[(i_hi << 8) | (cc & 255)]       = __float2half(ea[nt][2]);
        Rh[(i_hi << 8) | ((cc + 1) & 255)] = __float2half(ea[nt][3]);
    }
}

__global__ __launch_bounds__(256) void attn_kernel(const float* __restrict__ Er)
{
    extern __shared__ float sm[];
    uint32_t* Qs   = (uint32_t*)(sm + AQOFF);
    uint32_t* bufA = (uint32_t*)(sm + ABUF0);
    uint32_t* bufB = (uint32_t*)(sm + ABUF1);
    __half*   Rh   = (__half*)(sm + ARWORD);

    const int tid = threadIdx.x;
    const int wid = tid >> 5, lane = tid & 31;
    const int grp = lane >> 2, tig = lane & 3;
    const int bh = blockIdx.x;                 // 0..31
    const int qt = 15 - (int)blockIdx.y;       // biggest q-tiles first (LPT)
    const int q0 = qt * 128;
    const int nkt = 2 * qt + 2;
    const int e00 = (L_ - 1) - q0;
    const int m0 = wid * 16;
    const int i_lo = m0 + grp, i_hi = i_lo + 8;
    const int b = bh >> 4, h = bh & 15;
    const float NEG = -1e30f;
    const int srcA = (lane & ~3) | (tig >> 1);
    const bool odd = (tig & 1);

    // Load Q tile (128x64 -> fp16)
#pragma unroll
    for (int i = 0; i < 8; i++) {
        const int idx = i * 256 + tid;
        const int row = idx >> 4, sw = (idx & 15) * 2, dq = (idx & 15) * 4;
        float4 v = *(const float4*)&g_q[((size_t)bh * L_ + q0 + row) * HS_ + dq];
        sts_f16x4(&Qs[row * LQW + sw], v);
    }

    // ---- R ring prefill block A: [e00-128, e00-64) -> bufA.E ----
    {
        const int eb = e00 - 128;
#pragma unroll
        for (int i = 0; i < 4; i++) {
            const int idx = i * 256 + tid;
            const int row = idx >> 4, sw = (idx & 15) * 2, dq = (idx & 15) * 4;
            int er = eb + row; er = er < 0 ? 0 : (er > L_ - 1 ? L_ - 1 : er);
            float4 v = *(const float4*)&Er[(size_t)er * HS_ + dq];
            sts_f16x4(&bufA[2304 + row * LKW + sw], v);
        }
        __syncthreads();
        er_mma_store(Qs, bufA + 2304, Rh, eb, i_lo, i_hi, grp, tig);
        __syncthreads();   // bufA.E free
    }
    // ---- prefill block B -> bufB.E; tile0 K,V,E -> bufA ----
    {
        const int ebB = e00 - 64;
#pragma unroll
        for (int i = 0; i < 4; i++) {
            const int idx = i * 256 + tid;
            const int row = idx >> 4, sw = (idx & 15) * 2, dq = (idx & 15) * 4;
            int er = ebB + row; er = er < 0 ? 0 : (er > L_ - 1 ? L_ - 1 : er);
            float4 v = *(const float4*)&Er[(size_t)er * HS_ + dq];
            sts_f16x4(&bufB[2304 + row * LKW + sw], v);
            float4 kv = *(const float4*)&g_k[((size_t)bh * L_ + row) * HS_ + dq];
            float4 vv = *(const float4*)&g_v[((size_t)bh * L_ + row) * HS_ + dq];
            sts_f16x4(&bufA[row * LKW + sw], kv);
            sts_tf32x4(&bufA[4608 + row * LVW + dq], vv);
            int er0 = e00 + row; if (er0 > L_ - 1) er0 = L_ - 1;
            float4 ev = *(const float4*)&Er[(size_t)er0 * HS_ + dq];
            sts_f16x4(&bufA[2304 + row * LKW + sw], ev);
        }
        __syncthreads();
        er_mma_store(Qs, bufB + 2304, Rh, ebB, i_lo, i_hi, grp, tig);
        __syncthreads();   // bufB.E free (tile0 prefetch will overwrite it)
    }

    float m_lo = NEG, m_hi = NEG, l_lo = 0.0f, l_hi = 0.0f;
    float yacc[8][4];
#pragma unroll
    for (int nt = 0; nt < 8; nt++)
#pragma unroll
        for (int i = 0; i < 4; i++) yacc[nt][i] = 0.0f;

    // ---- main k-tile loop: compute on buf[kt&1], prefetch into buf[~] ----
#pragma unroll 1
    for (int kt = 0; kt < nkt; kt++) {
        uint32_t* cur = (kt & 1) ? bufB : bufA;
        uint32_t* nxt = (kt & 1) ? bufA : bufB;
        const int e0k = e00 + 64 * kt;

        // prefetch next tile's K,V,E into registers (latency hidden by compute)
        float4 pk[4], pv[4], pe[4];
        const bool pf = (kt + 1 < nkt);
        if (pf) {
            const int k0n = (kt + 1) * 64;
            const int ebn = e0k + 64;
#pragma unroll
            for (int i = 0; i < 4; i++) {
                const int idx = i * 256 + tid;
                const int row = idx >> 4, dq = (idx & 15) * 4;
                pk[i] = *(const float4*)&g_k[((size_t)bh * L_ + k0n + row) * HS_ + dq];
                pv[i] = *(const float4*)&g_v[((size_t)bh * L_ + k0n + row) * HS_ + dq];
                int er = ebn + row; if (er > L_ - 1) er = L_ - 1;
                pe[i] = *(const float4*)&Er[(size_t)er * HS_ + dq];
            }
        }

        const uint32_t* Ks = cur;
        const uint32_t* Es = cur + 2304;
        const uint32_t* Vs = cur + 4608;

        // ---- Phase A (fp16): ka = Q.K^T, ea = Q.Enew^T (shared Q frags) ----
        float ka[8][4], ea[8][4];
#pragma unroll
        for (int nt = 0; nt < 8; nt++)
#pragma unroll
            for (int i = 0; i < 4; i++) { ka[nt][i] = 0.0f; ea[nt][i] = 0.0f; }
#pragma unroll
        for (int ks = 0; ks < 4; ks++) {
            const int kw = ks * 8;
            uint32_t qf[4];
            const uint32_t* qlo = &Qs[i_lo * LQW + kw];
            const uint32_t* qhi = &Qs[i_hi * LQW + kw];
            qf[0] = qlo[tig]; qf[1] = qhi[tig];
            qf[2] = qlo[tig + 4]; qf[3] = qhi[tig + 4];
#pragma unroll
            for (int nt = 0; nt < 8; nt++) {
                const uint32_t* rb = &Ks[(nt * 8 + grp) * LKW + kw];
                uint32_t bfv[2] = { rb[tig], rb[tig + 4] };
                mma_f16(ka[nt], qf, bfv);
            }
#pragma unroll
            for (int nt = 0; nt < 8; nt++) {
                const uint32_t* rb = &Es[(nt * 8 + grp) * LKW + kw];
                uint32_t bfv[2] = { rb[tig], rb[tig + 4] };
                mma_f16(ea[nt], qf, bfv);
            }
        }
        // store new R ring block (warp-local rows)
#pragma unroll
        for (int nt = 0; nt < 8; nt++) {
            const int cc = e0k + nt * 8 + 2 * tig;
            Rh[(i_lo << 8) | (cc & 255)]       = __float2half(ea[nt][0]);
            Rh[(i_lo << 8) | ((cc + 1) & 255)] = __float2half(ea[nt][1]);
            Rh[(i_hi << 8) | (cc & 255)]       = __float2half(ea[nt][2]);
            Rh[(i_hi << 8) | ((cc + 1) & 255)] = __float2half(ea[nt][3]);
        }
        __syncwarp();

        // ---- Phase B: register softmax (P kept in ka as floats) ----
        const bool masked = (kt >= 2 * qt);
        const int lim_lo = q0 - kt * 64 + i_lo, lim_hi = lim_lo + 8;
        float mx0 = NEG, mx1 = NEG;
#pragma unroll
        for (int nt = 0; nt < 8; nt++) {
            const int j = nt * 8 + 2 * tig;
            float s00 = ka[nt][0] + __half2float(Rh[(i_lo << 8) | ((e0k + j     - i_lo) & 255)]);
            float s01 = ka[nt][1] + __half2float(Rh[(i_lo << 8) | ((e0k + j + 1 - i_lo) & 255)]);
            float s10 = ka[nt][2] + __half2float(Rh[(i_hi << 8) | ((e0k + j     - i_hi) & 255)]);
            float s11 = ka[nt][3] + __half2float(Rh[(i_hi << 8) | ((e0k + j + 1 - i_hi) & 255)]);
            if (masked) {
                if (j     > lim_lo) s00 = NEG;
                if (j + 1 > lim_lo) s01 = NEG;
                if (j     > lim_hi) s10 = NEG;
                if (j + 1 > lim_hi) s11 = NEG;
            }
            ka[nt][0] = s00; ka[nt][1] = s01; ka[nt][2] = s10; ka[nt][3] = s11;
            mx0 = fmaxf(mx0, fmaxf(s00, s01));
            mx1 = fmaxf(mx1, fmaxf(s10, s11));
        }
        mx0 = fmaxf(mx0, __shfl_xor_sync(0xffffffffu, mx0, 1));
        mx0 = fmaxf(mx0, __shfl_xor_sync(0xffffffffu, mx0, 2));
        mx1 = fmaxf(mx1, __shfl_xor_sync(0xffffffffu, mx1, 1));
        mx1 = fmaxf(mx1, __shfl_xor_sync(0xffffffffu, mx1, 2));
        const float mn0 = fmaxf(m_lo, mx0), mn1 = fmaxf(m_hi, mx1);
        const float a0 = fexp(m_lo - mn0),  a1 = fexp(m_hi - mn1);
        m_lo = mn0; m_hi = mn1;

        float sum0 = 0.0f, sum1 = 0.0f;
#pragma unroll
        for (int nt = 0; nt < 8; nt++) {
            const float p00 = fexp(ka[nt][0] - mn0);
            const float p01 = fexp(ka[nt][1] - mn0);
            const float p10 = fexp(ka[nt][2] - mn1);
            const float p11 = fexp(ka[nt][3] - mn1);
            sum0 += p00 + p01;
            sum1 += p10 + p11;
            ka[nt][0] = p00; ka[nt][1] = p01; ka[nt][2] = p10; ka[nt][3] = p11;
        }
        sum0 += __shfl_xor_sync(0xffffffffu, sum0, 1);
        sum0 += __shfl_xor_sync(0xffffffffu, sum0, 2);
        sum1 += __shfl_xor_sync(0xffffffffu, sum1, 1);
        sum1 += __shfl_xor_sync(0xffffffffu, sum1, 2);
        l_lo = l_lo * a0 + sum0;
        l_hi = l_hi * a1 + sum1;
#pragma unroll
        for (int nt = 0; nt < 8; nt++) {
            yacc[nt][0] *= a0; yacc[nt][1] *= a0;
            yacc[nt][2] *= a1; yacc[nt][3] *= a1;
        }

        // ---- Phase C (tf32): Y += P.V; P relayout C-frag -> A-frag ----
#pragma unroll
        for (int ks = 0; ks < 8; ks++) {
            const int k = ks * 8;
            const float v0 = __shfl_sync(0xffffffffu, ka[ks][0], srcA);
            const float v1 = __shfl_sync(0xffffffffu, ka[ks][1], srcA);
            const float w0 = __shfl_sync(0xffffffffu, ka[ks][0], srcA + 2);
            const float w1 = __shfl_sync(0xffffffffu, ka[ks][1], srcA + 2);
            const float u0 = __shfl_sync(0xffffffffu, ka[ks][2], srcA);
            const float u1 = __shfl_sync(0xffffffffu, ka[ks][3], srcA);
            const float t0 = __shfl_sync(0xffffffffu, ka[ks][2], srcA + 2);
            const float t1 = __shfl_sync(0xffffffffu, ka[ks][3], srcA + 2);
            uint32_t af[4];
            af[0] = f2tf(odd ? v1 : v0);
            af[1] = f2tf(odd ? u1 : u0);
            af[2] = f2tf(odd ? w1 : w0);
            af[3] = f2tf(odd ? t1 : t0);
#pragma unroll
            for (int nt = 0; nt < 8; nt++) {
                uint32_t bfv[2];
                bfv[0] = Vs[(k + tig) * LVW + nt * 8 + grp];
                bfv[1] = Vs[(k + tig + 4) * LVW + nt * 8 + grp];
                mma_tf32(yacc[nt], af, bfv);
            }
        }

        // ---- store prefetched tile into the alternate buffer ----
        if (pf) {
#pragma unroll
            for (int i = 0; i < 4; i++) {
                const int idx = i * 256 + tid;
                const int row = idx >> 4, sw = (idx & 15) * 2, dq = (idx & 15) * 4;
                sts_f16x4(&nxt[row * LKW + sw],        pk[i]);
                sts_f16x4(&nxt[2304 + row * LKW + sw], pe[i]);
                sts_tf32x4(&nxt[4608 + row * LVW + dq], pv[i]);
            }
        }
        __syncthreads();
    }

    // ---- Epilogue: normalize, write (B, L, D) ----
    const float linv0 = 1.0f / l_lo, linv1 = 1.0f / l_hi;
    const int rl = q0 + i_lo, rh = q0 + i_hi;
#pragma unroll
    for (int nt = 0; nt < 8; nt++) {
        const int col = h * 64 + nt * 8 + 2 * tig;
        float2 lo = make_float2(yacc[nt][0] * linv0, yacc[nt][1] * linv0);
        float2 hi = make_float2(yacc[nt][2] * linv1, yacc[nt][3] * linv1);
        *(float2*)&g_y[((size_t)b * L_ + rl) * D_ + col] = lo;
        *(float2*)&g_y[((size_t)b * L_ + rh) * D_ + col] = hi;
    }
}

// ---------------------------------------------------------------------------
extern "C" void kernel_launch(void* const* d_in, const int* in_sizes, int n_in,
                              void* d_out, int out_size)
{
    const float* x      = (const float*)d_in[0];   // (2, 2048, 1024)
    const float* W_attn = (const float*)d_in[1];   // (1024, 3072)
    const float* b_attn = (const float*)d_in[2];   // (3072,)
    const float* W_proj = (const float*)d_in[3];   // (1024, 1024)
    const float* b_proj = (const float*)d_in[4];   // (1024,)
    const float* Er     = (const float*)d_in[5];   // (2048, 64)
    float* out = (float*)d_out;

    cudaFuncSetAttribute(attn_kernel,
                         cudaFuncAttributeMaxDynamicSharedMemorySize, ATT_SMEMB);

    float* wat; cudaGetSymbolAddress((void**)&wat, g_wat);
    float* wpt; cudaGetSymbolAddress((void**)&wpt, g_wpt);
    float* y;   cudaGetSymbolAddress((void**)&y, g_y);

    // 0) Transpose weights to [N][K] for k-contiguous B-operand loads
    transpose_kernel<<<dim3(N3D_ / 32, D_ / 32), 256>>>(W_attn, wat, D_, N3D_);
    transpose_kernel<<<dim3(D_ / 32, D_ / 32), 256>>>(W_proj, wpt, D_, D_);

    // 1) QKV projection, fp16 mma (+ head scatter, q scaling)
    gemm_mma<0><<<dim3(N3D_ / 128, BL_ / 128), 256>>>(x, wat, b_attn, nullptr);

    // 2) Causal attention with relative position bias, fp16/tf32 mma
    attn_kernel<<<dim3(B_ * H_, 16), 256, ATT_SMEMB>>>(Er);

    // 3) Output projection, fp16 mma
    gemm_mma<1><<<dim3(D_ / 128, BL_ / 128), 256>>>(y, wpt, b_proj, out);
}

// round 16
// speedup vs baseline: 4.0921x; 1.0767x over previous
#include <cuda_runtime.h>
#include <cuda_bf16.h>
#include <cuda_fp16.h>
#include <math.h>
#include <stdint.h>

// Problem constants
#define B_   2
#define L_   2048
#define D_   1024
#define H_   16
#define HS_  64
#define BL_  (B_ * L_)        // 4096
#define N3D_ (3 * D_)         // 3072
#define GK   1024             // K dim of both GEMMs

// Scratch (device globals; allocation in kernel_launch is forbidden)
__device__ float g_q[B_ * H_ * L_ * HS_];   // (b*H+h, l, d), pre-scaled by 1/8
__device__ float g_k[B_ * H_ * L_ * HS_];
__device__ float g_v[B_ * H_ * L_ * HS_];
__device__ float g_y[BL_ * D_];             // (b, l, h*64+d)
__device__ float g_wat[N3D_ * D_];          // W_attn^T  [3072][1024]
__device__ float g_wpt[D_ * D_];            // W_proj^T  [1024][1024]

// ---------------------------------------------------------------------------
// mma.sync helpers (sm_80+ features only)
// ---------------------------------------------------------------------------
__device__ __forceinline__ uint32_t f2tf(float f) {
    uint32_t u;
    asm("cvt.rna.tf32.f32 %0, %1;" : "=r"(u) : "f"(f));
    return u;
}

// D(16x8,f32) += A(16x16,f16,row) * B(16x8,f16,col)
__device__ __forceinline__ void mma_f16(float* c, const uint32_t* a, const uint32_t* b) {
    asm volatile(
        "mma.sync.aligned.m16n8k16.row.col.f32.f16.f16.f32 "
        "{%0,%1,%2,%3},{%4,%5,%6,%7},{%8,%9},{%0,%1,%2,%3};"
        : "+f"(c[0]), "+f"(c[1]), "+f"(c[2]), "+f"(c[3])
        : "r"(a[0]), "r"(a[1]), "r"(a[2]), "r"(a[3]), "r"(b[0]), "r"(b[1]));
}

__device__ __forceinline__ void sts_tf32x4(uint32_t* p, float4 v) {
    uint4 u;
    u.x = f2tf(v.x); u.y = f2tf(v.y); u.z = f2tf(v.z); u.w = f2tf(v.w);
    *(uint4*)p = u;
}

__device__ __forceinline__ uint32_t f2h2(float lo, float hi) {
    __half2 h = __floats2half2_rn(lo, hi);
    return *reinterpret_cast<uint32_t*>(&h);
}

// 4 floats -> 4 halves (packed as 2 words)
__device__ __forceinline__ void sts_f16x4(uint32_t* p, float4 v) {
    uint2 u;
    u.x = f2h2(v.x, v.y);
    u.y = f2h2(v.z, v.w);
    *(uint2*)p = u;
}

// Fast exp on the FMA/ALU pipes (no MUFU). Valid for x <= 0 (clamped at -87).
__device__ __forceinline__ float fexp(float x) {
    x = fmaxf(x, -87.0f);
    const float L2E = 1.4426950408889634f;
    float y = fmaf(x, L2E, 12582912.0f);           // RN to integer
    int   n = __float_as_int(y) - 0x4B400000;
    float fl = y - 12582912.0f;
    float f = fmaf(x, L2E, -fl);                   // f in [-0.5, 0.5]
    float p = 1.3333558146428443e-3f;
    p = fmaf(p, f, 9.6181291076284772e-3f);
    p = fmaf(p, f, 5.5504108664821580e-2f);
    p = fmaf(p, f, 2.4022650695910071e-1f);
    p = fmaf(p, f, 6.9314718055994531e-1f);
    p = fmaf(p, f, 1.0f);
    return __int_as_float(__float_as_int(p) + (n << 23));
}

// ---------------------------------------------------------------------------
// Transpose: src[K][N] -> dst[N][K]
// ---------------------------------------------------------------------------
__global__ __launch_bounds__(256) void transpose_kernel(
    const float* __restrict__ src, float* __restrict__ dst, int K, int N)
{
    __shared__ float s[32][33];
    const int tx = threadIdx.x & 31, ty = threadIdx.x >> 5;
    const int gx = blockIdx.x * 32, gy = blockIdx.y * 32;
#pragma unroll
    for (int j = 0; j < 4; j++)
        s[ty + j * 8][tx] = src[(size_t)(gy + ty + j * 8) * N + gx + tx];
    __syncthreads();
#pragma unroll
    for (int j = 0; j < 4; j++)
        dst[(size_t)(gx + ty + j * 8) * K + gy + tx] = s[tx][ty + j * 8];
}

// ---------------------------------------------------------------------------
// fp16 mma.sync GEMM (unchanged from R15 passing version)
// ---------------------------------------------------------------------------
#define GLW 12
template <int MODE>
__global__ __launch_bounds__(256, 2) void gemm_mma(
    const float* __restrict__ A, const float* __restrict__ Bt,
    const float* __restrict__ bias, float* __restrict__ outp)
{
    __shared__ float    bias_s[128];
    __shared__ uint32_t As[2][128 * GLW];
    __shared__ uint32_t Bs[2][128 * GLW];

    const int tid = threadIdx.x;
    const int lane = tid & 31;
    const int wid = tid >> 5;
    const int grp = lane >> 2, tig = lane & 3;
    const int wm = wid & 3, wn = wid >> 2;
    const int row0 = blockIdx.y * 128, col0 = blockIdx.x * 128;

    if (tid < 128) bias_s[tid] = bias[col0 + tid];

    const int lr = tid >> 2;              // 0..63
    const int lq = (tid & 3) * 4;         // float offset within k16
    const int lw = (tid & 3) * 2;         // word offset (halves) within chunk row

    float acc[2][8][4];
#pragma unroll
    for (int mt = 0; mt < 2; mt++)
#pragma unroll
        for (int nt = 0; nt < 8; nt++)
#pragma unroll
            for (int i = 0; i < 4; i++) acc[mt][nt][i] = 0.0f;

    float4 pa0, pa1, pb0, pb1;
    pa0 = *(const float4*)&A [(size_t)(row0 + lr)      * GK + lq];
    pa1 = *(const float4*)&A [(size_t)(row0 + 64 + lr) * GK + lq];
    pb0 = *(const float4*)&Bt[(size_t)(col0 + lr)      * GK + lq];
    pb1 = *(const float4*)&Bt[(size_t)(col0 + 64 + lr) * GK + lq];
    sts_f16x4(&As[0][lr * GLW + lw],        pa0);
    sts_f16x4(&As[0][(64 + lr) * GLW + lw], pa1);
    sts_f16x4(&Bs[0][lr * GLW + lw],        pb0);
    sts_f16x4(&Bs[0][(64 + lr) * GLW + lw], pb1);
    __syncthreads();

    for (int c = 0; c < 64; c++) {
        const int bf = c & 1;
        if (c < 63) {
            const int k0 = (c + 1) * 16;
            pa0 = *(const float4*)&A [(size_t)(row0 + lr)      * GK + k0 + lq];
            pa1 = *(const float4*)&A [(size_t)(row0 + 64 + lr) * GK + k0 + lq];
            pb0 = *(const float4*)&Bt[(size_t)(col0 + lr)      * GK + k0 + lq];
            pb1 = *(const float4*)&Bt[(size_t)(col0 + 64 + lr) * GK + k0 + lq];
        }

        // one k16 fp16 MMA step per chunk
        {
            uint32_t af[2][4];
#pragma unroll
            for (int mt = 0; mt < 2; mt++) {
                const uint32_t* r0 = &As[bf][(wm * 32 + mt * 16 + grp) * GLW];
                af[mt][0] = r0[tig];
                af[mt][1] = r0[8 * GLW + tig];
                af[mt][2] = r0[tig + 4];
                af[mt][3] = r0[8 * GLW + tig + 4];
            }
            uint32_t bfr[8][2];
#pragma unroll
            for (int nt = 0; nt < 8; nt++) {
                const uint32_t* rb = &Bs[bf][(wn * 64 + nt * 8 + grp) * GLW];
                bfr[nt][0] = rb[tig];
                bfr[nt][1] = rb[tig + 4];
            }
#pragma unroll
            for (int mt = 0; mt < 2; mt++)
#pragma unroll
                for (int nt = 0; nt < 8; nt++)
                    mma_f16(acc[mt][nt], af[mt], bfr[nt]);
        }

        if (c < 63) {
            const int nb = bf ^ 1;
            sts_f16x4(&As[nb][lr * GLW + lw],        pa0);
            sts_f16x4(&As[nb][(64 + lr) * GLW + lw], pa1);
            sts_f16x4(&Bs[nb][lr * GLW + lw],        pb0);
            sts_f16x4(&Bs[nb][(64 + lr) * GLW + lw], pb1);
        }
        __syncthreads();
    }

#pragma unroll
    for (int nt = 0; nt < 8; nt++) {
        const int colb = col0 + wn * 64 + nt * 8;
        const int cloc = colb - col0 + 2 * tig;
        float scl = 1.0f;
        float* dstb = outp;
        int h = 0;
        if (MODE == 0) {
            const int sec = colb >> 10;
            const int cm = colb & 1023;
            h = cm >> 6;
            dstb = (sec == 0) ? g_q : (sec == 1) ? g_k : g_v;
            scl = (sec == 0) ? 0.125f : 1.0f;
        }
        const int d0 = MODE == 0 ? ((colb & 63) + 2 * tig) : 0;
#pragma unroll
        for (int mt = 0; mt < 2; mt++) {
            const int gm_lo = row0 + wm * 32 + mt * 16 + grp;
            const int gm_hi = gm_lo + 8;
            float2 lo, hi;
            lo.x = (acc[mt][nt][0] + bias_s[cloc])     * scl;
            lo.y = (acc[mt][nt][1] + bias_s[cloc + 1]) * scl;
            hi.x = (acc[mt][nt][2] + bias_s[cloc])     * scl;
            hi.y = (acc[mt][nt][3] + bias_s[cloc + 1]) * scl;
            if (MODE == 0) {
                const int bb_lo = gm_lo >> 11, l_lo = gm_lo & 2047;
                const int bb_hi = gm_hi >> 11, l_hi = gm_hi & 2047;
                *(float2*)&dstb[(((size_t)(bb_lo * H_ + h)) * L_ + l_lo) * HS_ + d0] = lo;
                *(float2*)&dstb[(((size_t)(bb_hi * H_ + h)) * L_ + l_hi) * HS_ + d0] = hi;
            } else {
                *(float2*)&outp[(size_t)gm_lo * D_ + colb + 2 * tig] = lo;
                *(float2*)&outp[(size_t)gm_hi * D_ + colb + 2 * tig] = hi;
            }
        }
    }
}

// ---------------------------------------------------------------------------
// R16 attention: ALL-fp16 operands (fp32 accum). Phase C uses the FA2 trick:
// the softmax'd S C-fragment IS the P A-fragment (packed half2) -> no shuffles,
// no smem P. V stored fp16 in j-pair-interleaved layout (word[(j/2)*72+d] =
// (V[j],V[j+1]) at dim d), built with lane^16 shuffles at store time; LVP=72
// gives conflict-free B-fragment loads. Double-buffered K/E/V + reg prefetch.
// ---------------------------------------------------------------------------
#define LQW 36               // Q row stride in words (64 halves = 32w + pad)
#define LKW 36               // K/E row stride in words
#define LVP 72               // V pair-row stride in words (conflict-free)
#define AQOFF  0             // Q: 128*36 = 4608 words
#define ABUF0  4608          // buffer: K(2304) + E(2304) + V(2304) = 6912
#define ABUF1  11520
#define ARWORD 18432         // R fp16 128*256 halves = 16384 words
#define ATT_SMEMB ((18432 + 16384) * 4)   // 139264 B

// Store one float4 (row, d=dq..dq+3) of V into pair-interleaved fp16 layout.
// Lane pairs (lane, lane^16) hold rows (r, r+1) at the same dq; exchange via
// shuffle, even-row lane stores words d=dq,dq+1, odd-row lane stores dq+2,dq+3.
__device__ __forceinline__ void sts_v_pair(uint32_t* Vbase, int row, int dq, float4 v) {
    float4 pr;
    pr.x = __shfl_xor_sync(0xffffffffu, v.x, 16);
    pr.y = __shfl_xor_sync(0xffffffffu, v.y, 16);
    pr.z = __shfl_xor_sync(0xffffffffu, v.z, 16);
    pr.w = __shfl_xor_sync(0xffffffffu, v.w, 16);
    uint2 w;
    int d;
    if ((row & 1) == 0) {
        w.x = f2h2(v.x, pr.x);
        w.y = f2h2(v.y, pr.y);
        d = dq;
    } else {
        w.x = f2h2(pr.z, v.z);
        w.y = f2h2(pr.w, v.w);
        d = dq + 2;
    }
    *(uint2*)&Vbase[(row >> 1) * LVP + d] = w;
}

// Q x E-block fp16 MMA -> store 64 new R ring columns (warp-local rows)
__device__ __forceinline__ void er_mma_store(
    const uint32_t* Qs, const uint32_t* Es, __half* Rh,
    int eb, int i_lo, int i_hi, int grp, int tig)
{
    float ea[8][4];
#pragma unroll
    for (int nt = 0; nt < 8; nt++)
#pragma unroll
        for (int i = 0; i < 4; i++) ea[nt][i] = 0.0f;
#pragma unroll
    for (int ks = 0; ks < 4; ks++) {
        const int kw = ks * 8;
        uint32_t qf[4];
        const uint32_t* qlo = &Qs[i_lo * LQW + kw];
        const uint32_t* qhi = &Qs[i_hi * LQW + kw];
        qf[0] = qlo[tig]; qf[1] = qhi[tig];
        qf[2] = qlo[tig + 4]; qf[3] = qhi[tig + 4];
#pragma unroll
        for (int nt = 0; nt < 8; nt++) {
            const uint32_t* rb = &Es[(nt * 8 + grp) * LKW + kw];
            uint32_t bfv[2] = { rb[tig], rb[tig + 4] };
            mma_f16(ea[nt], qf, bfv);
        }
    }
#pragma unroll
    for (int nt = 0; nt < 8; nt++) {
        const int cc = eb + nt * 8 + 2 * tig;
        Rh[(i_lo << 8) | (cc & 255)]       = __float2half(ea[nt][0]);
        Rh[(i_lo << 8) | ((cc + 1) & 255)] = __float2half(ea[nt][1]);
        Rh[(i_hi << 8) | (cc & 255)]       = __float2half(ea[nt][2]);
        Rh[(i_hi << 8) | ((cc + 1) & 255)] = __float2half(ea[nt][3]);
    }
}

__global__ __launch_bounds__(256) void attn_kernel(const float* __restrict__ Er)
{
    extern __shared__ float sm[];
    uint32_t* Qs   = (uint32_t*)(sm + AQOFF);
    uint32_t* bufA = (uint32_t*)(sm + ABUF0);
    uint32_t* bufB = (uint32_t*)(sm + ABUF1);
    __half*   Rh   = (__half*)(sm + ARWORD);

    const int tid = threadIdx.x;
    const int wid = tid >> 5, lane = tid & 31;
    const int grp = lane >> 2, tig = lane & 3;
    const int bh = blockIdx.x;                 // 0..31
    const int qt = 15 - (int)blockIdx.y;       // biggest q-tiles first (LPT)
    const int q0 = qt * 128;
    const int nkt = 2 * qt + 2;
    const int e00 = (L_ - 1) - q0;
    const int m0 = wid * 16;
    const int i_lo = m0 + grp, i_hi = i_lo + 8;
    const int b = bh >> 4, h = bh & 15;
    const float NEG = -1e30f;

    // Load Q tile (128x64 -> fp16)
#pragma unroll
    for (int i = 0; i < 8; i++) {
        const int idx = i * 256 + tid;
        const int row = idx >> 4, sw = (idx & 15) * 2, dq = (idx & 15) * 4;
        float4 v = *(const float4*)&g_q[((size_t)bh * L_ + q0 + row) * HS_ + dq];
        sts_f16x4(&Qs[row * LQW + sw], v);
    }

    // ---- R ring prefill block A: [e00-128, e00-64) -> bufA.E ----
    {
        const int eb = e00 - 128;
#pragma unroll
        for (int i = 0; i < 4; i++) {
            const int idx = i * 256 + tid;
            const int row = idx >> 4, sw = (idx & 15) * 2, dq = (idx & 15) * 4;
            int er = eb + row; er = er < 0 ? 0 : (er > L_ - 1 ? L_ - 1 : er);
            float4 v = *(const float4*)&Er[(size_t)er * HS_ + dq];
            sts_f16x4(&bufA[2304 + row * LKW + sw], v);
        }
        __syncthreads();
        er_mma_store(Qs, bufA + 2304, Rh, eb, i_lo, i_hi, grp, tig);
        __syncthreads();   // bufA.E free
    }
    // ---- prefill block B -> bufB.E; tile0 K,E,V -> bufA ----
    {
        const int ebB = e00 - 64;
#pragma unroll
        for (int i = 0; i < 4; i++) {
            const int idx = i * 256 + tid;
            const int row = idx >> 4, sw = (idx & 15) * 2, dq = (idx & 15) * 4;
            int er = ebB + row; er = er < 0 ? 0 : (er > L_ - 1 ? L_ - 1 : er);
            float4 v = *(const float4*)&Er[(size_t)er * HS_ + dq];
            sts_f16x4(&bufB[2304 + row * LKW + sw], v);
            float4 kv = *(const float4*)&g_k[((size_t)bh * L_ + row) * HS_ + dq];
            float4 vv = *(const float4*)&g_v[((size_t)bh * L_ + row) * HS_ + dq];
            sts_f16x4(&bufA[row * LKW + sw], kv);
            sts_v_pair(bufA + 4608, row, dq, vv);
            int er0 = e00 + row; if (er0 > L_ - 1) er0 = L_ - 1;
            float4 ev = *(const float4*)&Er[(size_t)er0 * HS_ + dq];
            sts_f16x4(&bufA[2304 + row * LKW + sw], ev);
        }
        __syncthreads();
        er_mma_store(Qs, bufB + 2304, Rh, ebB, i_lo, i_hi, grp, tig);
        __syncthreads();   // bufB.E free (tile0 prefetch will overwrite it)
    }

    float m_lo = NEG, m_hi = NEG, l_lo = 0.0f, l_hi = 0.0f;
    float yacc[8][4];
#pragma unroll
    for (int nt = 0; nt < 8; nt++)
#pragma unroll
        for (int i = 0; i < 4; i++) yacc[nt][i] = 0.0f;

    // ---- main k-tile loop: compute on buf[kt&1], prefetch into buf[~] ----
#pragma unroll 1
    for (int kt = 0; kt < nkt; kt++) {
        uint32_t* cur = (kt & 1) ? bufB : bufA;
        uint32_t* nxt = (kt & 1) ? bufA : bufB;
        const int e0k = e00 + 64 * kt;

        // prefetch next tile's K,V,E into registers (latency hidden by compute)
        float4 pk[4], pv[4], pe[4];
        const bool pf = (kt + 1 < nkt);
        if (pf) {
            const int k0n = (kt + 1) * 64;
            const int ebn = e0k + 64;
#pragma unroll
            for (int i = 0; i < 4; i++) {
                const int idx = i * 256 + tid;
                const int row = idx >> 4, dq = (idx & 15) * 4;
                pk[i] = *(const float4*)&g_k[((size_t)bh * L_ + k0n + row) * HS_ + dq];
                pv[i] = *(const float4*)&g_v[((size_t)bh * L_ + k0n + row) * HS_ + dq];
                int er = ebn + row; if (er > L_ - 1) er = L_ - 1;
                pe[i] = *(const float4*)&Er[(size_t)er * HS_ + dq];
            }
        }

        const uint32_t* Ks = cur;
        const uint32_t* Es = cur + 2304;
        const uint32_t* Vs = cur + 4608;

        // ---- Phase A (fp16): ka = Q.K^T, ea = Q.Enew^T (shared Q frags) ----
        float ka[8][4], ea[8][4];
#pragma unroll
        for (int nt = 0; nt < 8; nt++)
#pragma unroll
            for (int i = 0; i < 4; i++) { ka[nt][i] = 0.0f; ea[nt][i] = 0.0f; }
#pragma unroll
        for (int ks = 0; ks < 4; ks++) {
            const int kw = ks * 8;
            uint32_t qf[4];
            const uint32_t* qlo = &Qs[i_lo * LQW + kw];
            const uint32_t* qhi = &Qs[i_hi * LQW + kw];
            qf[0] = qlo[tig]; qf[1] = qhi[tig];
            qf[2] = qlo[tig + 4]; qf[3] = qhi[tig + 4];
#pragma unroll
            for (int nt = 0; nt < 8; nt++) {
                const uint32_t* rb = &Ks[(nt * 8 + grp) * LKW + kw];
                uint32_t bfv[2] = { rb[tig], rb[tig + 4] };
                mma_f16(ka[nt], qf, bfv);
            }
#pragma unroll
            for (int nt = 0; nt < 8; nt++) {
                const uint32_t* rb = &Es[(nt * 8 + grp) * LKW + kw];
                uint32_t bfv[2] = { rb[tig], rb[tig + 4] };
                mma_f16(ea[nt], qf, bfv);
            }
        }
        // store new R ring block (warp-local rows)
#pragma unroll
        for (int nt = 0; nt < 8; nt++) {
            const int cc = e0k + nt * 8 + 2 * tig;
            Rh[(i_lo << 8) | (cc & 255)]       = __float2half(ea[nt][0]);
            Rh[(i_lo << 8) | ((cc + 1) & 255)] = __float2half(ea[nt][1]);
            Rh[(i_hi << 8) | (cc & 255)]       = __float2half(ea[nt][2]);
            Rh[(i_hi << 8) | ((cc + 1) & 255)] = __float2half(ea[nt][3]);
        }
        __syncwarp();

        // ---- Phase B: register softmax (P stays in ka) ----
        const bool masked = (kt >= 2 * qt);
        const int lim_lo = q0 - kt * 64 + i_lo, lim_hi = lim_lo + 8;
        float mx0 = NEG, mx1 = NEG;
#pragma unroll
        for (int nt = 0; nt < 8; nt++) {
            const int j = nt * 8 + 2 * tig;
            float s00 = ka[nt][0] + __half2float(Rh[(i_lo << 8) | ((e0k + j     - i_lo) & 255)]);
            float s01 = ka[nt][1] + __half2float(Rh[(i_lo << 8) | ((e0k + j + 1 - i_lo) & 255)]);
            float s10 = ka[nt][2] + __half2float(Rh[(i_hi << 8) | ((e0k + j     - i_hi) & 255)]);
            float s11 = ka[nt][3] + __half2float(Rh[(i_hi << 8) | ((e0k + j + 1 - i_hi) & 255)]);
            if (masked) {
                if (j     > lim_lo) s00 = NEG;
                if (j + 1 > lim_lo) s01 = NEG;
                if (j     > lim_hi) s10 = NEG;
                if (j + 1 > lim_hi) s11 = NEG;
            }
            ka[nt][0] = s00; ka[nt][1] = s01; ka[nt][2] = s10; ka[nt][3] = s11;
            mx0 = fmaxf(mx0, fmaxf(s00, s01));
            mx1 = fmaxf(mx1, fmaxf(s10, s11));
        }
        mx0 = fmaxf(mx0, __shfl_xor_sync(0xffffffffu, mx0, 1));
        mx0 = fmaxf(mx0, __shfl_xor_sync(0xffffffffu, mx0, 2));
        mx1 = fmaxf(mx1, __shfl_xor_sync(0xffffffffu, mx1, 1));
        mx1 = fmaxf(mx1, __shfl_xor_sync(0xffffffffu, mx1, 2));
        const float mn0 = fmaxf(m_lo, mx0), mn1 = fmaxf(m_hi, mx1);
        const float a0 = fexp(m_lo - mn0),  a1 = fexp(m_hi - mn1);
        m_lo = mn0; m_hi = mn1;

        float sum0 = 0.0f, sum1 = 0.0f;
#pragma unroll
        for (int nt = 0; nt < 8; nt++) {
            const float p00 = fexp(ka[nt][0] - mn0);
            const float p01 = fexp(ka[nt][1] - mn0);
            const float p10 = fexp(ka[nt][2] - mn1);
            const float p11 = fexp(ka[nt][3] - mn1);
            sum0 += p00 + p01;
            sum1 += p10 + p11;
            ka[nt][0] = p00; ka[nt][1] = p01; ka[nt][2] = p10; ka[nt][3] = p11;
        }
        sum0 += __shfl_xor_sync(0xffffffffu, sum0, 1);
        sum0 += __shfl_xor_sync(0xffffffffu, sum0, 2);
        sum1 += __shfl_xor_sync(0xffffffffu, sum1, 1);
        sum1 += __shfl_xor_sync(0xffffffffu, sum1, 2);
        l_lo = l_lo * a0 + sum0;
        l_hi = l_hi * a1 + sum1;
#pragma unroll
        for (int nt = 0; nt < 8; nt++) {
            yacc[nt][0] *= a0; yacc[nt][1] *= a0;
            yacc[nt][2] *= a1; yacc[nt][3] *= a1;
        }

        // ---- Phase C (fp16): Y += P.V; S C-frag == P A-frag (FA2 trick) ----
#pragma unroll
        for (int ks = 0; ks < 4; ks++) {
            uint32_t af[4];
            af[0] = f2h2(ka[2 * ks][0],     ka[2 * ks][1]);
            af[1] = f2h2(ka[2 * ks][2],     ka[2 * ks][3]);
            af[2] = f2h2(ka[2 * ks + 1][0], ka[2 * ks + 1][1]);
            af[3] = f2h2(ka[2 * ks + 1][2], ka[2 * ks + 1][3]);
#pragma unroll
            for (int nt = 0; nt < 8; nt++) {
                uint32_t bfv[2];
                bfv[0] = Vs[(8 * ks + tig)     * LVP + nt * 8 + grp];
                bfv[1] = Vs[(8 * ks + tig + 4) * LVP + nt * 8 + grp];
                mma_f16(yacc[nt], af, bfv);
            }
        }

        // ---- store prefetched tile into the alternate buffer ----
        if (pf) {
#pragma unroll
            for (int i = 0; i < 4; i++) {
                const int idx = i * 256 + tid;
                const int row = idx >> 4, sw = (idx & 15) * 2, dq = (idx & 15) * 4;
                sts_f16x4(&nxt[row * LKW + sw],        pk[i]);
                sts_f16x4(&nxt[2304 + row * LKW + sw], pe[i]);
                sts_v_pair(nxt + 4608, row, dq, pv[i]);
            }
        }
        __syncthreads();
    }

    // ---- Epilogue: normalize, write (B, L, D) ----
    const float linv0 = 1.0f / l_lo, linv1 = 1.0f / l_hi;
    const int rl = q0 + i_lo, rh = q0 + i_hi;
#pragma unroll
    for (int nt = 0; nt < 8; nt++) {
        const int col = h * 64 + nt * 8 + 2 * tig;
        float2 lo = make_float2(yacc[nt][0] * linv0, yacc[nt][1] * linv0);
        float2 hi = make_float2(yacc[nt][2] * linv1, yacc[nt][3] * linv1);
        *(float2*)&g_y[((size_t)b * L_ + rl) * D_ + col] = lo;
        *(float2*)&g_y[((size_t)b * L_ + rh) * D_ + col] = hi;
    }
}

// ---------------------------------------------------------------------------
extern "C" void kernel_launch(void* const* d_in, const int* in_sizes, int n_in,
                              void* d_out, int out_size)
{
    const float* x      = (const float*)d_in[0];   // (2, 2048, 1024)
    const float* W_attn = (const float*)d_in[1];   // (1024, 3072)
    const float* b_attn = (const float*)d_in[2];   // (3072,)
    const float* W_proj = (const float*)d_in[3];   // (1024, 1024)
    const float* b_proj = (const float*)d_in[4];   // (1024,)
    const float* Er     = (const float*)d_in[5];   // (2048, 64)
    float* out = (float*)d_out;

    cudaFuncSetAttribute(attn_kernel,
                         cudaFuncAttributeMaxDynamicSharedMemorySize, ATT_SMEMB);

    float* wat; cudaGetSymbolAddress((void**)&wat, g_wat);
    float* wpt; cudaGetSymbolAddress((void**)&wpt, g_wpt);
    float* y;   cudaGetSymbolAddress((void**)&y, g_y);

    // 0) Transpose weights to [N][K] for k-contiguous B-operand loads
    transpose_kernel<<<dim3(N3D_ / 32, D_ / 32), 256>>>(W_attn, wat, D_, N3D_);
    transpose_kernel<<<dim3(D_ / 32, D_ / 32), 256>>>(W_proj, wpt, D_, D_);

    // 1) QKV projection, fp16 mma (+ head scatter, q scaling)
    gemm_mma<0><<<dim3(N3D_ / 128, BL_ / 128), 256>>>(x, wat, b_attn, nullptr);

    // 2) Causal attention with relative position bias, fp16 mma
    attn_kernel<<<dim3(B_ * H_, 16), 256, ATT_SMEMB>>>(Er);

    // 3) Output projection, fp16 mma
    gemm_mma<1><<<dim3(D_ / 128, BL_ / 128), 256>>>(y, wpt, b_proj, out);
}

// round 17
// speedup vs baseline: 5.1938x; 1.2692x over previous
#include <cuda_runtime.h>
#include <cuda_bf16.h>
#include <cuda_fp16.h>
#include <math.h>
#include <stdint.h>

// Problem constants
#define B_   2
#define L_   2048
#define D_   1024
#define H_   16
#define HS_  64
#define BL_  (B_ * L_)        // 4096
#define N3D_ (3 * D_)         // 3072
#define GK   1024             // K dim of both GEMMs

// Scratch (device globals; allocation in kernel_launch is forbidden)
__device__ __align__(16) __half   g_xh [BL_ * D_];            // x in fp16
__device__ __align__(16) __half   g_wat[N3D_ * GK];           // W_attn^T fp16
__device__ __align__(16) __half   g_wpt[D_ * GK];             // W_proj^T fp16
__device__ __align__(16) __half   g_qh [B_ * H_ * L_ * HS_];  // q fp16 (scaled 1/8)
__device__ __align__(16) __half   g_kh [B_ * H_ * L_ * HS_];  // k fp16
__device__ __align__(16) uint32_t g_vp [B_ * H_ * (L_/2) * HS_]; // V pair-interleaved half2
__device__ __align__(16) __half   g_erh[L_ * HS_];            // Er fp16
__device__ __align__(16) __half   g_yh [BL_ * D_];            // attn out fp16

// ---------------------------------------------------------------------------
// helpers
// ---------------------------------------------------------------------------
__device__ __forceinline__ uint32_t smem_u32(const void* p) {
    uint32_t a;
    asm("{ .reg .u64 t; cvta.to.shared.u64 t, %1; cvt.u32.u64 %0, t; }" : "=r"(a) : "l"(p));
    return a;
}
#define CP16(dst, src) \
    asm volatile("cp.async.cg.shared.global [%0], [%1], 16;" :: "r"((uint32_t)(dst)), "l"(src) : "memory")
#define CPCOMMIT()  asm volatile("cp.async.commit_group;" ::: "memory")
#define CPWAITALL() asm volatile("cp.async.wait_group 0;" ::: "memory")

// D(16x8,f32) += A(16x16,f16,row) * B(16x8,f16,col)
__device__ __forceinline__ void mma_f16(float* c, const uint32_t* a, const uint32_t* b) {
    asm volatile(
        "mma.sync.aligned.m16n8k16.row.col.f32.f16.f16.f32 "
        "{%0,%1,%2,%3},{%4,%5,%6,%7},{%8,%9},{%0,%1,%2,%3};"
        : "+f"(c[0]), "+f"(c[1]), "+f"(c[2]), "+f"(c[3])
        : "r"(a[0]), "r"(a[1]), "r"(a[2]), "r"(a[3]), "r"(b[0]), "r"(b[1]));
}

__device__ __forceinline__ uint32_t f2h2(float lo, float hi) {
    __half2 h = __floats2half2_rn(lo, hi);
    return *reinterpret_cast<uint32_t*>(&h);
}

// Fast exp on the FMA/ALU pipes (no MUFU). Valid for x <= 0 (clamped at -87).
__device__ __forceinline__ float fexp(float x) {
    x = fmaxf(x, -87.0f);
    const float L2E = 1.4426950408889634f;
    float y = fmaf(x, L2E, 12582912.0f);
    int   n = __float_as_int(y) - 0x4B400000;
    float fl = y - 12582912.0f;
    float f = fmaf(x, L2E, -fl);
    float p = 1.3333558146428443e-3f;
    p = fmaf(p, f, 9.6181291076284772e-3f);
    p = fmaf(p, f, 5.5504108664821580e-2f);
    p = fmaf(p, f, 2.4022650695910071e-1f);
    p = fmaf(p, f, 6.9314718055994531e-1f);
    p = fmaf(p, f, 1.0f);
    return __int_as_float(__float_as_int(p) + (n << 23));
}

// ---------------------------------------------------------------------------
// fp32 -> fp16 convert (vectorized)
// ---------------------------------------------------------------------------
__global__ __launch_bounds__(256) void f32_to_f16_kernel(
    const float* __restrict__ s, __half* __restrict__ d, int n4)
{
    int i = blockIdx.x * 256 + threadIdx.x;
    if (i < n4) {
        float4 v = ((const float4*)s)[i];
        uint2 u;
        u.x = f2h2(v.x, v.y);
        u.y = f2h2(v.z, v.w);
        ((uint2*)d)[i] = u;
    }
}

// ---------------------------------------------------------------------------
// Transpose + fp16: src[K][N] fp32 -> dst[N][K] fp16
// ---------------------------------------------------------------------------
__global__ __launch_bounds__(256) void transpose_h_kernel(
    const float* __restrict__ src, __half* __restrict__ dst, int K, int N)
{
    __shared__ float s[32][33];
    const int tx = threadIdx.x & 31, ty = threadIdx.x >> 5;
    const int gx = blockIdx.x * 32, gy = blockIdx.y * 32;
#pragma unroll
    for (int j = 0; j < 4; j++)
        s[ty + j * 8][tx] = src[(size_t)(gy + ty + j * 8) * N + gx + tx];
    __syncthreads();
#pragma unroll
    for (int j = 0; j < 4; j++)
        dst[(size_t)(gx + ty + j * 8) * K + gy + tx] = __float2half(s[tx][ty + j * 8]);
}

// ---------------------------------------------------------------------------
// fp16 GEMM with cp.async double-buffer: C[M][Ntot] = A x Bt^T + bias
// A, Bt fp16 in gmem (K-contiguous). 128x128 CTA tile, 8 warps, k16 chunks.
// MODE 0: epilogue scatters q (scaled, fp16), k (fp16), v (pair-interleaved).
// MODE 1: out fp32 row-major.
// ---------------------------------------------------------------------------
#define GLW 12
template <int MODE>
__global__ __launch_bounds__(256, 2) void gemm_mma(
    const __half* __restrict__ A, const __half* __restrict__ Bt,
    const float* __restrict__ bias, float* __restrict__ outp)
{
    __shared__ float    bias_s[128];
    __shared__ uint32_t As[2][128 * GLW];
    __shared__ uint32_t Bs[2][128 * GLW];

    const int tid = threadIdx.x;
    const int lane = tid & 31;
    const int wid = tid >> 5;
    const int grp = lane >> 2, tig = lane & 3;
    const int wm = wid & 3, wn = wid >> 2;
    const int row0 = blockIdx.y * 128, col0 = blockIdx.x * 128;

    const uint32_t as_u[2] = { smem_u32(&As[0][0]), smem_u32(&As[1][0]) };
    const uint32_t bs_u[2] = { smem_u32(&Bs[0][0]), smem_u32(&Bs[1][0]) };

    if (tid < 128) bias_s[tid] = bias[col0 + tid];

    const int lr = tid >> 1;          // 0..127 row
    const int lc = tid & 1;           // chunk (16 halves each)

    float acc[2][8][4];
#pragma unroll
    for (int mt = 0; mt < 2; mt++)
#pragma unroll
        for (int nt = 0; nt < 8; nt++)
#pragma unroll
            for (int i = 0; i < 4; i++) acc[mt][nt][i] = 0.0f;

    // issue chunk 0
    CP16(as_u[0] + (lr * GLW + lc * 4) * 4, &A [(size_t)(row0 + lr) * GK + lc * 8]);
    CP16(bs_u[0] + (lr * GLW + lc * 4) * 4, &Bt[(size_t)(col0 + lr) * GK + lc * 8]);
    CPCOMMIT();
    CPWAITALL();
    __syncthreads();

    for (int c = 0; c < 64; c++) {
        const int bf = c & 1;
        if (c < 63) {
            const int k0 = (c + 1) * 16;
            const int nb = bf ^ 1;
            CP16(as_u[nb] + (lr * GLW + lc * 4) * 4, &A [(size_t)(row0 + lr) * GK + k0 + lc * 8]);
            CP16(bs_u[nb] + (lr * GLW + lc * 4) * 4, &Bt[(size_t)(col0 + lr) * GK + k0 + lc * 8]);
            CPCOMMIT();
        }

        {
            uint32_t af[2][4];
#pragma unroll
            for (int mt = 0; mt < 2; mt++) {
                const uint32_t* r0 = &As[bf][(wm * 32 + mt * 16 + grp) * GLW];
                af[mt][0] = r0[tig];
                af[mt][1] = r0[8 * GLW + tig];
                af[mt][2] = r0[tig + 4];
                af[mt][3] = r0[8 * GLW + tig + 4];
            }
            uint32_t bfr[8][2];
#pragma unroll
            for (int nt = 0; nt < 8; nt++) {
                const uint32_t* rb = &Bs[bf][(wn * 64 + nt * 8 + grp) * GLW];
                bfr[nt][0] = rb[tig];
                bfr[nt][1] = rb[tig + 4];
            }
#pragma unroll
            for (int mt = 0; mt < 2; mt++)
#pragma unroll
                for (int nt = 0; nt < 8; nt++)
                    mma_f16(acc[mt][nt], af[mt], bfr[nt]);
        }

        if (c < 63) CPWAITALL();
        __syncthreads();
    }

    // ---- epilogue ----
#pragma unroll
    for (int nt = 0; nt < 8; nt++) {
        const int colb = col0 + wn * 64 + nt * 8;
        const int cloc = colb - col0 + 2 * tig;
#pragma unroll
        for (int mt = 0; mt < 2; mt++) {
            const int gm_lo = row0 + wm * 32 + mt * 16 + grp;
            const int gm_hi = gm_lo + 8;
            float2 lo, hi;
            lo.x = acc[mt][nt][0] + bias_s[cloc];
            lo.y = acc[mt][nt][1] + bias_s[cloc + 1];
            hi.x = acc[mt][nt][2] + bias_s[cloc];
            hi.y = acc[mt][nt][3] + bias_s[cloc + 1];
            if (MODE == 1) {
                *(float2*)&outp[(size_t)gm_lo * D_ + colb + 2 * tig] = lo;
                *(float2*)&outp[(size_t)gm_hi * D_ + colb + 2 * tig] = hi;
            } else {
                const int sec = colb >> 10;
                const int cm = colb & 1023;
                const int h = cm >> 6;
                const int d0 = (colb & 63) + 2 * tig;
                const int bb = gm_lo >> 11;
                const int l_lo = gm_lo & 2047, l_hi = gm_hi & 2047;
                const size_t bh_i = (size_t)(bb * H_ + h);
                if (sec == 0) {
                    *(uint32_t*)&g_qh[(bh_i * L_ + l_lo) * HS_ + d0] = f2h2(lo.x * 0.125f, lo.y * 0.125f);
                    *(uint32_t*)&g_qh[(bh_i * L_ + l_hi) * HS_ + d0] = f2h2(hi.x * 0.125f, hi.y * 0.125f);
                } else if (sec == 1) {
                    *(uint32_t*)&g_kh[(bh_i * L_ + l_lo) * HS_ + d0] = f2h2(lo.x, lo.y);
                    *(uint32_t*)&g_kh[(bh_i * L_ + l_hi) * HS_ + d0] = f2h2(hi.x, hi.y);
                } else {
                    // V: pair-interleave rows (j, j+1) via partner lane (grp^1 = lane^4)
                    float plox = __shfl_xor_sync(0xffffffffu, lo.x, 4);
                    float ploy = __shfl_xor_sync(0xffffffffu, lo.y, 4);
                    float phix = __shfl_xor_sync(0xffffffffu, hi.x, 4);
                    float phiy = __shfl_xor_sync(0xffffffffu, hi.y, 4);
                    if ((grp & 1) == 0) {      // even rows own the pair word
                        uint2 wlo, whi;
                        wlo.x = f2h2(lo.x, plox);  wlo.y = f2h2(lo.y, ploy);
                        whi.x = f2h2(hi.x, phix);  whi.y = f2h2(hi.y, phiy);
                        *(uint2*)&g_vp[(bh_i * (L_/2) + (l_lo >> 1)) * HS_ + d0] = wlo;
                        *(uint2*)&g_vp[(bh_i * (L_/2) + (l_hi >> 1)) * HS_ + d0] = whi;
                    }
                }
            }
        }
    }
}

// ---------------------------------------------------------------------------
// R17 attention: fp16 data plane, cp.async pipelined K/E/V, Q frags in regs,
// conflict-free R ring (stride 264 halves), FA2 P-trick, register softmax.
// ---------------------------------------------------------------------------
#define LQW 36               // Q row stride (words)
#define LKW 36               // K/E row stride (words)
#define LVP 72               // V pair-row stride (words)
#define RSTR 264             // R ring row stride (halves) -> conflict-free
#define AQOFF  0             // Q: 128*36 = 4608 words
#define ABUF0  4608          // buffer: K(2304) + E(2304) + V(2304) = 6912 words
#define ABUF1  11520
#define ARWORD 18432         // R ring: 128*132 = 16896 words
#define ATT_SMEMB ((18432 + 16896) * 4)   // 141312 B

// issue cp.async for one tile's K,E,V into buffer at word offset buf_w
__device__ __forceinline__ void issue_tile(
    uint32_t sb, int buf_w, int bh, int k0n, int ebn, int tid)
{
#pragma unroll
    for (int u = 0; u < 2; u++) {
        const int t = u * 256 + tid;
        const int row = t >> 3, ch = t & 7;
        CP16(sb + (buf_w + row * LKW) * 4 + ch * 16,
             (const char*)&g_kh[((size_t)bh * L_ + k0n + row) * HS_] + ch * 16);
        int er = ebn + row; er = er < 0 ? 0 : (er > L_ - 1 ? L_ - 1 : er);
        CP16(sb + (buf_w + 2304 + row * LKW) * 4 + ch * 16,
             (const char*)&g_erh[(size_t)er * HS_] + ch * 16);
    }
#pragma unroll
    for (int u = 0; u < 2; u++) {
        const int t = u * 256 + tid;
        const int p = t >> 4, ch = t & 15;
        CP16(sb + (buf_w + 4608 + p * LVP) * 4 + ch * 16,
             (const char*)&g_vp[((size_t)bh * (L_/2) + (k0n >> 1) + p) * HS_] + ch * 16);
    }
}

// issue cp.async for one E-only block into buffer E slot
__device__ __forceinline__ void issue_e(
    uint32_t sb, int buf_w, int ebn, int tid)
{
#pragma unroll
    for (int u = 0; u < 2; u++) {
        const int t = u * 256 + tid;
        const int row = t >> 3, ch = t & 7;
        int er = ebn + row; er = er < 0 ? 0 : (er > L_ - 1 ? L_ - 1 : er);
        CP16(sb + (buf_w + 2304 + row * LKW) * 4 + ch * 16,
             (const char*)&g_erh[(size_t)er * HS_] + ch * 16);
    }
}

// Q x E-block fp16 MMA -> store 64 new R ring columns (warp-local rows)
__device__ __forceinline__ void er_mma_store(
    const uint32_t qreg[4][4], const uint32_t* Es, __half* r_lo, __half* r_hi,
    int eb, int grp, int tig)
{
    float ea[8][4];
#pragma unroll
    for (int nt = 0; nt < 8; nt++)
#pragma unroll
        for (int i = 0; i < 4; i++) ea[nt][i] = 0.0f;
#pragma unroll
    for (int ks = 0; ks < 4; ks++) {
        const int kw = ks * 8;
#pragma unroll
        for (int nt = 0; nt < 8; nt++) {
            const uint32_t* rb = &Es[(nt * 8 + grp) * LKW + kw];
            uint32_t bfv[2] = { rb[tig], rb[tig + 4] };
            mma_f16(ea[nt], qreg[ks], bfv);
        }
    }
#pragma unroll
    for (int nt = 0; nt < 8; nt++) {
        const int cc = eb + nt * 8 + 2 * tig;
        r_lo[cc & 255]       = __float2half(ea[nt][0]);
        r_lo[(cc + 1) & 255] = __float2half(ea[nt][1]);
        r_hi[cc & 255]       = __float2half(ea[nt][2]);
        r_hi[(cc + 1) & 255] = __float2half(ea[nt][3]);
    }
}

__global__ __launch_bounds__(256) void attn_kernel()
{
    extern __shared__ float sm[];
    const uint32_t sb = smem_u32(sm);
    uint32_t* smw = (uint32_t*)sm;
    uint32_t* Qs = smw + AQOFF;
    __half*   Rh = (__half*)(smw + ARWORD);

    const int tid = threadIdx.x;
    const int wid = tid >> 5, lane = tid & 31;
    const int grp = lane >> 2, tig = lane & 3;
    const int bh = blockIdx.x;                 // 0..31
    const int qt = 15 - (int)blockIdx.y;       // biggest q-tiles first (LPT)
    const int q0 = qt * 128;
    const int nkt = 2 * qt + 2;
    const int e00 = (L_ - 1) - q0;
    const int m0 = wid * 16;
    const int i_lo = m0 + grp, i_hi = i_lo + 8;
    const int b = bh >> 4, h = bh & 15;
    const float NEG = -1e30f;
    __half* r_lo = Rh + i_lo * RSTR;
    __half* r_hi = Rh + i_hi * RSTR;

    // ---- stage 1: Q tile + E block A ----
#pragma unroll
    for (int u = 0; u < 4; u++) {
        const int t = u * 256 + tid;
        const int row = t >> 3, ch = t & 7;
        CP16(sb + (AQOFF + row * LQW) * 4 + ch * 16,
             (const char*)&g_qh[((size_t)bh * L_ + q0 + row) * HS_] + ch * 16);
    }
    issue_e(sb, ABUF0, e00 - 128, tid);
    CPCOMMIT();
    CPWAITALL();
    __syncthreads();

    // Q fragments -> registers (fixed for whole block)
    uint32_t qreg[4][4];
#pragma unroll
    for (int ks = 0; ks < 4; ks++) {
        const int kw = ks * 8;
        qreg[ks][0] = Qs[i_lo * LQW + kw + tig];
        qreg[ks][1] = Qs[i_hi * LQW + kw + tig];
        qreg[ks][2] = Qs[i_lo * LQW + kw + tig + 4];
        qreg[ks][3] = Qs[i_hi * LQW + kw + tig + 4];
    }

    er_mma_store(qreg, smw + ABUF0 + 2304, r_lo, r_hi, e00 - 128, grp, tig);
    __syncthreads();   // all E_A reads done before overwriting bufA.E

    // ---- stage 2: E block B -> bufB.E; tile0 K,E,V -> bufA ----
    issue_e(sb, ABUF1, e00 - 64, tid);
    issue_tile(sb, ABUF0, bh, 0, e00, tid);
    CPCOMMIT();
    CPWAITALL();
    __syncthreads();
    er_mma_store(qreg, smw + ABUF1 + 2304, r_lo, r_hi, e00 - 64, grp, tig);
    __syncthreads();   // bufB.E reads done before kt=0 issues kt=1 into bufB

    float m_lo = NEG, m_hi = NEG, l_lo = 0.0f, l_hi = 0.0f;
    float yacc[8][4];
#pragma unroll
    for (int nt = 0; nt < 8; nt++)
#pragma unroll
        for (int i = 0; i < 4; i++) yacc[nt][i] = 0.0f;

    // ---- main k-tile loop ----
#pragma unroll 1
    for (int kt = 0; kt < nkt; kt++) {
        const int cur_w = (kt & 1) ? ABUF1 : ABUF0;
        const int nxt_w = (kt & 1) ? ABUF0 : ABUF1;
        const int e0k = e00 + 64 * kt;
        const bool pf = (kt + 1 < nkt);

        if (pf) {
            issue_tile(sb, nxt_w, bh, (kt + 1) * 64, e0k + 64, tid);
            CPCOMMIT();
        }

        const uint32_t* Ks = smw + cur_w;
        const uint32_t* Es = smw + cur_w + 2304;
        const uint32_t* Vs = smw + cur_w + 4608;

        // ---- Phase A (fp16): ka = Q.K^T, ea = Q.Enew^T ----
        float ka[8][4], ea[8][4];
#pragma unroll
        for (int nt = 0; nt < 8; nt++)
#pragma unroll
            for (int i = 0; i < 4; i++) { ka[nt][i] = 0.0f; ea[nt][i] = 0.0f; }
#pragma unroll
        for (int ks = 0; ks < 4; ks++) {
            const int kw = ks * 8;
#pragma unroll
            for (int nt = 0; nt < 8; nt++) {
                const uint32_t* rb = &Ks[(nt * 8 + grp) * LKW + kw];
                uint32_t bfv[2] = { rb[tig], rb[tig + 4] };
                mma_f16(ka[nt], qreg[ks], bfv);
            }
#pragma unroll
            for (int nt = 0; nt < 8; nt++) {
                const uint32_t* rb = &Es[(nt * 8 + grp) * LKW + kw];
                uint32_t bfv[2] = { rb[tig], rb[tig + 4] };
                mma_f16(ea[nt], qreg[ks], bfv);
            }
        }
        // store new R ring block (warp-local rows)
#pragma unroll
        for (int nt = 0; nt < 8; nt++) {
            const int cc = e0k + nt * 8 + 2 * tig;
            r_lo[cc & 255]       = __float2half(ea[nt][0]);
            r_lo[(cc + 1) & 255] = __float2half(ea[nt][1]);
            r_hi[cc & 255]       = __float2half(ea[nt][2]);
            r_hi[(cc + 1) & 255] = __float2half(ea[nt][3]);
        }
        __syncwarp();

        // ---- Phase B: register softmax ----
        const bool masked = (kt >= 2 * qt);
        const int lim_lo = q0 - kt * 64 + i_lo, lim_hi = lim_lo + 8;
        float mx0 = NEG, mx1 = NEG;
#pragma unroll
        for (int nt = 0; nt < 8; nt++) {
            const int j = nt * 8 + 2 * tig;
            float s00 = ka[nt][0] + __half2float(r_lo[(e0k + j     - i_lo) & 255]);
            float s01 = ka[nt][1] + __half2float(r_lo[(e0k + j + 1 - i_lo) & 255]);
            float s10 = ka[nt][2] + __half2float(r_hi[(e0k + j     - i_hi) & 255]);
            float s11 = ka[nt][3] + __half2float(r_hi[(e0k + j + 1 - i_hi) & 255]);
            if (masked) {
                if (j     > lim_lo) s00 = NEG;
                if (j + 1 > lim_lo) s01 = NEG;
                if (j     > lim_hi) s10 = NEG;
                if (j + 1 > lim_hi) s11 = NEG;
            }
            ka[nt][0] = s00; ka[nt][1] = s01; ka[nt][2] = s10; ka[nt][3] = s11;
            mx0 = fmaxf(mx0, fmaxf(s00, s01));
            mx1 = fmaxf(mx1, fmaxf(s10, s11));
        }
        mx0 = fmaxf(mx0, __shfl_xor_sync(0xffffffffu, mx0, 1));
        mx0 = fmaxf(mx0, __shfl_xor_sync(0xffffffffu, mx0, 2));
        mx1 = fmaxf(mx1, __shfl_xor_sync(0xffffffffu, mx1, 1));
        mx1 = fmaxf(mx1, __shfl_xor_sync(0xffffffffu, mx1, 2));
        const float mn0 = fmaxf(m_lo, mx0), mn1 = fmaxf(m_hi, mx1);
        const float a0 = fexp(m_lo - mn0),  a1 = fexp(m_hi - mn1);
        m_lo = mn0; m_hi = mn1;

        float sum0 = 0.0f, sum1 = 0.0f;
#pragma unroll
        for (int nt = 0; nt < 8; nt++) {
            const float p00 = fexp(ka[nt][0] - mn0);
            const float p01 = fexp(ka[nt][1] - mn0);
            const float p10 = fexp(ka[nt][2] - mn1);
            const float p11 = fexp(ka[nt][3] - mn1);
            sum0 += p00 + p01;
            sum1 += p10 + p11;
            ka[nt][0] = p00; ka[nt][1] = p01; ka[nt][2] = p10; ka[nt][3] = p11;
        }
        sum0 += __shfl_xor_sync(0xffffffffu, sum0, 1);
        sum0 += __shfl_xor_sync(0xffffffffu, sum0, 2);
        sum1 += __shfl_xor_sync(0xffffffffu, sum1, 1);
        sum1 += __shfl_xor_sync(0xffffffffu, sum1, 2);
        l_lo = l_lo * a0 + sum0;
        l_hi = l_hi * a1 + sum1;
#pragma unroll
        for (int nt = 0; nt < 8; nt++) {
            yacc[nt][0] *= a0; yacc[nt][1] *= a0;
            yacc[nt][2] *= a1; yacc[nt][3] *= a1;
        }

        // ---- Phase C (fp16): Y += P.V; S C-frag == P A-frag ----
#pragma unroll
        for (int ks = 0; ks < 4; ks++) {
            uint32_t af[4];
            af[0] = f2h2(ka[2 * ks][0],     ka[2 * ks][1]);
            af[1] = f2h2(ka[2 * ks][2],     ka[2 * ks][3]);
            af[2] = f2h2(ka[2 * ks + 1][0], ka[2 * ks + 1][1]);
            af[3] = f2h2(ka[2 * ks + 1][2], ka[2 * ks + 1][3]);
#pragma unroll
            for (int nt = 0; nt < 8; nt++) {
                uint32_t bfv[2];
                bfv[0] = Vs[(8 * ks + tig)     * LVP + nt * 8 + grp];
                bfv[1] = Vs[(8 * ks + tig + 4) * LVP + nt * 8 + grp];
                mma_f16(yacc[nt], af, bfv);
            }
        }

        if (pf) CPWAITALL();
        __syncthreads();
    }

    // ---- Epilogue: normalize, write g_yh (fp16) ----
    const float linv0 = 1.0f / l_lo, linv1 = 1.0f / l_hi;
    const int rl = q0 + i_lo, rh = q0 + i_hi;
#pragma unroll
    for (int nt = 0; nt < 8; nt++) {
        const int col = h * 64 + nt * 8 + 2 * tig;
        *(uint32_t*)&g_yh[((size_t)b * L_ + rl) * D_ + col] =
            f2h2(yacc[nt][0] * linv0, yacc[nt][1] * linv0);
        *(uint32_t*)&g_yh[((size_t)b * L_ + rh) * D_ + col] =
            f2h2(yacc[nt][2] * linv1, yacc[nt][3] * linv1);
    }
}

// ---------------------------------------------------------------------------
extern "C" void kernel_launch(void* const* d_in, const int* in_sizes, int n_in,
                              void* d_out, int out_size)
{
    const float* x      = (const float*)d_in[0];   // (2, 2048, 1024)
    const float* W_attn = (const float*)d_in[1];   // (1024, 3072)
    const float* b_attn = (const float*)d_in[2];   // (3072,)
    const float* W_proj = (const float*)d_in[3];   // (1024, 1024)
    const float* b_proj = (const float*)d_in[4];   // (1024,)
    const float* Er     = (const float*)d_in[5];   // (2048, 64)
    float* out = (float*)d_out;

    cudaFuncSetAttribute(attn_kernel,
                         cudaFuncAttributeMaxDynamicSharedMemorySize, ATT_SMEMB);

    __half* xh;  cudaGetSymbolAddress((void**)&xh,  g_xh);
    __half* erh; cudaGetSymbolAddress((void**)&erh, g_erh);
    __half* wat; cudaGetSymbolAddress((void**)&wat, g_wat);
    __half* wpt; cudaGetSymbolAddress((void**)&wpt, g_wpt);
    __half* yh;  cudaGetSymbolAddress((void**)&yh,  g_yh);

    // 0) fp16 conversions + weight transposes
    f32_to_f16_kernel<<<(BL_ * D_ / 4 + 255) / 256, 256>>>(x, xh, BL_ * D_ / 4);
    f32_to_f16_kernel<<<(L_ * HS_ / 4 + 255) / 256, 256>>>(Er, erh, L_ * HS_ / 4);
    transpose_h_kernel<<<dim3(N3D_ / 32, D_ / 32), 256>>>(W_attn, wat, D_, N3D_);
    transpose_h_kernel<<<dim3(D_ / 32, D_ / 32), 256>>>(W_proj, wpt, D_, D_);

    // 1) QKV projection (fp16 in, q/k/v fp16 out, V pair-interleaved)
    gemm_mma<0><<<dim3(N3D_ / 128, BL_ / 128), 256>>>(xh, wat, b_attn, nullptr);

    // 2) Causal attention with relative position bias
    attn_kernel<<<dim3(B_ * H_, 16), 256, ATT_SMEMB>>>();

    // 3) Output projection (fp16 in, fp32 out)
    gemm_mma<1><<<dim3(D_ / 128, BL_ / 128), 256>>>(yh, wpt, b_proj, out);
}